// round 1
// baseline (speedup 1.0000x reference)
#include <cuda_runtime.h>
#include <math.h>

#define BB 2
#define TT 2048
#define CC 768
#define HH 12
#define HS 64
#define C3 2304
#define MTOT (BB*TT)   // 4096

// Scratch (allocation-free contract): qkv activations + attention output
__device__ float g_qkv[(size_t)BB * TT * C3];   // 37.7 MB
__device__ float g_y[(size_t)BB * TT * CC];     // 12.6 MB

// ---------------------------------------------------------------------------
// SGEMM: out[M,N] = A[M,K] @ W[K,N] + bias[N]
// 128x128 block tile, BK=8, 256 threads, 8x8 per-thread microtile using the
// split-64 layout (rows {ty*4..+3, 64+ty*4..+3}, cols {tx*4..+3, 64+tx*4..+3})
// so all shared loads are conflict-free float4s.
// Requires M%128==0, N%128==0, K%8==0 (true for all our shapes).
// ---------------------------------------------------------------------------
__global__ __launch_bounds__(256) void sgemm_bias_kernel(
    const float* __restrict__ A, const float* __restrict__ W,
    const float* __restrict__ bias, float* __restrict__ out,
    int M, int N, int K)
{
    __shared__ float As[8][132];   // padded: conflict-free transposed stores
    __shared__ float Bs[8][128];

    const int tid = threadIdx.x;
    const int tx = tid & 15;
    const int ty = tid >> 4;
    const int row0 = blockIdx.y * 128;
    const int col0 = blockIdx.x * 128;

    // A tile loaders: 128 rows x 8 k, float4 along K, transposed store
    const int a_row = tid >> 1;
    const int a_k4  = (tid & 1) * 4;
    // B tile loaders: 8 rows x 128 cols, float4 along N
    const int b_k  = tid >> 5;
    const int b_c4 = (tid & 31) * 4;

    const float* Arow = A + (size_t)(row0 + a_row) * K;

    float acc[8][8];
    #pragma unroll
    for (int i = 0; i < 8; i++)
        #pragma unroll
        for (int j = 0; j < 8; j++) acc[i][j] = 0.f;

    for (int k0 = 0; k0 < K; k0 += 8) {
        float4 av = *(const float4*)(Arow + k0 + a_k4);
        As[a_k4 + 0][a_row] = av.x;
        As[a_k4 + 1][a_row] = av.y;
        As[a_k4 + 2][a_row] = av.z;
        As[a_k4 + 3][a_row] = av.w;
        float4 bv = *(const float4*)(W + (size_t)(k0 + b_k) * N + col0 + b_c4);
        *(float4*)&Bs[b_k][b_c4] = bv;
        __syncthreads();

        #pragma unroll
        for (int kk = 0; kk < 8; kk++) {
            float a[8], b[8];
            *(float4*)&a[0] = *(const float4*)&As[kk][ty * 4];
            *(float4*)&a[4] = *(const float4*)&As[kk][64 + ty * 4];
            *(float4*)&b[0] = *(const float4*)&Bs[kk][tx * 4];
            *(float4*)&b[4] = *(const float4*)&Bs[kk][64 + tx * 4];
            #pragma unroll
            for (int i = 0; i < 8; i++)
                #pragma unroll
                for (int j = 0; j < 8; j++)
                    acc[i][j] += a[i] * b[j];
        }
        __syncthreads();
    }

    // Epilogue: add bias, vectorized stores
    #pragma unroll
    for (int i = 0; i < 8; i++) {
        int r = row0 + ((i < 4) ? (ty * 4 + i) : (64 + ty * 4 + (i - 4)));
        float* orow = out + (size_t)r * N;
        {
            int c = col0 + tx * 4;
            float4 o;
            o.x = acc[i][0] + bias[c + 0];
            o.y = acc[i][1] + bias[c + 1];
            o.z = acc[i][2] + bias[c + 2];
            o.w = acc[i][3] + bias[c + 3];
            *(float4*)(orow + c) = o;
        }
        {
            int c = col0 + 64 + tx * 4;
            float4 o;
            o.x = acc[i][4] + bias[c + 0];
            o.y = acc[i][5] + bias[c + 1];
            o.z = acc[i][6] + bias[c + 2];
            o.w = acc[i][7] + bias[c + 3];
            *(float4*)(orow + c) = o;
        }
    }
}

// ---------------------------------------------------------------------------
// Flash attention (fp32, online softmax).
// grid = (T/64, B*H); block = 256 threads.
// Each block: one 64-row query tile of one (b,h). Loops over KV tiles of 64
// up to (and including) the diagonal tile; strictly-above-diagonal tiles are
// never visited (causal skip ~halves the work).
// Thread (ty,tx) owns S/O rows 4ty..4ty+3, cols 4tx..4tx+3.
// K tile is stored with an XOR swizzle on float4 index (f ^= (row>>2)&7) so
// the Q.K^T inner loop's LDS.128s are bank-conflict-free.
// ---------------------------------------------------------------------------
__global__ __launch_bounds__(256) void flash_kernel(
    const float* __restrict__ qkv, float* __restrict__ y)
{
    extern __shared__ float sm[];
    float* q_sh = sm;           // 64*64
    float* k_sh = sm + 4096;    // 64*64 (swizzled)
    float* v_sh = sm + 8192;    // 64*64
    float* p_sh = sm + 12288;   // 64*64
    // total 16384 floats = 65536 bytes

    const int tid = threadIdx.x;
    const int tx = tid & 15;
    const int ty = tid >> 4;
    const int qi = blockIdx.x;
    const int b  = blockIdx.y / HH;
    const int h  = blockIdx.y % HH;
    const int q0 = qi * 64;

    const float* qbase = qkv + (size_t)b * TT * C3 + (size_t)h * HS;

    // load Q tile (rows q0..q0+63, this head's 64 dims)
    for (int i = tid; i < 64 * 16; i += 256) {
        int r = i >> 4, f = i & 15;
        *(float4*)&q_sh[r * 64 + f * 4] =
            *(const float4*)(qbase + (size_t)(q0 + r) * C3 + f * 4);
    }

    float m_i[4], l_i[4], o_acc[4][4];
    #pragma unroll
    for (int i = 0; i < 4; i++) {
        m_i[i] = -1e30f;
        l_i[i] = 0.f;
        #pragma unroll
        for (int j = 0; j < 4; j++) o_acc[i][j] = 0.f;
    }
    const float scale = 0.125f; // 1/sqrt(64)

    for (int kt = 0; kt <= qi; kt++) {
        __syncthreads();  // protect q(first iter) / k,v,p (later iters)

        const float* kbase = qkv + (size_t)b * TT * C3 + CC  + (size_t)h * HS
                             + (size_t)(kt * 64) * C3;
        const float* vbase = kbase + CC;  // V lives CC after K in qkv row

        for (int i = tid; i < 64 * 16; i += 256) {
            int r = i >> 4, f = i & 15;
            float4 kv4 = *(const float4*)(kbase + (size_t)r * C3 + f * 4);
            int fk = f ^ ((r >> 2) & 7);
            *(float4*)&k_sh[r * 64 + fk * 4] = kv4;
            float4 vv4 = *(const float4*)(vbase + (size_t)r * C3 + f * 4);
            *(float4*)&v_sh[r * 64 + f * 4] = vv4;
        }
        __syncthreads();

        // S = Q @ K^T  (per-thread 4x4)
        float s[4][4];
        #pragma unroll
        for (int i = 0; i < 4; i++)
            #pragma unroll
            for (int j = 0; j < 4; j++) s[i][j] = 0.f;

        #pragma unroll 4
        for (int kk4 = 0; kk4 < 16; kk4++) {
            float4 qv[4], kv[4];
            #pragma unroll
            for (int i = 0; i < 4; i++)
                qv[i] = *(const float4*)&q_sh[(4 * ty + i) * 64 + kk4 * 4];
            #pragma unroll
            for (int j = 0; j < 4; j++) {
                int c = 4 * tx + j;
                int fk = kk4 ^ ((c >> 2) & 7);
                kv[j] = *(const float4*)&k_sh[c * 64 + fk * 4];
            }
            #pragma unroll
            for (int i = 0; i < 4; i++)
                #pragma unroll
                for (int j = 0; j < 4; j++)
                    s[i][j] += qv[i].x * kv[j].x + qv[i].y * kv[j].y
                             + qv[i].z * kv[j].z + qv[i].w * kv[j].w;
        }

        const bool diag = (kt == qi);
        #pragma unroll
        for (int i = 0; i < 4; i++)
            #pragma unroll
            for (int j = 0; j < 4; j++) {
                float val = s[i][j] * scale;
                if (diag && (4 * tx + j > 4 * ty + i)) val = -1e30f;
                s[i][j] = val;
            }

        // Online softmax update (per row: shfl-reduce across the 16 tx lanes)
        #pragma unroll
        for (int i = 0; i < 4; i++) {
            float tm = fmaxf(fmaxf(s[i][0], s[i][1]), fmaxf(s[i][2], s[i][3]));
            #pragma unroll
            for (int off = 8; off >= 1; off >>= 1)
                tm = fmaxf(tm, __shfl_xor_sync(0xffffffffu, tm, off));
            float m_new = fmaxf(m_i[i], tm);
            float corr = __expf(m_i[i] - m_new);
            float rs = 0.f;
            #pragma unroll
            for (int j = 0; j < 4; j++) {
                float p = __expf(s[i][j] - m_new);
                s[i][j] = p;
                rs += p;
            }
            #pragma unroll
            for (int off = 8; off >= 1; off >>= 1)
                rs += __shfl_xor_sync(0xffffffffu, rs, off);
            l_i[i] = l_i[i] * corr + rs;
            m_i[i] = m_new;
            #pragma unroll
            for (int j = 0; j < 4; j++) o_acc[i][j] *= corr;
        }

        // stage P
        #pragma unroll
        for (int i = 0; i < 4; i++)
            *(float4*)&p_sh[(4 * ty + i) * 64 + 4 * tx] =
                make_float4(s[i][0], s[i][1], s[i][2], s[i][3]);
        __syncthreads();

        // O += P @ V
        #pragma unroll 4
        for (int kk4 = 0; kk4 < 16; kk4++) {
            float4 pv[4], vv[4];
            #pragma unroll
            for (int i = 0; i < 4; i++)
                pv[i] = *(const float4*)&p_sh[(4 * ty + i) * 64 + kk4 * 4];
            #pragma unroll
            for (int t = 0; t < 4; t++)
                vv[t] = *(const float4*)&v_sh[(kk4 * 4 + t) * 64 + 4 * tx];
            #pragma unroll
            for (int i = 0; i < 4; i++) {
                o_acc[i][0] += pv[i].x * vv[0].x + pv[i].y * vv[1].x
                             + pv[i].z * vv[2].x + pv[i].w * vv[3].x;
                o_acc[i][1] += pv[i].x * vv[0].y + pv[i].y * vv[1].y
                             + pv[i].z * vv[2].y + pv[i].w * vv[3].y;
                o_acc[i][2] += pv[i].x * vv[0].z + pv[i].y * vv[1].z
                             + pv[i].z * vv[2].z + pv[i].w * vv[3].z;
                o_acc[i][3] += pv[i].x * vv[0].w + pv[i].y * vv[1].w
                             + pv[i].z * vv[2].w + pv[i].w * vv[3].w;
            }
        }
    }

    // Epilogue: normalize and write y[b, t, h*64 + d]
    #pragma unroll
    for (int i = 0; i < 4; i++) {
        float inv = 1.f / l_i[i];
        int r = q0 + 4 * ty + i;
        float4 o4 = make_float4(o_acc[i][0] * inv, o_acc[i][1] * inv,
                                o_acc[i][2] * inv, o_acc[i][3] * inv);
        *(float4*)(y + (size_t)b * TT * CC + (size_t)r * CC + h * HS + 4 * tx) = o4;
    }
}

extern "C" void kernel_launch(void* const* d_in, const int* in_sizes, int n_in,
                              void* d_out, int out_size)
{
    const float* x      = (const float*)d_in[0];
    const float* W_attn = (const float*)d_in[1];
    const float* b_attn = (const float*)d_in[2];
    const float* W_proj = (const float*)d_in[3];
    const float* b_proj = (const float*)d_in[4];
    float* out = (float*)d_out;

    float *qkv, *y;
    cudaGetSymbolAddress((void**)&qkv, g_qkv);
    cudaGetSymbolAddress((void**)&y, g_y);

    cudaFuncSetAttribute(flash_kernel,
                         cudaFuncAttributeMaxDynamicSharedMemorySize, 65536);

    // 1) qkv = x @ W_attn + b_attn
    sgemm_bias_kernel<<<dim3(C3 / 128, MTOT / 128), 256>>>(
        x, W_attn, b_attn, qkv, MTOT, C3, CC);

    // 2) y = causal_softmax(q k^T / sqrt(hs)) v, written back in [B,T,C]
    flash_kernel<<<dim3(TT / 64, BB * HH), 256, 65536>>>(qkv, y);

    // 3) out = y @ W_proj + b_proj
    sgemm_bias_kernel<<<dim3(CC / 128, MTOT / 128), 256>>>(
        y, W_proj, b_proj, out, MTOT, CC, CC);
}

// round 5
// speedup vs baseline: 1.9158x; 1.9158x over previous
#include <cuda_runtime.h>
#include <cuda_bf16.h>
#include <math.h>
#include <cstdint>

#define BB 2
#define TT 2048
#define CC 768
#define HH 12
#define HS 64
#define C3 2304
#define MTOT (BB*TT)   // 4096

// Scratch (allocation-free contract)
__device__ float g_qkv[(size_t)BB * TT * C3];       // 37.7 MB
__device__ float g_y[(size_t)BB * TT * CC];         // 12.6 MB
__device__ uint32_t g_wt[(size_t)CC * C3];          // hi/lo bf16-pair planes of W^T

// ---------------------------------------------------------------------------
// Helpers
// ---------------------------------------------------------------------------
// m16n8k16 bf16 mma: D = A*B + C (A row-major 16x16, B col-major 16x8, f32 acc)
__device__ __forceinline__ void mma_bf16(float c[4],
    uint32_t a0, uint32_t a1, uint32_t a2, uint32_t a3,
    uint32_t b0, uint32_t b1)
{
    asm("mma.sync.aligned.m16n8k16.row.col.f32.bf16.bf16.f32 "
        "{%0,%1,%2,%3}, {%4,%5,%6,%7}, {%8,%9}, {%0,%1,%2,%3};"
        : "+f"(c[0]), "+f"(c[1]), "+f"(c[2]), "+f"(c[3])
        : "r"(a0), "r"(a1), "r"(a2), "r"(a3), "r"(b0), "r"(b1));
}

// Split (x,y) fp32 pair into bf16x2 hi-pair + bf16x2 lo-pair (residuals).
__device__ __forceinline__ void split2(float x, float y, uint32_t& hi, uint32_t& lo)
{
    __nv_bfloat162 h = __floats2bfloat162_rn(x, y);
    hi = *reinterpret_cast<uint32_t*>(&h);
    float hx = __bfloat162float(h.x);
    float hy = __bfloat162float(h.y);
    __nv_bfloat162 l = __floats2bfloat162_rn(x - hx, y - hy);
    lo = *reinterpret_cast<uint32_t*>(&l);
}

#define F2U(x) __float_as_uint(x)

// ---------------------------------------------------------------------------
// Weight transpose + bf16 split: in [K,N] row-major fp32 ->
//   out_hi[n][k/2] (bf16 pair of k, k+1), out_lo likewise.
// ---------------------------------------------------------------------------
__global__ void transpose_split(const float* __restrict__ in,
                                uint32_t* __restrict__ out_hi,
                                uint32_t* __restrict__ out_lo,
                                int K, int N)
{
    __shared__ float t[32][33];
    int n0 = blockIdx.x << 5, k0 = blockIdx.y << 5;
    int x = threadIdx.x, y = threadIdx.y;          // 32 x 8
    #pragma unroll
    for (int i = 0; i < 32; i += 8)
        t[y + i][x] = in[(size_t)(k0 + y + i) * N + n0 + x];
    __syncthreads();
    const int xp = x & 15, plane = x >> 4;
    #pragma unroll
    for (int i = 0; i < 32; i += 8) {
        int n = n0 + y + i;
        float v0 = t[2 * xp][y + i], v1 = t[2 * xp + 1][y + i];
        uint32_t h, l;
        split2(v0, v1, h, l);
        size_t o = (size_t)n * (K / 2) + k0 / 2 + xp;
        if (plane == 0) out_hi[o] = h;
        else            out_lo[o] = l;
    }
}

// ---------------------------------------------------------------------------
// bf16x2-split GEMM: out[M,N] = A[M,K] @ W + bias, W given as transposed
// hi/lo bf16-pair planes (Wt_hi/Wt_lo: [N][K/2] u32).
// CTA 128x128, BK=32 (2 k16 steps), 8 warps 4(m)x2(n) -> warp tile 32x64.
// Single smem buffer + register prefetch. Plane stride 20 u32: fragment
// LDS banks (20*gid + tig) mod 32 all-distinct -> conflict-free.
// ---------------------------------------------------------------------------
__global__ __launch_bounds__(256) void gemm_bf16s(
    const float* __restrict__ A,
    const uint32_t* __restrict__ Wt_hi, const uint32_t* __restrict__ Wt_lo,
    const float* __restrict__ bias, float* __restrict__ out,
    int M, int N, int K)
{
    __shared__ uint32_t a_hi[128 * 20], a_lo[128 * 20];
    __shared__ uint32_t b_hi[128 * 20], b_lo[128 * 20];

    const int tid  = threadIdx.x;
    const int wid  = tid >> 5, lane = tid & 31;
    const int gid  = lane >> 2, tig = lane & 3;
    const int wm   = wid & 3;
    const int wn   = wid >> 2;
    const int row0 = blockIdx.y * 128;
    const int col0 = blockIdx.x * 128;
    const int K2   = K >> 1;

    // loader mappings
    const int ra = tid >> 3;          // + 32p : A rows
    const int fa = tid & 7;           // k-float4 within 32-chunk
    const int rb = tid >> 2;          // + 64p : B rows
    const int qb = tid & 3;           // uint4 within 16-pair chunk

    float cf[2][8][4];
    #pragma unroll
    for (int ma = 0; ma < 2; ma++)
        #pragma unroll
        for (int na = 0; na < 8; na++)
            #pragma unroll
            for (int r = 0; r < 4; r++) cf[ma][na][r] = 0.f;

    const int NK = K >> 5;
    float4 areg[4];
    uint4  brh[2], brl[2];

    // prologue loads for kt = 0
    #pragma unroll
    for (int p = 0; p < 4; p++)
        areg[p] = *(const float4*)(A + (size_t)(row0 + ra + 32 * p) * K + 4 * fa);
    #pragma unroll
    for (int p = 0; p < 2; p++) {
        size_t o = (size_t)(col0 + rb + 64 * p) * K2 + 4 * qb;
        brh[p] = *(const uint4*)(Wt_hi + o);
        brl[p] = *(const uint4*)(Wt_lo + o);
    }

    for (int kt = 0; kt < NK; kt++) {
        __syncthreads();   // prior MMAs done reading smem
        #pragma unroll
        for (int p = 0; p < 4; p++) {
            uint32_t h0, l0, h1, l1;
            split2(areg[p].x, areg[p].y, h0, l0);
            split2(areg[p].z, areg[p].w, h1, l1);
            int off = (ra + 32 * p) * 20 + 2 * fa;
            *(uint2*)&a_hi[off] = make_uint2(h0, h1);
            *(uint2*)&a_lo[off] = make_uint2(l0, l1);
        }
        #pragma unroll
        for (int p = 0; p < 2; p++) {
            int off = (rb + 64 * p) * 20 + 4 * qb;
            *(uint4*)&b_hi[off] = brh[p];
            *(uint4*)&b_lo[off] = brl[p];
        }
        __syncthreads();

        if (kt + 1 < NK) {
            const int k0 = (kt + 1) << 5;
            #pragma unroll
            for (int p = 0; p < 4; p++)
                areg[p] = *(const float4*)(A + (size_t)(row0 + ra + 32 * p) * K + k0 + 4 * fa);
            #pragma unroll
            for (int p = 0; p < 2; p++) {
                size_t o = (size_t)(col0 + rb + 64 * p) * K2 + (k0 >> 1) + 4 * qb;
                brh[p] = *(const uint4*)(Wt_hi + o);
                brl[p] = *(const uint4*)(Wt_lo + o);
            }
        }

        #pragma unroll
        for (int s = 0; s < 2; s++) {
            uint32_t ah[2][4], al[2][4];
            #pragma unroll
            for (int ma = 0; ma < 2; ma++) {
                const int base = (wm * 32 + ma * 16 + gid) * 20 + 8 * s + tig;
                ah[ma][0] = a_hi[base];       ah[ma][1] = a_hi[base + 160];
                ah[ma][2] = a_hi[base + 4];   ah[ma][3] = a_hi[base + 164];
                al[ma][0] = a_lo[base];       al[ma][1] = a_lo[base + 160];
                al[ma][2] = a_lo[base + 4];   al[ma][3] = a_lo[base + 164];
            }
            #pragma unroll
            for (int na = 0; na < 8; na++) {
                const int bb = (wn * 64 + na * 8 + gid) * 20 + 8 * s + tig;
                uint32_t b0h = b_hi[bb], b1h = b_hi[bb + 4];
                uint32_t b0l = b_lo[bb], b1l = b_lo[bb + 4];
                #pragma unroll
                for (int ma = 0; ma < 2; ma++) {
                    mma_bf16(cf[ma][na], ah[ma][0], ah[ma][1], ah[ma][2], ah[ma][3], b0h, b1h);
                    mma_bf16(cf[ma][na], ah[ma][0], ah[ma][1], ah[ma][2], ah[ma][3], b0l, b1l);
                    mma_bf16(cf[ma][na], al[ma][0], al[ma][1], al[ma][2], al[ma][3], b0h, b1h);
                }
            }
        }
    }

    // epilogue: bias + float2 stores
    #pragma unroll
    for (int ma = 0; ma < 2; ma++) {
        const int rg = row0 + wm * 32 + ma * 16 + gid;
        #pragma unroll
        for (int na = 0; na < 8; na++) {
            const int cg = col0 + wn * 64 + na * 8 + tig * 2;
            const float bx0 = bias[cg], bx1 = bias[cg + 1];
            *(float2*)(out + (size_t)rg * N + cg) =
                make_float2(cf[ma][na][0] + bx0, cf[ma][na][1] + bx1);
            *(float2*)(out + (size_t)(rg + 8) * N + cg) =
                make_float2(cf[ma][na][2] + bx0, cf[ma][na][3] + bx1);
        }
    }
}

// ---------------------------------------------------------------------------
// Flash attention, bf16x2-split mma.
// grid = (T/128, B*H); 256 threads = 8 warps x 16 q-rows.
// Q hi/lo fragments resident in registers. K planes [64][36] u32
// (bank 4*gid+tig: conflict-free). V planes key-pair-major [32][72]
// (bank 8*tig+gid: conflict-free). P feeds PV directly from C-fragments.
// ---------------------------------------------------------------------------
__global__ __launch_bounds__(256) void flash_bf16s(
    const float* __restrict__ qkv, float* __restrict__ y)
{
    __shared__ uint32_t sm[4 * 2304];       // k_hi, k_lo, v_hi, v_lo (36864 B)
    uint32_t* k_hi = sm;
    uint32_t* k_lo = sm + 2304;
    uint32_t* v_hi = sm + 4608;
    uint32_t* v_lo = sm + 6912;

    const int tid = threadIdx.x;
    const int wid = tid >> 5, lane = tid & 31;
    const int gid = lane >> 2, tig = lane & 3;
    const int bx = blockIdx.x;
    const int b  = blockIdx.y / HH;
    const int h  = blockIdx.y % HH;
    const int q0 = bx * 128;
    const float* base = qkv + (size_t)b * TT * C3;

    // ---- stage Q fp32 into smem overlay, then extract hi/lo fragments ----
    float* qs = (float*)sm;                  // [128][68] = 34816 B <= 36864
    for (int i = tid; i < 128 * 16; i += 256) {
        int r = i >> 4, f = i & 15;
        *(float4*)&qs[r * 68 + f * 4] =
            *(const float4*)(base + (size_t)(q0 + r) * C3 + h * HS + f * 4);
    }
    __syncthreads();

    const int qr = wid * 16 + gid;
    uint32_t qh[4][4], ql[4][4];
    #pragma unroll
    for (int ks = 0; ks < 4; ks++) {
        const int c = 16 * ks + 2 * tig;
        split2(qs[qr * 68 + c],            qs[qr * 68 + c + 1],       qh[ks][0], ql[ks][0]);
        split2(qs[(qr + 8) * 68 + c],      qs[(qr + 8) * 68 + c + 1], qh[ks][1], ql[ks][1]);
        split2(qs[qr * 68 + c + 8],        qs[qr * 68 + c + 9],       qh[ks][2], ql[ks][2]);
        split2(qs[(qr + 8) * 68 + c + 8],  qs[(qr + 8) * 68 + c + 9], qh[ks][3], ql[ks][3]);
    }
    __syncthreads();

    float of[8][4];
    #pragma unroll
    for (int na = 0; na < 8; na++)
        #pragma unroll
        for (int r = 0; r < 4; r++) of[na][r] = 0.f;
    float m0 = -1e30f, m1 = -1e30f, l0 = 0.f, l1 = 0.f;
    const float scale = 0.125f;
    const int r0g = q0 + wid * 16 + gid;
    const int r1g = r0g + 8;

    const int nkt = 2 * bx + 2;
    for (int kt = 0; kt < nkt; kt++) {
        __syncthreads();

        const float* kb = base + CC + (size_t)(kt * 64) * C3 + h * HS;
        const float* vb = kb + CC;
        // K: [64 keys][dim-pair 0..31] hi/lo, stride 36
        for (int i = tid; i < 64 * 16; i += 256) {
            int r = i >> 4, f = i & 15;
            float4 kv = *(const float4*)(kb + (size_t)r * C3 + 4 * f);
            uint32_t h0, lo0, h1, lo1;
            split2(kv.x, kv.y, h0, lo0);
            split2(kv.z, kv.w, h1, lo1);
            int off = r * 36 + 2 * f;
            *(uint2*)&k_hi[off] = make_uint2(h0, h1);
            *(uint2*)&k_lo[off] = make_uint2(lo0, lo1);
        }
        // V: key-pair-major [32 kp][64 dims], stride 72
        for (int i = tid; i < 32 * 16; i += 256) {
            int kp = i >> 4, f = i & 15;
            float4 v0 = *(const float4*)(vb + (size_t)(2 * kp) * C3 + 4 * f);
            float4 v1 = *(const float4*)(vb + (size_t)(2 * kp + 1) * C3 + 4 * f);
            uint4 hv, lv;
            split2(v0.x, v1.x, hv.x, lv.x);
            split2(v0.y, v1.y, hv.y, lv.y);
            split2(v0.z, v1.z, hv.z, lv.z);
            split2(v0.w, v1.w, hv.w, lv.w);
            int off = kp * 72 + 4 * f;
            *(uint4*)&v_hi[off] = hv;
            *(uint4*)&v_lo[off] = lv;
        }
        __syncthreads();

        // skip warps whose entire 16-row tile is masked
        if (kt * 64 > q0 + wid * 16 + 15) continue;

        // ---- S = Q @ K^T ----
        float sf[8][4];
        #pragma unroll
        for (int na = 0; na < 8; na++)
            #pragma unroll
            for (int r = 0; r < 4; r++) sf[na][r] = 0.f;

        #pragma unroll
        for (int ks = 0; ks < 4; ks++) {
            #pragma unroll
            for (int na = 0; na < 8; na++) {
                const int n = na * 8 + gid;
                const int kk = n * 36 + 8 * ks + tig;
                uint32_t b0h = k_hi[kk], b1h = k_hi[kk + 4];
                uint32_t b0l = k_lo[kk], b1l = k_lo[kk + 4];
                mma_bf16(sf[na], qh[ks][0], qh[ks][1], qh[ks][2], qh[ks][3], b0h, b1h);
                mma_bf16(sf[na], qh[ks][0], qh[ks][1], qh[ks][2], qh[ks][3], b0l, b1l);
                mma_bf16(sf[na], ql[ks][0], ql[ks][1], ql[ks][2], ql[ks][3], b0h, b1h);
            }
        }

        // ---- scale + causal mask ----
        const bool need_mask = (kt >= 2 * bx);
        #pragma unroll
        for (int na = 0; na < 8; na++) {
            const int cg = kt * 64 + na * 8 + tig * 2;
            sf[na][0] *= scale; sf[na][1] *= scale;
            sf[na][2] *= scale; sf[na][3] *= scale;
            if (need_mask) {
                if (cg     > r0g) sf[na][0] = -1e30f;
                if (cg + 1 > r0g) sf[na][1] = -1e30f;
                if (cg     > r1g) sf[na][2] = -1e30f;
                if (cg + 1 > r1g) sf[na][3] = -1e30f;
            }
        }

        // ---- online softmax ----
        float rm0 = -1e30f, rm1 = -1e30f;
        #pragma unroll
        for (int na = 0; na < 8; na++) {
            rm0 = fmaxf(rm0, fmaxf(sf[na][0], sf[na][1]));
            rm1 = fmaxf(rm1, fmaxf(sf[na][2], sf[na][3]));
        }
        rm0 = fmaxf(rm0, __shfl_xor_sync(0xffffffffu, rm0, 1));
        rm0 = fmaxf(rm0, __shfl_xor_sync(0xffffffffu, rm0, 2));
        rm1 = fmaxf(rm1, __shfl_xor_sync(0xffffffffu, rm1, 1));
        rm1 = fmaxf(rm1, __shfl_xor_sync(0xffffffffu, rm1, 2));
        const float mn0 = fmaxf(m0, rm0), mn1 = fmaxf(m1, rm1);
        const float c0 = __expf(m0 - mn0), c1 = __expf(m1 - mn1);
        float rs0 = 0.f, rs1 = 0.f;
        #pragma unroll
        for (int na = 0; na < 8; na++) {
            sf[na][0] = __expf(sf[na][0] - mn0);
            sf[na][1] = __expf(sf[na][1] - mn0);
            sf[na][2] = __expf(sf[na][2] - mn1);
            sf[na][3] = __expf(sf[na][3] - mn1);
            rs0 += sf[na][0] + sf[na][1];
            rs1 += sf[na][2] + sf[na][3];
        }
        rs0 += __shfl_xor_sync(0xffffffffu, rs0, 1);
        rs0 += __shfl_xor_sync(0xffffffffu, rs0, 2);
        rs1 += __shfl_xor_sync(0xffffffffu, rs1, 1);
        rs1 += __shfl_xor_sync(0xffffffffu, rs1, 2);
        l0 = l0 * c0 + rs0; m0 = mn0;
        l1 = l1 * c1 + rs1; m1 = mn1;
        #pragma unroll
        for (int na = 0; na < 8; na++) {
            of[na][0] *= c0; of[na][1] *= c0;
            of[na][2] *= c1; of[na][3] *= c1;
        }

        // ---- O += P @ V  (P packed straight from C-fragments) ----
        #pragma unroll
        for (int ks = 0; ks < 4; ks++) {
            uint32_t pah[4], pal[4];
            split2(sf[2 * ks][0],     sf[2 * ks][1],     pah[0], pal[0]);
            split2(sf[2 * ks][2],     sf[2 * ks][3],     pah[1], pal[1]);
            split2(sf[2 * ks + 1][0], sf[2 * ks + 1][1], pah[2], pal[2]);
            split2(sf[2 * ks + 1][2], sf[2 * ks + 1][3], pah[3], pal[3]);
            #pragma unroll
            for (int na = 0; na < 8; na++) {
                const int d = na * 8 + gid;
                const int o0 = (8 * ks + tig) * 72 + d;
                const int o1 = (8 * ks + tig + 4) * 72 + d;
                uint32_t b0h = v_hi[o0], b1h = v_hi[o1];
                uint32_t b0l = v_lo[o0], b1l = v_lo[o1];
                mma_bf16(of[na], pah[0], pah[1], pah[2], pah[3], b0h, b1h);
                mma_bf16(of[na], pah[0], pah[1], pah[2], pah[3], b0l, b1l);
                mma_bf16(of[na], pal[0], pal[1], pal[2], pal[3], b0h, b1h);
            }
        }
    }

    // ---- epilogue ----
    const float i0 = 1.f / l0, i1 = 1.f / l1;
    float* yb = y + (size_t)b * TT * CC + h * HS;
    #pragma unroll
    for (int na = 0; na < 8; na++) {
        const int cg = na * 8 + tig * 2;
        *(float2*)(yb + (size_t)r0g * CC + cg) =
            make_float2(of[na][0] * i0, of[na][1] * i0);
        *(float2*)(yb + (size_t)r1g * CC + cg) =
            make_float2(of[na][2] * i1, of[na][3] * i1);
    }
}

extern "C" void kernel_launch(void* const* d_in, const int* in_sizes, int n_in,
                              void* d_out, int out_size)
{
    const float* x      = (const float*)d_in[0];
    const float* W_attn = (const float*)d_in[1];
    const float* b_attn = (const float*)d_in[2];
    const float* W_proj = (const float*)d_in[3];
    const float* b_proj = (const float*)d_in[4];
    float* out = (float*)d_out;

    float *qkv, *y;
    uint32_t *wt;
    cudaGetSymbolAddress((void**)&qkv, g_qkv);
    cudaGetSymbolAddress((void**)&y, g_y);
    cudaGetSymbolAddress((void**)&wt, g_wt);

    // 1) W_attn -> transposed hi/lo planes; qkv = x @ W_attn + b_attn
    {
        uint32_t* wt_hi = wt;
        uint32_t* wt_lo = wt + (size_t)C3 * CC / 2;
        transpose_split<<<dim3(C3 / 32, CC / 32), dim3(32, 8)>>>(W_attn, wt_hi, wt_lo, CC, C3);
        gemm_bf16s<<<dim3(C3 / 128, MTOT / 128), 256>>>(
            x, wt_hi, wt_lo, b_attn, qkv, MTOT, C3, CC);
    }

    // 2) flash attention
    flash_bf16s<<<dim3(TT / 128, BB * HH), 256>>>(qkv, y);

    // 3) W_proj -> planes; out = y @ W_proj + b_proj
    {
        uint32_t* wt_hi = wt;
        uint32_t* wt_lo = wt + (size_t)CC * CC / 2;
        transpose_split<<<dim3(CC / 32, CC / 32), dim3(32, 8)>>>(W_proj, wt_hi, wt_lo, CC, CC);
        gemm_bf16s<<<dim3(CC / 128, MTOT / 128), 256>>>(
            y, wt_hi, wt_lo, b_proj, out, MTOT, CC, CC);
    }
}

// round 6
// speedup vs baseline: 2.2734x; 1.1866x over previous
#include <cuda_runtime.h>
#include <cuda_bf16.h>
#include <math.h>
#include <cstdint>

#define BB 2
#define TT 2048
#define CC 768
#define HH 12
#define HS 64
#define C3 2304
#define MTOT (BB*TT)          // 4096
#define PSZ (4096*384)        // u32 per plane for [M][K/2] with K=768

// Scratch (allocation-free contract)
__device__ uint32_t g_qkvp[6 * (size_t)PSZ];        // q_hi,q_lo,k_hi,k_lo,v_hi,v_lo
__device__ uint32_t g_vt[2 * (size_t)2048 * 768];   // V token-pair-major planes
__device__ uint32_t g_xp[2 * (size_t)PSZ];          // x planes
__device__ uint32_t g_yp[2 * (size_t)PSZ];          // y planes
__device__ uint32_t g_wt[(size_t)CC * C3];          // W^T planes (hi then lo)

// ---------------------------------------------------------------------------
// Helpers
// ---------------------------------------------------------------------------
__device__ __forceinline__ uint32_t smem_u32(const void* p) {
    uint32_t a;
    asm("{ .reg .u64 t; cvta.to.shared.u64 t, %1; cvt.u32.u64 %0, t; }"
        : "=r"(a) : "l"(p));
    return a;
}

__device__ __forceinline__ void mma_bf16(float c[4],
    uint32_t a0, uint32_t a1, uint32_t a2, uint32_t a3,
    uint32_t b0, uint32_t b1)
{
    asm("mma.sync.aligned.m16n8k16.row.col.f32.bf16.bf16.f32 "
        "{%0,%1,%2,%3}, {%4,%5,%6,%7}, {%8,%9}, {%0,%1,%2,%3};"
        : "+f"(c[0]), "+f"(c[1]), "+f"(c[2]), "+f"(c[3])
        : "r"(a0), "r"(a1), "r"(a2), "r"(a3), "r"(b0), "r"(b1));
}

__device__ __forceinline__ void split2(float x, float y, uint32_t& hi, uint32_t& lo)
{
    __nv_bfloat162 h = __floats2bfloat162_rn(x, y);
    hi = *reinterpret_cast<uint32_t*>(&h);
    float hx = __bfloat162float(h.x);
    float hy = __bfloat162float(h.y);
    __nv_bfloat162 l = __floats2bfloat162_rn(x - hx, y - hy);
    lo = *reinterpret_cast<uint32_t*>(&l);
}

__device__ __forceinline__ void cpasync16(uint32_t dst, const void* src) {
    asm volatile("cp.async.cg.shared.global [%0], [%1], 16;"
                 :: "r"(dst), "l"(src));
}
#define CP_COMMIT() asm volatile("cp.async.commit_group;" ::: "memory")
#define CP_WAIT1()  asm volatile("cp.async.wait_group 1;" ::: "memory")
#define CP_WAIT0()  asm volatile("cp.async.wait_group 0;" ::: "memory")

// ---------------------------------------------------------------------------
// Prep kernels
// ---------------------------------------------------------------------------
// x [4096][768] fp32 -> hi/lo pair planes [4096][384]
__global__ void split_x(const float* __restrict__ x,
                        uint32_t* __restrict__ xh, uint32_t* __restrict__ xl)
{
    int idx = blockIdx.x * 256 + threadIdx.x;       // 786432 total
    int r = idx / 192, j2 = idx % 192;              // 2 pairs per thread
    float4 v = *(const float4*)(x + (size_t)r * 768 + 4 * j2);
    uint32_t h0, l0, h1, l1;
    split2(v.x, v.y, h0, l0);
    split2(v.z, v.w, h1, l1);
    size_t o = (size_t)r * 384 + 2 * j2;
    *(uint2*)(xh + o) = make_uint2(h0, h1);
    *(uint2*)(xl + o) = make_uint2(l0, l1);
}

// W [K][N] fp32 -> transposed hi/lo pair planes [N][K/2]
__global__ void transpose_split(const float* __restrict__ in,
                                uint32_t* __restrict__ out_hi,
                                uint32_t* __restrict__ out_lo,
                                int K, int N)
{
    __shared__ float t[32][33];
    int n0 = blockIdx.x << 5, k0 = blockIdx.y << 5;
    int x = threadIdx.x, y = threadIdx.y;
    #pragma unroll
    for (int i = 0; i < 32; i += 8)
        t[y + i][x] = in[(size_t)(k0 + y + i) * N + n0 + x];
    __syncthreads();
    const int xp = x & 15, plane = x >> 4;
    #pragma unroll
    for (int i = 0; i < 32; i += 8) {
        int n = n0 + y + i;
        uint32_t h, l;
        split2(t[2 * xp][y + i], t[2 * xp + 1][y + i], h, l);
        size_t o = (size_t)n * (K / 2) + k0 / 2 + xp;
        if (plane == 0) out_hi[o] = h;
        else            out_lo[o] = l;
    }
}

// V dim-pair planes [4096][384] -> token-pair-major planes [2048][768]
__global__ void pack_vt(const uint32_t* __restrict__ vh,
                        const uint32_t* __restrict__ vl,
                        uint32_t* __restrict__ vth, uint32_t* __restrict__ vtl)
{
    int idx = blockIdx.x * 256 + threadIdx.x;       // 2048*384 total
    int bp = idx / 384, j = idx % 384;
    size_t s0 = (size_t)(2 * bp) * 384 + j;
    size_t s1 = s0 + 384;
    uint32_t ah = vh[s0], bh = vh[s1];
    uint32_t al = vl[s0], bl = vl[s1];
    size_t o = (size_t)bp * 768 + 2 * j;
    vth[o]     = __byte_perm(ah, bh, 0x5410);
    vth[o + 1] = __byte_perm(ah, bh, 0x7632);
    vtl[o]     = __byte_perm(al, bl, 0x5410);
    vtl[o + 1] = __byte_perm(al, bl, 0x7632);
}

// ---------------------------------------------------------------------------
// Plane GEMM: out = A @ W^T + bias, A/W given as hi/lo bf16-pair planes.
// CTA 128x128, BK=32 floats (16 pairs), 8 warps 4(m)x2(n), cp.async 2-stage.
// smem per stage (u32): a_hi@0, a_lo@2560, b_hi@5120, b_lo@7680 (stride 20).
// MODE 0: epilogue splits to Q/K/V planes. MODE 1: fp32 out.
// ---------------------------------------------------------------------------
__device__ __forceinline__ void gemm_issue(
    uint32_t st_u32,
    const uint32_t* Ah, const uint32_t* Al,
    const uint32_t* Bh, const uint32_t* Bl,
    int row0, int col0, int K2, int kp0, int tid)
{
    #pragma unroll
    for (int p = 0; p < 4; p++) {
        int idx = p * 256 + tid;
        const uint32_t* src = (idx < 512) ? Ah : Al;
        int rem = idx & 511;
        int r = rem >> 2, c = rem & 3;
        uint32_t dst = st_u32 + (((idx < 512) ? 0 : 2560) + r * 20 + c * 4) * 4;
        cpasync16(dst, src + (size_t)(row0 + r) * K2 + kp0 + c * 4);
    }
    #pragma unroll
    for (int p = 0; p < 4; p++) {
        int idx = p * 256 + tid;
        const uint32_t* src = (idx < 512) ? Bh : Bl;
        int rem = idx & 511;
        int r = rem >> 2, c = rem & 3;
        uint32_t dst = st_u32 + ((5120 + ((idx < 512) ? 0 : 2560)) + r * 20 + c * 4) * 4;
        cpasync16(dst, src + (size_t)(col0 + r) * K2 + kp0 + c * 4);
    }
}

template <int MODE>
__global__ __launch_bounds__(256) void gemm_planes(
    const uint32_t* __restrict__ Ah, const uint32_t* __restrict__ Al,
    const uint32_t* __restrict__ Bh, const uint32_t* __restrict__ Bl,
    const float* __restrict__ bias,
    float* __restrict__ outf,            // MODE 1
    uint32_t* __restrict__ qkvp,         // MODE 0
    int M, int N, int K)
{
    extern __shared__ uint32_t sm[];     // 2 stages x 10240 u32
    const uint32_t sm_u = smem_u32(sm);

    const int tid  = threadIdx.x;
    const int wid  = tid >> 5, lane = tid & 31;
    const int gid  = lane >> 2, tig = lane & 3;
    const int wm   = wid & 3;
    const int wn   = wid >> 2;
    const int row0 = blockIdx.y * 128;
    const int col0 = blockIdx.x * 128;
    const int K2   = K >> 1;
    const int NK   = K >> 5;

    float cf[2][8][4];
    #pragma unroll
    for (int ma = 0; ma < 2; ma++)
        #pragma unroll
        for (int na = 0; na < 8; na++)
            #pragma unroll
            for (int r = 0; r < 4; r++) cf[ma][na][r] = 0.f;

    gemm_issue(sm_u, Ah, Al, Bh, Bl, row0, col0, K2, 0, tid);
    CP_COMMIT();

    for (int kt = 0; kt < NK; kt++) {
        const int s = kt & 1;
        if (kt + 1 < NK) {
            gemm_issue(sm_u + (s ^ 1) * 10240 * 4, Ah, Al, Bh, Bl,
                       row0, col0, K2, (kt + 1) << 4, tid);
            CP_COMMIT();
            CP_WAIT1();
        } else {
            CP_WAIT0();
        }
        __syncthreads();

        const uint32_t* a_hi = sm + s * 10240;
        const uint32_t* a_lo = a_hi + 2560;
        const uint32_t* b_hi = a_hi + 5120;
        const uint32_t* b_lo = a_hi + 7680;

        #pragma unroll
        for (int ss = 0; ss < 2; ss++) {
            uint32_t ah[2][4], al[2][4];
            #pragma unroll
            for (int ma = 0; ma < 2; ma++) {
                const int base = (wm * 32 + ma * 16 + gid) * 20 + 8 * ss + tig;
                ah[ma][0] = a_hi[base];       ah[ma][1] = a_hi[base + 160];
                ah[ma][2] = a_hi[base + 4];   ah[ma][3] = a_hi[base + 164];
                al[ma][0] = a_lo[base];       al[ma][1] = a_lo[base + 160];
                al[ma][2] = a_lo[base + 4];   al[ma][3] = a_lo[base + 164];
            }
            #pragma unroll
            for (int na = 0; na < 8; na++) {
                const int bb = (wn * 64 + na * 8 + gid) * 20 + 8 * ss + tig;
                uint32_t b0h = b_hi[bb], b1h = b_hi[bb + 4];
                uint32_t b0l = b_lo[bb], b1l = b_lo[bb + 4];
                #pragma unroll
                for (int ma = 0; ma < 2; ma++) {
                    mma_bf16(cf[ma][na], ah[ma][0], ah[ma][1], ah[ma][2], ah[ma][3], b0h, b1h);
                    mma_bf16(cf[ma][na], ah[ma][0], ah[ma][1], ah[ma][2], ah[ma][3], b0l, b1l);
                    mma_bf16(cf[ma][na], al[ma][0], al[ma][1], al[ma][2], al[ma][3], b0h, b1h);
                }
            }
        }
        __syncthreads();
    }

    if (MODE == 1) {
        #pragma unroll
        for (int ma = 0; ma < 2; ma++) {
            const int rg = row0 + wm * 32 + ma * 16 + gid;
            #pragma unroll
            for (int na = 0; na < 8; na++) {
                const int cg = col0 + wn * 64 + na * 8 + tig * 2;
                const float bx0 = bias[cg], bx1 = bias[cg + 1];
                *(float2*)(outf + (size_t)rg * N + cg) =
                    make_float2(cf[ma][na][0] + bx0, cf[ma][na][1] + bx1);
                *(float2*)(outf + (size_t)(rg + 8) * N + cg) =
                    make_float2(cf[ma][na][2] + bx0, cf[ma][na][3] + bx1);
            }
        }
    } else {
        // split and scatter into Q/K/V planes
        const int which = col0 / 768;
        uint32_t* dh = qkvp + (size_t)(which * 2 + 0) * PSZ;
        uint32_t* dl = qkvp + (size_t)(which * 2 + 1) * PSZ;
        const int lc0 = col0 - which * 768;
        #pragma unroll
        for (int ma = 0; ma < 2; ma++) {
            const int rg = row0 + wm * 32 + ma * 16 + gid;
            #pragma unroll
            for (int na = 0; na < 8; na++) {
                const int gc = col0 + wn * 64 + na * 8 + tig * 2;
                const int pr = (lc0 >> 1) + wn * 32 + na * 4 + tig;
                const float bx0 = bias[gc], bx1 = bias[gc + 1];
                uint32_t h, l;
                split2(cf[ma][na][0] + bx0, cf[ma][na][1] + bx1, h, l);
                dh[(size_t)rg * 384 + pr] = h;
                dl[(size_t)rg * 384 + pr] = l;
                split2(cf[ma][na][2] + bx0, cf[ma][na][3] + bx1, h, l);
                dh[(size_t)(rg + 8) * 384 + pr] = h;
                dl[(size_t)(rg + 8) * 384 + pr] = l;
            }
        }
    }
}

// ---------------------------------------------------------------------------
// Flash attention: plane-native, cp.async 2-stage K/V pipeline.
// grid = (T/128, B*H); 256 threads = 8 warps x 16 q-rows.
// smem per stage (u32): kh@0 [64][36], kl@2304, vh@4608 [32][72], vl@6912.
// ---------------------------------------------------------------------------
__device__ __forceinline__ void flash_issue(
    uint32_t st_u32,
    const uint32_t* kh, const uint32_t* kl,
    const uint32_t* vth, const uint32_t* vtl,
    int tok0, int vrow0, int h, int tid)
{
    #pragma unroll
    for (int p = 0; p < 4; p++) {
        int idx = p * 256 + tid;
        const uint32_t* src = (idx < 512) ? kh : kl;
        int rem = idx & 511;
        int r = rem >> 3, c = rem & 7;
        uint32_t dst = st_u32 + (((idx < 512) ? 0 : 2304) + r * 36 + c * 4) * 4;
        cpasync16(dst, src + (size_t)(tok0 + r) * 384 + h * 32 + c * 4);
    }
    #pragma unroll
    for (int p = 0; p < 4; p++) {
        int idx = p * 256 + tid;
        const uint32_t* src = (idx < 512) ? vth : vtl;
        int rem = idx & 511;
        int r = rem >> 4, c = rem & 15;
        uint32_t dst = st_u32 + ((4608 + ((idx < 512) ? 0 : 2304)) + r * 72 + c * 4) * 4;
        cpasync16(dst, src + (size_t)(vrow0 + r) * 768 + h * 64 + c * 4);
    }
}

__global__ __launch_bounds__(256) void flash_planes(
    const uint32_t* __restrict__ qkvp, const uint32_t* __restrict__ vt,
    uint32_t* __restrict__ yh, uint32_t* __restrict__ yl)
{
    extern __shared__ uint32_t sm[];       // 2 stages x 9216 u32
    const uint32_t sm_u = smem_u32(sm);

    const int tid = threadIdx.x;
    const int wid = tid >> 5, lane = tid & 31;
    const int gid = lane >> 2, tig = lane & 3;
    const int bx = blockIdx.x;
    const int b  = blockIdx.y / HH;
    const int h  = blockIdx.y % HH;
    const int q0 = bx * 128;

    const uint32_t* qph = qkvp;
    const uint32_t* qpl = qkvp + (size_t)PSZ;
    const uint32_t* kph = qkvp + (size_t)2 * PSZ;
    const uint32_t* kpl = qkvp + (size_t)3 * PSZ;
    const uint32_t* vth = vt;
    const uint32_t* vtl = vt + (size_t)2048 * 768;

    // Q fragments straight from planes
    const int grow0 = b * 2048 + q0 + wid * 16 + gid;
    uint32_t qh[4][4], ql[4][4];
    #pragma unroll
    for (int ks = 0; ks < 4; ks++) {
        const int pr = h * 32 + 8 * ks + tig;
        qh[ks][0] = qph[(size_t)grow0 * 384 + pr];
        qh[ks][1] = qph[(size_t)(grow0 + 8) * 384 + pr];
        qh[ks][2] = qph[(size_t)grow0 * 384 + pr + 4];
        qh[ks][3] = qph[(size_t)(grow0 + 8) * 384 + pr + 4];
        ql[ks][0] = qpl[(size_t)grow0 * 384 + pr];
        ql[ks][1] = qpl[(size_t)(grow0 + 8) * 384 + pr];
        ql[ks][2] = qpl[(size_t)grow0 * 384 + pr + 4];
        ql[ks][3] = qpl[(size_t)(grow0 + 8) * 384 + pr + 4];
    }

    float of[8][4];
    #pragma unroll
    for (int na = 0; na < 8; na++)
        #pragma unroll
        for (int r = 0; r < 4; r++) of[na][r] = 0.f;
    float m0 = -1e30f, m1 = -1e30f, l0 = 0.f, l1 = 0.f;
    const float scale = 0.125f;
    const int r0g = q0 + wid * 16 + gid;
    const int r1g = r0g + 8;

    const int nkt = 2 * bx + 2;
    flash_issue(sm_u, kph, kpl, vth, vtl,
                b * 2048, b * 1024, h, tid);
    CP_COMMIT();

    for (int kt = 0; kt < nkt; kt++) {
        const int s = kt & 1;
        if (kt + 1 < nkt) {
            flash_issue(sm_u + (s ^ 1) * 9216 * 4, kph, kpl, vth, vtl,
                        b * 2048 + (kt + 1) * 64, b * 1024 + (kt + 1) * 32, h, tid);
            CP_COMMIT();
            CP_WAIT1();
        } else {
            CP_WAIT0();
        }
        __syncthreads();

        if (kt * 64 <= q0 + wid * 16 + 15) {   // warp-level causal skip
            const uint32_t* k_hi = sm + s * 9216;
            const uint32_t* k_lo = k_hi + 2304;
            const uint32_t* v_hi = k_hi + 4608;
            const uint32_t* v_lo = k_hi + 6912;

            // ---- S = Q @ K^T ----
            float sf[8][4];
            #pragma unroll
            for (int na = 0; na < 8; na++)
                #pragma unroll
                for (int r = 0; r < 4; r++) sf[na][r] = 0.f;

            #pragma unroll
            for (int ks = 0; ks < 4; ks++) {
                #pragma unroll
                for (int na = 0; na < 8; na++) {
                    const int kk = (na * 8 + gid) * 36 + 8 * ks + tig;
                    uint32_t b0h = k_hi[kk], b1h = k_hi[kk + 4];
                    uint32_t b0l = k_lo[kk], b1l = k_lo[kk + 4];
                    mma_bf16(sf[na], qh[ks][0], qh[ks][1], qh[ks][2], qh[ks][3], b0h, b1h);
                    mma_bf16(sf[na], qh[ks][0], qh[ks][1], qh[ks][2], qh[ks][3], b0l, b1l);
                    mma_bf16(sf[na], ql[ks][0], ql[ks][1], ql[ks][2], ql[ks][3], b0h, b1h);
                }
            }

            // ---- scale + causal mask ----
            const bool need_mask = (kt >= 2 * bx);
            #pragma unroll
            for (int na = 0; na < 8; na++) {
                const int cg = kt * 64 + na * 8 + tig * 2;
                sf[na][0] *= scale; sf[na][1] *= scale;
                sf[na][2] *= scale; sf[na][3] *= scale;
                if (need_mask) {
                    if (cg     > r0g) sf[na][0] = -1e30f;
                    if (cg + 1 > r0g) sf[na][1] = -1e30f;
                    if (cg     > r1g) sf[na][2] = -1e30f;
                    if (cg + 1 > r1g) sf[na][3] = -1e30f;
                }
            }

            // ---- online softmax ----
            float rm0 = -1e30f, rm1 = -1e30f;
            #pragma unroll
            for (int na = 0; na < 8; na++) {
                rm0 = fmaxf(rm0, fmaxf(sf[na][0], sf[na][1]));
                rm1 = fmaxf(rm1, fmaxf(sf[na][2], sf[na][3]));
            }
            rm0 = fmaxf(rm0, __shfl_xor_sync(0xffffffffu, rm0, 1));
            rm0 = fmaxf(rm0, __shfl_xor_sync(0xffffffffu, rm0, 2));
            rm1 = fmaxf(rm1, __shfl_xor_sync(0xffffffffu, rm1, 1));
            rm1 = fmaxf(rm1, __shfl_xor_sync(0xffffffffu, rm1, 2));
            const float mn0 = fmaxf(m0, rm0), mn1 = fmaxf(m1, rm1);
            const float c0 = __expf(m0 - mn0), c1 = __expf(m1 - mn1);
            float rs0 = 0.f, rs1 = 0.f;
            #pragma unroll
            for (int na = 0; na < 8; na++) {
                sf[na][0] = __expf(sf[na][0] - mn0);
                sf[na][1] = __expf(sf[na][1] - mn0);
                sf[na][2] = __expf(sf[na][2] - mn1);
                sf[na][3] = __expf(sf[na][3] - mn1);
                rs0 += sf[na][0] + sf[na][1];
                rs1 += sf[na][2] + sf[na][3];
            }
            rs0 += __shfl_xor_sync(0xffffffffu, rs0, 1);
            rs0 += __shfl_xor_sync(0xffffffffu, rs0, 2);
            rs1 += __shfl_xor_sync(0xffffffffu, rs1, 1);
            rs1 += __shfl_xor_sync(0xffffffffu, rs1, 2);
            l0 = l0 * c0 + rs0; m0 = mn0;
            l1 = l1 * c1 + rs1; m1 = mn1;
            #pragma unroll
            for (int na = 0; na < 8; na++) {
                of[na][0] *= c0; of[na][1] *= c0;
                of[na][2] *= c1; of[na][3] *= c1;
            }

            // ---- O += P @ V (P packed from C-fragments) ----
            #pragma unroll
            for (int ks = 0; ks < 4; ks++) {
                uint32_t pah[4], pal[4];
                split2(sf[2 * ks][0],     sf[2 * ks][1],     pah[0], pal[0]);
                split2(sf[2 * ks][2],     sf[2 * ks][3],     pah[1], pal[1]);
                split2(sf[2 * ks + 1][0], sf[2 * ks + 1][1], pah[2], pal[2]);
                split2(sf[2 * ks + 1][2], sf[2 * ks + 1][3], pah[3], pal[3]);
                #pragma unroll
                for (int na = 0; na < 8; na++) {
                    const int d = na * 8 + gid;
                    const int o0 = (8 * ks + tig) * 72 + d;
                    const int o1 = (8 * ks + tig + 4) * 72 + d;
                    uint32_t b0h = v_hi[o0], b1h = v_hi[o1];
                    uint32_t b0l = v_lo[o0], b1l = v_lo[o1];
                    mma_bf16(of[na], pah[0], pah[1], pah[2], pah[3], b0h, b1h);
                    mma_bf16(of[na], pah[0], pah[1], pah[2], pah[3], b0l, b1l);
                    mma_bf16(of[na], pal[0], pal[1], pal[2], pal[3], b0h, b1h);
                }
            }
        }
        __syncthreads();
    }

    // ---- epilogue: y planes ----
    const float i0 = 1.f / l0, i1 = 1.f / l1;
    const int gr0 = b * 2048 + r0g;
    #pragma unroll
    for (int na = 0; na < 8; na++) {
        const int pr = h * 32 + na * 4 + tig;
        uint32_t h0, lo0;
        split2(of[na][0] * i0, of[na][1] * i0, h0, lo0);
        yh[(size_t)gr0 * 384 + pr] = h0;
        yl[(size_t)gr0 * 384 + pr] = lo0;
        split2(of[na][2] * i1, of[na][3] * i1, h0, lo0);
        yh[(size_t)(gr0 + 8) * 384 + pr] = h0;
        yl[(size_t)(gr0 + 8) * 384 + pr] = lo0;
    }
}

extern "C" void kernel_launch(void* const* d_in, const int* in_sizes, int n_in,
                              void* d_out, int out_size)
{
    const float* x      = (const float*)d_in[0];
    const float* W_attn = (const float*)d_in[1];
    const float* b_attn = (const float*)d_in[2];
    const float* W_proj = (const float*)d_in[3];
    const float* b_proj = (const float*)d_in[4];
    float* out = (float*)d_out;

    uint32_t *qkvp, *vt, *xp, *yp, *wt;
    cudaGetSymbolAddress((void**)&qkvp, g_qkvp);
    cudaGetSymbolAddress((void**)&vt, g_vt);
    cudaGetSymbolAddress((void**)&xp, g_xp);
    cudaGetSymbolAddress((void**)&yp, g_yp);
    cudaGetSymbolAddress((void**)&wt, g_wt);

    const int GEMM_SMEM  = 2 * 10240 * 4;   // 81920
    const int FLASH_SMEM = 2 * 9216 * 4;    // 73728
    cudaFuncSetAttribute(gemm_planes<0>,
                         cudaFuncAttributeMaxDynamicSharedMemorySize, GEMM_SMEM);
    cudaFuncSetAttribute(gemm_planes<1>,
                         cudaFuncAttributeMaxDynamicSharedMemorySize, GEMM_SMEM);
    cudaFuncSetAttribute(flash_planes,
                         cudaFuncAttributeMaxDynamicSharedMemorySize, FLASH_SMEM);

    // prep: x planes + W_attn^T planes
    split_x<<<786432 / 256, 256>>>(x, xp, xp + PSZ);
    transpose_split<<<dim3(C3 / 32, CC / 32), dim3(32, 8)>>>(
        W_attn, wt, wt + (size_t)C3 * CC / 2, CC, C3);

    // 1) QKV gemm -> q/k/v planes
    gemm_planes<0><<<dim3(C3 / 128, MTOT / 128), 256, GEMM_SMEM>>>(
        xp, xp + PSZ, wt, wt + (size_t)C3 * CC / 2, b_attn,
        nullptr, qkvp, MTOT, C3, CC);

    // 2) V -> token-pair-major planes
    pack_vt<<<(2048 * 384) / 256, 256>>>(
        qkvp + (size_t)4 * PSZ, qkvp + (size_t)5 * PSZ, vt, vt + (size_t)2048 * 768);

    // 3) flash attention -> y planes
    flash_planes<<<dim3(TT / 128, BB * HH), 256, FLASH_SMEM>>>(
        qkvp, vt, yp, yp + PSZ);

    // 4) W_proj^T planes ; out = y @ W_proj + b_proj
    transpose_split<<<dim3(CC / 32, CC / 32), dim3(32, 8)>>>(
        W_proj, wt, wt + (size_t)CC * CC / 2, CC, CC);
    gemm_planes<1><<<dim3(CC / 128, MTOT / 128), 256, GEMM_SMEM>>>(
        yp, yp + PSZ, wt, wt + (size_t)CC * CC / 2, b_proj,
        out, nullptr, MTOT, CC, CC);
}

// round 7
// speedup vs baseline: 2.2949x; 1.0095x over previous
#include <cuda_runtime.h>
#include <cuda_bf16.h>
#include <math.h>
#include <cstdint>

#define BB 2
#define TT 2048
#define CC 768
#define HH 12
#define HS 64
#define C3 2304
#define MTOT (BB*TT)          // 4096
#define PSZ (4096*384)        // u32 per plane for [M][K/2] with K=768

// Scratch (allocation-free contract)
__device__ uint32_t g_qkvp[6 * (size_t)PSZ];        // q_hi,q_lo,k_hi,k_lo,v_hi,v_lo
__device__ uint32_t g_vt[2 * (size_t)2048 * 768];   // V token-pair-major planes
__device__ uint32_t g_xp[2 * (size_t)PSZ];          // x planes
__device__ uint32_t g_yp[2 * (size_t)PSZ];          // y planes
__device__ uint32_t g_wt[(size_t)CC * C3];          // W^T planes (hi then lo)

// ---------------------------------------------------------------------------
// Helpers
// ---------------------------------------------------------------------------
__device__ __forceinline__ uint32_t smem_u32(const void* p) {
    uint32_t a;
    asm("{ .reg .u64 t; cvta.to.shared.u64 t, %1; cvt.u32.u64 %0, t; }"
        : "=r"(a) : "l"(p));
    return a;
}

__device__ __forceinline__ void mma_bf16(float c[4],
    uint32_t a0, uint32_t a1, uint32_t a2, uint32_t a3,
    uint32_t b0, uint32_t b1)
{
    asm("mma.sync.aligned.m16n8k16.row.col.f32.bf16.bf16.f32 "
        "{%0,%1,%2,%3}, {%4,%5,%6,%7}, {%8,%9}, {%0,%1,%2,%3};"
        : "+f"(c[0]), "+f"(c[1]), "+f"(c[2]), "+f"(c[3])
        : "r"(a0), "r"(a1), "r"(a2), "r"(a3), "r"(b0), "r"(b1));
}

__device__ __forceinline__ void ldm_x4(uint32_t& r0, uint32_t& r1,
                                       uint32_t& r2, uint32_t& r3, uint32_t addr)
{
    asm volatile("ldmatrix.sync.aligned.m8n8.x4.shared.b16 {%0,%1,%2,%3}, [%4];"
        : "=r"(r0), "=r"(r1), "=r"(r2), "=r"(r3) : "r"(addr));
}

__device__ __forceinline__ void split2(float x, float y, uint32_t& hi, uint32_t& lo)
{
    __nv_bfloat162 h = __floats2bfloat162_rn(x, y);
    hi = *reinterpret_cast<uint32_t*>(&h);
    float hx = __bfloat162float(h.x);
    float hy = __bfloat162float(h.y);
    __nv_bfloat162 l = __floats2bfloat162_rn(x - hx, y - hy);
    lo = *reinterpret_cast<uint32_t*>(&l);
}

__device__ __forceinline__ void cpasync16(uint32_t dst, const void* src) {
    asm volatile("cp.async.cg.shared.global [%0], [%1], 16;"
                 :: "r"(dst), "l"(src));
}
#define CP_COMMIT() asm volatile("cp.async.commit_group;" ::: "memory")
#define CP_WAIT1()  asm volatile("cp.async.wait_group 1;" ::: "memory")
#define CP_WAIT0()  asm volatile("cp.async.wait_group 0;" ::: "memory")

// ---------------------------------------------------------------------------
// Prep kernels
// ---------------------------------------------------------------------------
__global__ void split_x(const float* __restrict__ x,
                        uint32_t* __restrict__ xh, uint32_t* __restrict__ xl)
{
    int idx = blockIdx.x * 256 + threadIdx.x;
    int r = idx / 192, j2 = idx % 192;
    float4 v = *(const float4*)(x + (size_t)r * 768 + 4 * j2);
    uint32_t h0, l0, h1, l1;
    split2(v.x, v.y, h0, l0);
    split2(v.z, v.w, h1, l1);
    size_t o = (size_t)r * 384 + 2 * j2;
    *(uint2*)(xh + o) = make_uint2(h0, h1);
    *(uint2*)(xl + o) = make_uint2(l0, l1);
}

__global__ void transpose_split(const float* __restrict__ in,
                                uint32_t* __restrict__ out_hi,
                                uint32_t* __restrict__ out_lo,
                                int K, int N)
{
    __shared__ float t[32][33];
    int n0 = blockIdx.x << 5, k0 = blockIdx.y << 5;
    int x = threadIdx.x, y = threadIdx.y;
    #pragma unroll
    for (int i = 0; i < 32; i += 8)
        t[y + i][x] = in[(size_t)(k0 + y + i) * N + n0 + x];
    __syncthreads();
    const int xp = x & 15, plane = x >> 4;
    #pragma unroll
    for (int i = 0; i < 32; i += 8) {
        int n = n0 + y + i;
        uint32_t h, l;
        split2(t[2 * xp][y + i], t[2 * xp + 1][y + i], h, l);
        size_t o = (size_t)n * (K / 2) + k0 / 2 + xp;
        if (plane == 0) out_hi[o] = h;
        else            out_lo[o] = l;
    }
}

__global__ void pack_vt(const uint32_t* __restrict__ vh,
                        const uint32_t* __restrict__ vl,
                        uint32_t* __restrict__ vth, uint32_t* __restrict__ vtl)
{
    int idx = blockIdx.x * 256 + threadIdx.x;
    int bp = idx / 384, j = idx % 384;
    size_t s0 = (size_t)(2 * bp) * 384 + j;
    size_t s1 = s0 + 384;
    uint32_t ah = vh[s0], bh = vh[s1];
    uint32_t al = vl[s0], bl = vl[s1];
    size_t o = (size_t)bp * 768 + 2 * j;
    vth[o]     = __byte_perm(ah, bh, 0x5410);
    vth[o + 1] = __byte_perm(ah, bh, 0x7632);
    vtl[o]     = __byte_perm(al, bl, 0x5410);
    vtl[o + 1] = __byte_perm(al, bl, 0x7632);
}

// ---------------------------------------------------------------------------
// Plane GEMM (ldmatrix fragment loads)
// ---------------------------------------------------------------------------
__device__ __forceinline__ void gemm_issue(
    uint32_t st_u32,
    const uint32_t* Ah, const uint32_t* Al,
    const uint32_t* Bh, const uint32_t* Bl,
    int row0, int col0, int K2, int kp0, int tid)
{
    #pragma unroll
    for (int p = 0; p < 4; p++) {
        int idx = p * 256 + tid;
        const uint32_t* src = (idx < 512) ? Ah : Al;
        int rem = idx & 511;
        int r = rem >> 2, c = rem & 3;
        uint32_t dst = st_u32 + (((idx < 512) ? 0 : 2560) + r * 20 + c * 4) * 4;
        cpasync16(dst, src + (size_t)(row0 + r) * K2 + kp0 + c * 4);
    }
    #pragma unroll
    for (int p = 0; p < 4; p++) {
        int idx = p * 256 + tid;
        const uint32_t* src = (idx < 512) ? Bh : Bl;
        int rem = idx & 511;
        int r = rem >> 2, c = rem & 3;
        uint32_t dst = st_u32 + ((5120 + ((idx < 512) ? 0 : 2560)) + r * 20 + c * 4) * 4;
        cpasync16(dst, src + (size_t)(col0 + r) * K2 + kp0 + c * 4);
    }
}

template <int MODE>
__global__ __launch_bounds__(256) void gemm_planes(
    const uint32_t* __restrict__ Ah, const uint32_t* __restrict__ Al,
    const uint32_t* __restrict__ Bh, const uint32_t* __restrict__ Bl,
    const float* __restrict__ bias,
    float* __restrict__ outf,
    uint32_t* __restrict__ qkvp,
    int M, int N, int K)
{
    extern __shared__ uint32_t sm[];     // 2 stages x 10240 u32
    const uint32_t sm_u = smem_u32(sm);

    const int tid  = threadIdx.x;
    const int wid  = tid >> 5, lane = tid & 31;
    const int gid  = lane >> 2, tig = lane & 3;
    const int wm   = wid & 3;
    const int wn   = wid >> 2;
    const int row0 = blockIdx.y * 128;
    const int col0 = blockIdx.x * 128;
    const int K2   = K >> 1;
    const int NK   = K >> 5;

    // ldmatrix per-lane byte offsets (within a stage)
    const int lane7 = lane & 7;
    const int aRow  = wm * 32 + lane7 + ((lane >> 3) & 1) * 8;
    const int aColB = ((lane >> 4) & 1) * 16;                     // kpair-col *4B
    const uint32_t aOff = (uint32_t)(aRow * 80) + aColB;          // stride 20 u32
    const int bRow  = wn * 64 + lane7 + ((lane >> 4) & 1) * 8;
    const int bColB = ((lane >> 3) & 1) * 16;
    const uint32_t bOff = 5120 * 4 + (uint32_t)(bRow * 80) + bColB;

    float cf[2][8][4];
    #pragma unroll
    for (int ma = 0; ma < 2; ma++)
        #pragma unroll
        for (int na = 0; na < 8; na++)
            #pragma unroll
            for (int r = 0; r < 4; r++) cf[ma][na][r] = 0.f;

    gemm_issue(sm_u, Ah, Al, Bh, Bl, row0, col0, K2, 0, tid);
    CP_COMMIT();

    for (int kt = 0; kt < NK; kt++) {
        const int s = kt & 1;
        if (kt + 1 < NK) {
            gemm_issue(sm_u + (s ^ 1) * 40960, Ah, Al, Bh, Bl,
                       row0, col0, K2, (kt + 1) << 4, tid);
            CP_COMMIT();
            CP_WAIT1();
        } else {
            CP_WAIT0();
        }
        __syncthreads();

        const uint32_t stage = sm_u + s * 40960;

        #pragma unroll
        for (int ss = 0; ss < 2; ss++) {
            const uint32_t ssb = ss * 32;                // 8 u32 col step
            uint32_t ah[2][4], al[2][4];
            #pragma unroll
            for (int ma = 0; ma < 2; ma++) {
                ldm_x4(ah[ma][0], ah[ma][1], ah[ma][2], ah[ma][3],
                       stage + aOff + ma * 1280 + ssb);
                ldm_x4(al[ma][0], al[ma][1], al[ma][2], al[ma][3],
                       stage + 2560 * 4 + aOff + ma * 1280 + ssb);
            }
            #pragma unroll
            for (int j = 0; j < 4; j++) {
                uint32_t bh0, bh1, bh2, bh3, bl0, bl1, bl2, bl3;
                ldm_x4(bh0, bh1, bh2, bh3, stage + bOff + j * 1280 + ssb);
                ldm_x4(bl0, bl1, bl2, bl3, stage + 2560 * 4 + bOff + j * 1280 + ssb);
                #pragma unroll
                for (int ma = 0; ma < 2; ma++) {
                    mma_bf16(cf[ma][2 * j], ah[ma][0], ah[ma][1], ah[ma][2], ah[ma][3], bh0, bh1);
                    mma_bf16(cf[ma][2 * j], ah[ma][0], ah[ma][1], ah[ma][2], ah[ma][3], bl0, bl1);
                    mma_bf16(cf[ma][2 * j], al[ma][0], al[ma][1], al[ma][2], al[ma][3], bh0, bh1);
                    mma_bf16(cf[ma][2 * j + 1], ah[ma][0], ah[ma][1], ah[ma][2], ah[ma][3], bh2, bh3);
                    mma_bf16(cf[ma][2 * j + 1], ah[ma][0], ah[ma][1], ah[ma][2], ah[ma][3], bl2, bl3);
                    mma_bf16(cf[ma][2 * j + 1], al[ma][0], al[ma][1], al[ma][2], al[ma][3], bh2, bh3);
                }
            }
        }
        __syncthreads();
    }

    if (MODE == 1) {
        #pragma unroll
        for (int ma = 0; ma < 2; ma++) {
            const int rg = row0 + wm * 32 + ma * 16 + gid;
            #pragma unroll
            for (int na = 0; na < 8; na++) {
                const int cg = col0 + wn * 64 + na * 8 + tig * 2;
                const float bx0 = bias[cg], bx1 = bias[cg + 1];
                *(float2*)(outf + (size_t)rg * N + cg) =
                    make_float2(cf[ma][na][0] + bx0, cf[ma][na][1] + bx1);
                *(float2*)(outf + (size_t)(rg + 8) * N + cg) =
                    make_float2(cf[ma][na][2] + bx0, cf[ma][na][3] + bx1);
            }
        }
    } else {
        const int which = col0 / 768;
        uint32_t* dh = qkvp + (size_t)(which * 2 + 0) * PSZ;
        uint32_t* dl = qkvp + (size_t)(which * 2 + 1) * PSZ;
        const int lc0 = col0 - which * 768;
        #pragma unroll
        for (int ma = 0; ma < 2; ma++) {
            const int rg = row0 + wm * 32 + ma * 16 + gid;
            #pragma unroll
            for (int na = 0; na < 8; na++) {
                const int gc = col0 + wn * 64 + na * 8 + tig * 2;
                const int pr = (lc0 >> 1) + wn * 32 + na * 4 + tig;
                const float bx0 = bias[gc], bx1 = bias[gc + 1];
                uint32_t h, l;
                split2(cf[ma][na][0] + bx0, cf[ma][na][1] + bx1, h, l);
                dh[(size_t)rg * 384 + pr] = h;
                dl[(size_t)rg * 384 + pr] = l;
                split2(cf[ma][na][2] + bx0, cf[ma][na][3] + bx1, h, l);
                dh[(size_t)(rg + 8) * 384 + pr] = h;
                dl[(size_t)(rg + 8) * 384 + pr] = l;
            }
        }
    }
}

// ---------------------------------------------------------------------------
// Flash attention (ldmatrix K-frags, heavy-first grid order)
// ---------------------------------------------------------------------------
__device__ __forceinline__ void flash_issue(
    uint32_t st_u32,
    const uint32_t* kh, const uint32_t* kl,
    const uint32_t* vth, const uint32_t* vtl,
    int tok0, int vrow0, int h, int tid)
{
    #pragma unroll
    for (int p = 0; p < 4; p++) {
        int idx = p * 256 + tid;
        const uint32_t* src = (idx < 512) ? kh : kl;
        int rem = idx & 511;
        int r = rem >> 3, c = rem & 7;
        uint32_t dst = st_u32 + (((idx < 512) ? 0 : 2304) + r * 36 + c * 4) * 4;
        cpasync16(dst, src + (size_t)(tok0 + r) * 384 + h * 32 + c * 4);
    }
    #pragma unroll
    for (int p = 0; p < 4; p++) {
        int idx = p * 256 + tid;
        const uint32_t* src = (idx < 512) ? vth : vtl;
        int rem = idx & 511;
        int r = rem >> 4, c = rem & 15;
        uint32_t dst = st_u32 + ((4608 + ((idx < 512) ? 0 : 2304)) + r * 72 + c * 4) * 4;
        cpasync16(dst, src + (size_t)(vrow0 + r) * 768 + h * 64 + c * 4);
    }
}

__global__ __launch_bounds__(256) void flash_planes(
    const uint32_t* __restrict__ qkvp, const uint32_t* __restrict__ vt,
    uint32_t* __restrict__ yh, uint32_t* __restrict__ yl)
{
    extern __shared__ uint32_t sm[];       // 2 stages x 9216 u32
    const uint32_t sm_u = smem_u32(sm);

    const int tid = threadIdx.x;
    const int wid = tid >> 5, lane = tid & 31;
    const int gid = lane >> 2, tig = lane & 3;
    const int bx = (gridDim.x - 1) - blockIdx.x;   // heavy CTAs launch first
    const int b  = blockIdx.y / HH;
    const int h  = blockIdx.y % HH;
    const int q0 = bx * 128;

    const uint32_t* qph = qkvp;
    const uint32_t* qpl = qkvp + (size_t)PSZ;
    const uint32_t* kph = qkvp + (size_t)2 * PSZ;
    const uint32_t* kpl = qkvp + (size_t)3 * PSZ;
    const uint32_t* vth = vt;
    const uint32_t* vtl = vt + (size_t)2048 * 768;

    // K-frag ldmatrix per-lane byte offset (stride 36 u32)
    const int lane7 = lane & 7;
    const int kRow  = lane7 + ((lane >> 4) & 1) * 8;
    const int kColB = ((lane >> 3) & 1) * 16;
    const uint32_t kOff = (uint32_t)(kRow * 144) + kColB;

    // Q fragments straight from planes
    const int grow0 = b * 2048 + q0 + wid * 16 + gid;
    uint32_t qh[4][4], ql[4][4];
    #pragma unroll
    for (int ks = 0; ks < 4; ks++) {
        const int pr = h * 32 + 8 * ks + tig;
        qh[ks][0] = qph[(size_t)grow0 * 384 + pr];
        qh[ks][1] = qph[(size_t)(grow0 + 8) * 384 + pr];
        qh[ks][2] = qph[(size_t)grow0 * 384 + pr + 4];
        qh[ks][3] = qph[(size_t)(grow0 + 8) * 384 + pr + 4];
        ql[ks][0] = qpl[(size_t)grow0 * 384 + pr];
        ql[ks][1] = qpl[(size_t)(grow0 + 8) * 384 + pr];
        ql[ks][2] = qpl[(size_t)grow0 * 384 + pr + 4];
        ql[ks][3] = qpl[(size_t)(grow0 + 8) * 384 + pr + 4];
    }

    float of[8][4];
    #pragma unroll
    for (int na = 0; na < 8; na++)
        #pragma unroll
        for (int r = 0; r < 4; r++) of[na][r] = 0.f;
    float m0 = -1e30f, m1 = -1e30f, l0 = 0.f, l1 = 0.f;
    const float scale = 0.125f;
    const int r0g = q0 + wid * 16 + gid;
    const int r1g = r0g + 8;

    const int nkt = 2 * bx + 2;
    flash_issue(sm_u, kph, kpl, vth, vtl, b * 2048, b * 1024, h, tid);
    CP_COMMIT();

    for (int kt = 0; kt < nkt; kt++) {
        const int s = kt & 1;
        if (kt + 1 < nkt) {
            flash_issue(sm_u + (s ^ 1) * 9216 * 4, kph, kpl, vth, vtl,
                        b * 2048 + (kt + 1) * 64, b * 1024 + (kt + 1) * 32, h, tid);
            CP_COMMIT();
            CP_WAIT1();
        } else {
            CP_WAIT0();
        }
        __syncthreads();

        if (kt * 64 <= q0 + wid * 16 + 15) {
            const uint32_t stage = sm_u + s * 9216 * 4;
            const uint32_t* v_hi = sm + s * 9216 + 4608;
            const uint32_t* v_lo = v_hi + 2304;

            // ---- S = Q @ K^T ----
            float sf[8][4];
            #pragma unroll
            for (int na = 0; na < 8; na++)
                #pragma unroll
                for (int r = 0; r < 4; r++) sf[na][r] = 0.f;

            #pragma unroll
            for (int ks = 0; ks < 4; ks++) {
                const uint32_t ksb = ks * 32;
                #pragma unroll
                for (int j = 0; j < 4; j++) {
                    uint32_t bh0, bh1, bh2, bh3, bl0, bl1, bl2, bl3;
                    ldm_x4(bh0, bh1, bh2, bh3, stage + kOff + j * 2304 + ksb);
                    ldm_x4(bl0, bl1, bl2, bl3, stage + 2304 * 4 + kOff + j * 2304 + ksb);
                    mma_bf16(sf[2 * j], qh[ks][0], qh[ks][1], qh[ks][2], qh[ks][3], bh0, bh1);
                    mma_bf16(sf[2 * j], qh[ks][0], qh[ks][1], qh[ks][2], qh[ks][3], bl0, bl1);
                    mma_bf16(sf[2 * j], ql[ks][0], ql[ks][1], ql[ks][2], ql[ks][3], bh0, bh1);
                    mma_bf16(sf[2 * j + 1], qh[ks][0], qh[ks][1], qh[ks][2], qh[ks][3], bh2, bh3);
                    mma_bf16(sf[2 * j + 1], qh[ks][0], qh[ks][1], qh[ks][2], qh[ks][3], bl2, bl3);
                    mma_bf16(sf[2 * j + 1], ql[ks][0], ql[ks][1], ql[ks][2], ql[ks][3], bh2, bh3);
                }
            }

            // ---- scale + causal mask ----
            const bool need_mask = (kt >= 2 * bx);
            #pragma unroll
            for (int na = 0; na < 8; na++) {
                const int cg = kt * 64 + na * 8 + tig * 2;
                sf[na][0] *= scale; sf[na][1] *= scale;
                sf[na][2] *= scale; sf[na][3] *= scale;
                if (need_mask) {
                    if (cg     > r0g) sf[na][0] = -1e30f;
                    if (cg + 1 > r0g) sf[na][1] = -1e30f;
                    if (cg     > r1g) sf[na][2] = -1e30f;
                    if (cg + 1 > r1g) sf[na][3] = -1e30f;
                }
            }

            // ---- online softmax ----
            float rm0 = -1e30f, rm1 = -1e30f;
            #pragma unroll
            for (int na = 0; na < 8; na++) {
                rm0 = fmaxf(rm0, fmaxf(sf[na][0], sf[na][1]));
                rm1 = fmaxf(rm1, fmaxf(sf[na][2], sf[na][3]));
            }
            rm0 = fmaxf(rm0, __shfl_xor_sync(0xffffffffu, rm0, 1));
            rm0 = fmaxf(rm0, __shfl_xor_sync(0xffffffffu, rm0, 2));
            rm1 = fmaxf(rm1, __shfl_xor_sync(0xffffffffu, rm1, 1));
            rm1 = fmaxf(rm1, __shfl_xor_sync(0xffffffffu, rm1, 2));
            const float mn0 = fmaxf(m0, rm0), mn1 = fmaxf(m1, rm1);
            const float c0 = __expf(m0 - mn0), c1 = __expf(m1 - mn1);
            float rs0 = 0.f, rs1 = 0.f;
            #pragma unroll
            for (int na = 0; na < 8; na++) {
                sf[na][0] = __expf(sf[na][0] - mn0);
                sf[na][1] = __expf(sf[na][1] - mn0);
                sf[na][2] = __expf(sf[na][2] - mn1);
                sf[na][3] = __expf(sf[na][3] - mn1);
                rs0 += sf[na][0] + sf[na][1];
                rs1 += sf[na][2] + sf[na][3];
            }
            rs0 += __shfl_xor_sync(0xffffffffu, rs0, 1);
            rs0 += __shfl_xor_sync(0xffffffffu, rs0, 2);
            rs1 += __shfl_xor_sync(0xffffffffu, rs1, 1);
            rs1 += __shfl_xor_sync(0xffffffffu, rs1, 2);
            l0 = l0 * c0 + rs0; m0 = mn0;
            l1 = l1 * c1 + rs1; m1 = mn1;
            #pragma unroll
            for (int na = 0; na < 8; na++) {
                of[na][0] *= c0; of[na][1] *= c0;
                of[na][2] *= c1; of[na][3] *= c1;
            }

            // ---- O += P @ V ----
            #pragma unroll
            for (int ks = 0; ks < 4; ks++) {
                uint32_t pah[4], pal[4];
                split2(sf[2 * ks][0],     sf[2 * ks][1],     pah[0], pal[0]);
                split2(sf[2 * ks][2],     sf[2 * ks][3],     pah[1], pal[1]);
                split2(sf[2 * ks + 1][0], sf[2 * ks + 1][1], pah[2], pal[2]);
                split2(sf[2 * ks + 1][2], sf[2 * ks + 1][3], pah[3], pal[3]);
                #pragma unroll
                for (int na = 0; na < 8; na++) {
                    const int d = na * 8 + gid;
                    const int o0 = (8 * ks + tig) * 72 + d;
                    const int o1 = (8 * ks + tig + 4) * 72 + d;
                    uint32_t b0h = v_hi[o0], b1h = v_hi[o1];
                    uint32_t b0l = v_lo[o0], b1l = v_lo[o1];
                    mma_bf16(of[na], pah[0], pah[1], pah[2], pah[3], b0h, b1h);
                    mma_bf16(of[na], pah[0], pah[1], pah[2], pah[3], b0l, b1l);
                    mma_bf16(of[na], pal[0], pal[1], pal[2], pal[3], b0h, b1h);
                }
            }
        }
        __syncthreads();
    }

    // ---- epilogue: y planes ----
    const float i0 = 1.f / l0, i1 = 1.f / l1;
    const int gr0 = b * 2048 + r0g;
    #pragma unroll
    for (int na = 0; na < 8; na++) {
        const int pr = h * 32 + na * 4 + tig;
        uint32_t h0, lo0;
        split2(of[na][0] * i0, of[na][1] * i0, h0, lo0);
        yh[(size_t)gr0 * 384 + pr] = h0;
        yl[(size_t)gr0 * 384 + pr] = lo0;
        split2(of[na][2] * i1, of[na][3] * i1, h0, lo0);
        yh[(size_t)(gr0 + 8) * 384 + pr] = h0;
        yl[(size_t)(gr0 + 8) * 384 + pr] = lo0;
    }
}

extern "C" void kernel_launch(void* const* d_in, const int* in_sizes, int n_in,
                              void* d_out, int out_size)
{
    const float* x      = (const float*)d_in[0];
    const float* W_attn = (const float*)d_in[1];
    const float* b_attn = (const float*)d_in[2];
    const float* W_proj = (const float*)d_in[3];
    const float* b_proj = (const float*)d_in[4];
    float* out = (float*)d_out;

    uint32_t *qkvp, *vt, *xp, *yp, *wt;
    cudaGetSymbolAddress((void**)&qkvp, g_qkvp);
    cudaGetSymbolAddress((void**)&vt, g_vt);
    cudaGetSymbolAddress((void**)&xp, g_xp);
    cudaGetSymbolAddress((void**)&yp, g_yp);
    cudaGetSymbolAddress((void**)&wt, g_wt);

    const int GEMM_SMEM  = 2 * 10240 * 4;   // 81920
    const int FLASH_SMEM = 2 * 9216 * 4;    // 73728
    cudaFuncSetAttribute(gemm_planes<0>,
                         cudaFuncAttributeMaxDynamicSharedMemorySize, GEMM_SMEM);
    cudaFuncSetAttribute(gemm_planes<1>,
                         cudaFuncAttributeMaxDynamicSharedMemorySize, GEMM_SMEM);
    cudaFuncSetAttribute(flash_planes,
                         cudaFuncAttributeMaxDynamicSharedMemorySize, FLASH_SMEM);

    split_x<<<786432 / 256, 256>>>(x, xp, xp + PSZ);
    transpose_split<<<dim3(C3 / 32, CC / 32), dim3(32, 8)>>>(
        W_attn, wt, wt + (size_t)C3 * CC / 2, CC, C3);

    gemm_planes<0><<<dim3(C3 / 128, MTOT / 128), 256, GEMM_SMEM>>>(
        xp, xp + PSZ, wt, wt + (size_t)C3 * CC / 2, b_attn,
        nullptr, qkvp, MTOT, C3, CC);

    pack_vt<<<(2048 * 384) / 256, 256>>>(
        qkvp + (size_t)4 * PSZ, qkvp + (size_t)5 * PSZ, vt, vt + (size_t)2048 * 768);

    flash_planes<<<dim3(TT / 128, BB * HH), 256, FLASH_SMEM>>>(
        qkvp, vt, yp, yp + PSZ);

    transpose_split<<<dim3(CC / 32, CC / 32), dim3(32, 8)>>>(
        W_proj, wt, wt + (size_t)CC * CC / 2, CC, CC);
    gemm_planes<1><<<dim3(CC / 128, MTOT / 128), 256, GEMM_SMEM>>>(
        yp, yp + PSZ, wt, wt + (size_t)CC * CC / 2, b_proj,
        out, nullptr, MTOT, CC, CC);
}

// round 9
// speedup vs baseline: 2.5091x; 1.0933x over previous
#include <cuda_runtime.h>
#include <cuda_bf16.h>
#include <math.h>
#include <cstdint>

#define BB 2
#define TT 2048
#define CC 768
#define HH 12
#define HS 64
#define C3 2304
#define MTOT (BB*TT)          // 4096
#define PSZ (4096*384)        // u32 per plane for [M][K/2] with K=768

// Scratch (allocation-free contract)
__device__ uint32_t g_qkvp[6 * (size_t)PSZ];        // q_hi,q_lo,k_hi,k_lo,v_hi,v_lo
__device__ uint32_t g_vt[2 * (size_t)2048 * 768];   // V token-pair-major planes
__device__ uint32_t g_xp[2 * (size_t)PSZ];          // x planes
__device__ uint32_t g_yp[2 * (size_t)PSZ];          // y planes
__device__ uint32_t g_wt[(size_t)CC * C3];          // W_attn^T planes (hi then lo)
__device__ uint32_t g_wt2[2 * (size_t)CC * CC / 2]; // W_proj^T planes (hi then lo)

// ---------------------------------------------------------------------------
// Helpers
// ---------------------------------------------------------------------------
__device__ __forceinline__ uint32_t smem_u32(const void* p) {
    uint32_t a;
    asm("{ .reg .u64 t; cvta.to.shared.u64 t, %1; cvt.u32.u64 %0, t; }"
        : "=r"(a) : "l"(p));
    return a;
}

__device__ __forceinline__ void mma_bf16(float c[4],
    uint32_t a0, uint32_t a1, uint32_t a2, uint32_t a3,
    uint32_t b0, uint32_t b1)
{
    asm("mma.sync.aligned.m16n8k16.row.col.f32.bf16.bf16.f32 "
        "{%0,%1,%2,%3}, {%4,%5,%6,%7}, {%8,%9}, {%0,%1,%2,%3};"
        : "+f"(c[0]), "+f"(c[1]), "+f"(c[2]), "+f"(c[3])
        : "r"(a0), "r"(a1), "r"(a2), "r"(a3), "r"(b0), "r"(b1));
}

__device__ __forceinline__ void ldm_x4(uint32_t& r0, uint32_t& r1,
                                       uint32_t& r2, uint32_t& r3, uint32_t addr)
{
    asm volatile("ldmatrix.sync.aligned.m8n8.x4.shared.b16 {%0,%1,%2,%3}, [%4];"
        : "=r"(r0), "=r"(r1), "=r"(r2), "=r"(r3) : "r"(addr));
}

__device__ __forceinline__ void split2(float x, float y, uint32_t& hi, uint32_t& lo)
{
    __nv_bfloat162 h = __floats2bfloat162_rn(x, y);
    hi = *reinterpret_cast<uint32_t*>(&h);
    float hx = __bfloat162float(h.x);
    float hy = __bfloat162float(h.y);
    __nv_bfloat162 l = __floats2bfloat162_rn(x - hx, y - hy);
    lo = *reinterpret_cast<uint32_t*>(&l);
}

__device__ __forceinline__ void cpasync16(uint32_t dst, const void* src) {
    asm volatile("cp.async.cg.shared.global [%0], [%1], 16;"
                 :: "r"(dst), "l"(src));
}
#define CP_COMMIT() asm volatile("cp.async.commit_group;" ::: "memory")
#define CP_WAIT1()  asm volatile("cp.async.wait_group 1;" ::: "memory")
#define CP_WAIT0()  asm volatile("cp.async.wait_group 0;" ::: "memory")

// ---------------------------------------------------------------------------
// Prep kernels
// ---------------------------------------------------------------------------
__global__ void split_x(const float* __restrict__ x,
                        uint32_t* __restrict__ xh, uint32_t* __restrict__ xl)
{
    int idx = blockIdx.x * 256 + threadIdx.x;
    int r = idx / 192, j2 = idx % 192;
    float4 v = *(const float4*)(x + (size_t)r * 768 + 4 * j2);
    uint32_t h0, l0, h1, l1;
    split2(v.x, v.y, h0, l0);
    split2(v.z, v.w, h1, l1);
    size_t o = (size_t)r * 384 + 2 * j2;
    *(uint2*)(xh + o) = make_uint2(h0, h1);
    *(uint2*)(xl + o) = make_uint2(l0, l1);
}

__global__ void transpose_split(const float* __restrict__ in,
                                uint32_t* __restrict__ out_hi,
                                uint32_t* __restrict__ out_lo,
                                int K, int N)
{
    __shared__ float t[32][33];
    int n0 = blockIdx.x << 5, k0 = blockIdx.y << 5;
    int x = threadIdx.x, y = threadIdx.y;
    #pragma unroll
    for (int i = 0; i < 32; i += 8)
        t[y + i][x] = in[(size_t)(k0 + y + i) * N + n0 + x];
    __syncthreads();
    const int xp = x & 15, plane = x >> 4;
    #pragma unroll
    for (int i = 0; i < 32; i += 8) {
        int n = n0 + y + i;
        uint32_t h, l;
        split2(t[2 * xp][y + i], t[2 * xp + 1][y + i], h, l);
        size_t o = (size_t)n * (K / 2) + k0 / 2 + xp;
        if (plane == 0) out_hi[o] = h;
        else            out_lo[o] = l;
    }
}

__global__ void pack_vt(const uint32_t* __restrict__ vh,
                        const uint32_t* __restrict__ vl,
                        uint32_t* __restrict__ vth, uint32_t* __restrict__ vtl)
{
    int idx = blockIdx.x * 256 + threadIdx.x;
    int bp = idx / 384, j = idx % 384;
    size_t s0 = (size_t)(2 * bp) * 384 + j;
    size_t s1 = s0 + 384;
    uint32_t ah = vh[s0], bh = vh[s1];
    uint32_t al = vl[s0], bl = vl[s1];
    size_t o = (size_t)bp * 768 + 2 * j;
    vth[o]     = __byte_perm(ah, bh, 0x5410);
    vth[o + 1] = __byte_perm(ah, bh, 0x7632);
    vtl[o]     = __byte_perm(al, bl, 0x5410);
    vtl[o + 1] = __byte_perm(al, bl, 0x7632);
}

// ---------------------------------------------------------------------------
// Plane GEMM (ldmatrix fragment loads, occupancy-2)
// ---------------------------------------------------------------------------
__device__ __forceinline__ void gemm_issue(
    uint32_t st_u32,
    const uint32_t* Ah, const uint32_t* Al,
    const uint32_t* Bh, const uint32_t* Bl,
    int row0, int col0, int K2, int kp0, int tid)
{
    #pragma unroll
    for (int p = 0; p < 4; p++) {
        int idx = p * 256 + tid;
        const uint32_t* src = (idx < 512) ? Ah : Al;
        int rem = idx & 511;
        int r = rem >> 2, c = rem & 3;
        uint32_t dst = st_u32 + (((idx < 512) ? 0 : 2560) + r * 20 + c * 4) * 4;
        cpasync16(dst, src + (size_t)(row0 + r) * K2 + kp0 + c * 4);
    }
    #pragma unroll
    for (int p = 0; p < 4; p++) {
        int idx = p * 256 + tid;
        const uint32_t* src = (idx < 512) ? Bh : Bl;
        int rem = idx & 511;
        int r = rem >> 2, c = rem & 3;
        uint32_t dst = st_u32 + ((5120 + ((idx < 512) ? 0 : 2560)) + r * 20 + c * 4) * 4;
        cpasync16(dst, src + (size_t)(col0 + r) * K2 + kp0 + c * 4);
    }
}

template <int MODE>
__global__ __launch_bounds__(256, 2) void gemm_planes(
    const uint32_t* __restrict__ Ah, const uint32_t* __restrict__ Al,
    const uint32_t* __restrict__ Bh, const uint32_t* __restrict__ Bl,
    const float* __restrict__ bias,
    float* __restrict__ outf,
    uint32_t* __restrict__ qkvp,
    int M, int N, int K)
{
    extern __shared__ uint32_t sm[];     // 2 stages x 10240 u32
    const uint32_t sm_u = smem_u32(sm);

    const int tid  = threadIdx.x;
    const int wid  = tid >> 5, lane = tid & 31;
    const int gid  = lane >> 2, tig = lane & 3;
    const int wm   = wid & 3;
    const int wn   = wid >> 2;
    const int row0 = blockIdx.y * 128;
    const int col0 = blockIdx.x * 128;
    const int K2   = K >> 1;
    const int NK   = K >> 5;

    const int lane7 = lane & 7;
    const int aRow  = wm * 32 + lane7 + ((lane >> 3) & 1) * 8;
    const int aColB = ((lane >> 4) & 1) * 16;
    const uint32_t aOff = (uint32_t)(aRow * 80) + aColB;
    const int bRow  = wn * 64 + lane7 + ((lane >> 4) & 1) * 8;
    const int bColB = ((lane >> 3) & 1) * 16;
    const uint32_t bOff = 5120 * 4 + (uint32_t)(bRow * 80) + bColB;

    float cf[2][8][4];
    #pragma unroll
    for (int ma = 0; ma < 2; ma++)
        #pragma unroll
        for (int na = 0; na < 8; na++)
            #pragma unroll
            for (int r = 0; r < 4; r++) cf[ma][na][r] = 0.f;

    gemm_issue(sm_u, Ah, Al, Bh, Bl, row0, col0, K2, 0, tid);
    CP_COMMIT();

    for (int kt = 0; kt < NK; kt++) {
        const int s = kt & 1;
        if (kt + 1 < NK) {
            gemm_issue(sm_u + (s ^ 1) * 40960, Ah, Al, Bh, Bl,
                       row0, col0, K2, (kt + 1) << 4, tid);
            CP_COMMIT();
            CP_WAIT1();
        } else {
            CP_WAIT0();
        }
        __syncthreads();

        const uint32_t stage = sm_u + s * 40960;

        #pragma unroll
        for (int ss = 0; ss < 2; ss++) {
            const uint32_t ssb = ss * 32;
            uint32_t ah[2][4], al[2][4];
            #pragma unroll
            for (int ma = 0; ma < 2; ma++) {
                ldm_x4(ah[ma][0], ah[ma][1], ah[ma][2], ah[ma][3],
                       stage + aOff + ma * 1280 + ssb);
                ldm_x4(al[ma][0], al[ma][1], al[ma][2], al[ma][3],
                       stage + 2560 * 4 + aOff + ma * 1280 + ssb);
            }
            #pragma unroll
            for (int j = 0; j < 4; j++) {
                uint32_t bh0, bh1, bh2, bh3, bl0, bl1, bl2, bl3;
                ldm_x4(bh0, bh1, bh2, bh3, stage + bOff + j * 1280 + ssb);
                ldm_x4(bl0, bl1, bl2, bl3, stage + 2560 * 4 + bOff + j * 1280 + ssb);
                #pragma unroll
                for (int ma = 0; ma < 2; ma++) {
                    mma_bf16(cf[ma][2 * j], ah[ma][0], ah[ma][1], ah[ma][2], ah[ma][3], bh0, bh1);
                    mma_bf16(cf[ma][2 * j], ah[ma][0], ah[ma][1], ah[ma][2], ah[ma][3], bl0, bl1);
                    mma_bf16(cf[ma][2 * j], al[ma][0], al[ma][1], al[ma][2], al[ma][3], bh0, bh1);
                    mma_bf16(cf[ma][2 * j + 1], ah[ma][0], ah[ma][1], ah[ma][2], ah[ma][3], bh2, bh3);
                    mma_bf16(cf[ma][2 * j + 1], ah[ma][0], ah[ma][1], ah[ma][2], ah[ma][3], bl2, bl3);
                    mma_bf16(cf[ma][2 * j + 1], al[ma][0], al[ma][1], al[ma][2], al[ma][3], bh2, bh3);
                }
            }
        }
        __syncthreads();
    }

    if (MODE == 1) {
        #pragma unroll
        for (int ma = 0; ma < 2; ma++) {
            const int rg = row0 + wm * 32 + ma * 16 + gid;
            #pragma unroll
            for (int na = 0; na < 8; na++) {
                const int cg = col0 + wn * 64 + na * 8 + tig * 2;
                const float bx0 = bias[cg], bx1 = bias[cg + 1];
                *(float2*)(outf + (size_t)rg * N + cg) =
                    make_float2(cf[ma][na][0] + bx0, cf[ma][na][1] + bx1);
                *(float2*)(outf + (size_t)(rg + 8) * N + cg) =
                    make_float2(cf[ma][na][2] + bx0, cf[ma][na][3] + bx1);
            }
        }
    } else {
        const int which = col0 / 768;
        uint32_t* dh = qkvp + (size_t)(which * 2 + 0) * PSZ;
        uint32_t* dl = qkvp + (size_t)(which * 2 + 1) * PSZ;
        const int lc0 = col0 - which * 768;
        #pragma unroll
        for (int ma = 0; ma < 2; ma++) {
            const int rg = row0 + wm * 32 + ma * 16 + gid;
            #pragma unroll
            for (int na = 0; na < 8; na++) {
                const int gc = col0 + wn * 64 + na * 8 + tig * 2;
                const int pr = (lc0 >> 1) + wn * 32 + na * 4 + tig;
                const float bx0 = bias[gc], bx1 = bias[gc + 1];
                uint32_t h, l;
                split2(cf[ma][na][0] + bx0, cf[ma][na][1] + bx1, h, l);
                dh[(size_t)rg * 384 + pr] = h;
                dl[(size_t)rg * 384 + pr] = l;
                split2(cf[ma][na][2] + bx0, cf[ma][na][3] + bx1, h, l);
                dh[(size_t)(rg + 8) * 384 + pr] = h;
                dl[(size_t)(rg + 8) * 384 + pr] = l;
            }
        }
    }
}

// ---------------------------------------------------------------------------
// Flash attention (occupancy-2)
// ---------------------------------------------------------------------------
__device__ __forceinline__ void flash_issue(
    uint32_t st_u32,
    const uint32_t* kh, const uint32_t* kl,
    const uint32_t* vth, const uint32_t* vtl,
    int tok0, int vrow0, int h, int tid)
{
    #pragma unroll
    for (int p = 0; p < 4; p++) {
        int idx = p * 256 + tid;
        const uint32_t* src = (idx < 512) ? kh : kl;
        int rem = idx & 511;
        int r = rem >> 3, c = rem & 7;
        uint32_t dst = st_u32 + (((idx < 512) ? 0 : 2304) + r * 36 + c * 4) * 4;
        cpasync16(dst, src + (size_t)(tok0 + r) * 384 + h * 32 + c * 4);
    }
    #pragma unroll
    for (int p = 0; p < 4; p++) {
        int idx = p * 256 + tid;
        const uint32_t* src = (idx < 512) ? vth : vtl;
        int rem = idx & 511;
        int r = rem >> 4, c = rem & 15;
        uint32_t dst = st_u32 + ((4608 + ((idx < 512) ? 0 : 2304)) + r * 72 + c * 4) * 4;
        cpasync16(dst, src + (size_t)(vrow0 + r) * 768 + h * 64 + c * 4);
    }
}

__global__ __launch_bounds__(256, 2) void flash_planes(
    const uint32_t* __restrict__ qkvp, const uint32_t* __restrict__ vt,
    uint32_t* __restrict__ yh, uint32_t* __restrict__ yl)
{
    extern __shared__ uint32_t sm[];       // 2 stages x 9216 u32
    const uint32_t sm_u = smem_u32(sm);

    const int tid = threadIdx.x;
    const int wid = tid >> 5, lane = tid & 31;
    const int gid = lane >> 2, tig = lane & 3;
    const int bx = (gridDim.x - 1) - blockIdx.x;   // heavy CTAs launch first
    const int b  = blockIdx.y / HH;
    const int h  = blockIdx.y % HH;
    const int q0 = bx * 128;

    const uint32_t* qph = qkvp;
    const uint32_t* qpl = qkvp + (size_t)PSZ;
    const uint32_t* kph = qkvp + (size_t)2 * PSZ;
    const uint32_t* kpl = qkvp + (size_t)3 * PSZ;
    const uint32_t* vth = vt;
    const uint32_t* vtl = vt + (size_t)2048 * 768;

    const int lane7 = lane & 7;
    const int kRow  = lane7 + ((lane >> 4) & 1) * 8;
    const int kColB = ((lane >> 3) & 1) * 16;
    const uint32_t kOff = (uint32_t)(kRow * 144) + kColB;

    const int grow0 = b * 2048 + q0 + wid * 16 + gid;
    uint32_t qh[4][4], ql[4][4];
    #pragma unroll
    for (int ks = 0; ks < 4; ks++) {
        const int pr = h * 32 + 8 * ks + tig;
        qh[ks][0] = qph[(size_t)grow0 * 384 + pr];
        qh[ks][1] = qph[(size_t)(grow0 + 8) * 384 + pr];
        qh[ks][2] = qph[(size_t)grow0 * 384 + pr + 4];
        qh[ks][3] = qph[(size_t)(grow0 + 8) * 384 + pr + 4];
        ql[ks][0] = qpl[(size_t)grow0 * 384 + pr];
        ql[ks][1] = qpl[(size_t)(grow0 + 8) * 384 + pr];
        ql[ks][2] = qpl[(size_t)grow0 * 384 + pr + 4];
        ql[ks][3] = qpl[(size_t)(grow0 + 8) * 384 + pr + 4];
    }

    float of[8][4];
    #pragma unroll
    for (int na = 0; na < 8; na++)
        #pragma unroll
        for (int r = 0; r < 4; r++) of[na][r] = 0.f;
    float m0 = -1e30f, m1 = -1e30f, l0 = 0.f, l1 = 0.f;
    const float scale = 0.125f;
    const int r0g = q0 + wid * 16 + gid;
    const int r1g = r0g + 8;

    const int nkt = 2 * bx + 2;
    flash_issue(sm_u, kph, kpl, vth, vtl, b * 2048, b * 1024, h, tid);
    CP_COMMIT();

    for (int kt = 0; kt < nkt; kt++) {
        const int s = kt & 1;
        if (kt + 1 < nkt) {
            flash_issue(sm_u + (s ^ 1) * 9216 * 4, kph, kpl, vth, vtl,
                        b * 2048 + (kt + 1) * 64, b * 1024 + (kt + 1) * 32, h, tid);
            CP_COMMIT();
            CP_WAIT1();
        } else {
            CP_WAIT0();
        }
        __syncthreads();

        if (kt * 64 <= q0 + wid * 16 + 15) {
            const uint32_t stage = sm_u + s * 9216 * 4;
            const uint32_t* v_hi = sm + s * 9216 + 4608;
            const uint32_t* v_lo = v_hi + 2304;

            // ---- S = Q @ K^T ----
            float sf[8][4];
            #pragma unroll
            for (int na = 0; na < 8; na++)
                #pragma unroll
                for (int r = 0; r < 4; r++) sf[na][r] = 0.f;

            #pragma unroll
            for (int ks = 0; ks < 4; ks++) {
                const uint32_t ksb = ks * 32;
                #pragma unroll
                for (int j = 0; j < 4; j++) {
                    uint32_t bh0, bh1, bh2, bh3, bl0, bl1, bl2, bl3;
                    ldm_x4(bh0, bh1, bh2, bh3, stage + kOff + j * 2304 + ksb);
                    ldm_x4(bl0, bl1, bl2, bl3, stage + 2304 * 4 + kOff + j * 2304 + ksb);
                    mma_bf16(sf[2 * j], qh[ks][0], qh[ks][1], qh[ks][2], qh[ks][3], bh0, bh1);
                    mma_bf16(sf[2 * j], qh[ks][0], qh[ks][1], qh[ks][2], qh[ks][3], bl0, bl1);
                    mma_bf16(sf[2 * j], ql[ks][0], ql[ks][1], ql[ks][2], ql[ks][3], bh0, bh1);
                    mma_bf16(sf[2 * j + 1], qh[ks][0], qh[ks][1], qh[ks][2], qh[ks][3], bh2, bh3);
                    mma_bf16(sf[2 * j + 1], qh[ks][0], qh[ks][1], qh[ks][2], qh[ks][3], bl2, bl3);
                    mma_bf16(sf[2 * j + 1], ql[ks][0], ql[ks][1], ql[ks][2], ql[ks][3], bh2, bh3);
                }
            }

            // ---- scale + causal mask ----
            const bool need_mask = (kt >= 2 * bx);
            #pragma unroll
            for (int na = 0; na < 8; na++) {
                const int cg = kt * 64 + na * 8 + tig * 2;
                sf[na][0] *= scale; sf[na][1] *= scale;
                sf[na][2] *= scale; sf[na][3] *= scale;
                if (need_mask) {
                    if (cg     > r0g) sf[na][0] = -1e30f;
                    if (cg + 1 > r0g) sf[na][1] = -1e30f;
                    if (cg     > r1g) sf[na][2] = -1e30f;
                    if (cg + 1 > r1g) sf[na][3] = -1e30f;
                }
            }

            // ---- online softmax ----
            float rm0 = -1e30f, rm1 = -1e30f;
            #pragma unroll
            for (int na = 0; na < 8; na++) {
                rm0 = fmaxf(rm0, fmaxf(sf[na][0], sf[na][1]));
                rm1 = fmaxf(rm1, fmaxf(sf[na][2], sf[na][3]));
            }
            rm0 = fmaxf(rm0, __shfl_xor_sync(0xffffffffu, rm0, 1));
            rm0 = fmaxf(rm0, __shfl_xor_sync(0xffffffffu, rm0, 2));
            rm1 = fmaxf(rm1, __shfl_xor_sync(0xffffffffu, rm1, 1));
            rm1 = fmaxf(rm1, __shfl_xor_sync(0xffffffffu, rm1, 2));
            const float mn0 = fmaxf(m0, rm0), mn1 = fmaxf(m1, rm1);
            const float c0 = __expf(m0 - mn0), c1 = __expf(m1 - mn1);
            float rs0 = 0.f, rs1 = 0.f;
            #pragma unroll
            for (int na = 0; na < 8; na++) {
                sf[na][0] = __expf(sf[na][0] - mn0);
                sf[na][1] = __expf(sf[na][1] - mn0);
                sf[na][2] = __expf(sf[na][2] - mn1);
                sf[na][3] = __expf(sf[na][3] - mn1);
                rs0 += sf[na][0] + sf[na][1];
                rs1 += sf[na][2] + sf[na][3];
            }
            rs0 += __shfl_xor_sync(0xffffffffu, rs0, 1);
            rs0 += __shfl_xor_sync(0xffffffffu, rs0, 2);
            rs1 += __shfl_xor_sync(0xffffffffu, rs1, 1);
            rs1 += __shfl_xor_sync(0xffffffffu, rs1, 2);
            l0 = l0 * c0 + rs0; m0 = mn0;
            l1 = l1 * c1 + rs1; m1 = mn1;
            #pragma unroll
            for (int na = 0; na < 8; na++) {
                of[na][0] *= c0; of[na][1] *= c0;
                of[na][2] *= c1; of[na][3] *= c1;
            }

            // ---- O += P @ V ----
            #pragma unroll
            for (int ks = 0; ks < 4; ks++) {
                uint32_t pah[4], pal[4];
                split2(sf[2 * ks][0],     sf[2 * ks][1],     pah[0], pal[0]);
                split2(sf[2 * ks][2],     sf[2 * ks][3],     pah[1], pal[1]);
                split2(sf[2 * ks + 1][0], sf[2 * ks + 1][1], pah[2], pal[2]);
                split2(sf[2 * ks + 1][2], sf[2 * ks + 1][3], pah[3], pal[3]);
                #pragma unroll
                for (int na = 0; na < 8; na++) {
                    const int d = na * 8 + gid;
                    const int o0 = (8 * ks + tig) * 72 + d;
                    const int o1 = (8 * ks + tig + 4) * 72 + d;
                    uint32_t b0h = v_hi[o0], b1h = v_hi[o1];
                    uint32_t b0l = v_lo[o0], b1l = v_lo[o1];
                    mma_bf16(of[na], pah[0], pah[1], pah[2], pah[3], b0h, b1h);
                    mma_bf16(of[na], pah[0], pah[1], pah[2], pah[3], b0l, b1l);
                    mma_bf16(of[na], pal[0], pal[1], pal[2], pal[3], b0h, b1h);
                }
            }
        }
        __syncthreads();
    }

    // ---- epilogue: y planes ----
    const float i0 = 1.f / l0, i1 = 1.f / l1;
    const int gr0 = b * 2048 + r0g;
    #pragma unroll
    for (int na = 0; na < 8; na++) {
        const int pr = h * 32 + na * 4 + tig;
        uint32_t h0, lo0;
        split2(of[na][0] * i0, of[na][1] * i0, h0, lo0);
        yh[(size_t)gr0 * 384 + pr] = h0;
        yl[(size_t)gr0 * 384 + pr] = lo0;
        split2(of[na][2] * i1, of[na][3] * i1, h0, lo0);
        yh[(size_t)(gr0 + 8) * 384 + pr] = h0;
        yl[(size_t)(gr0 + 8) * 384 + pr] = lo0;
    }
}

extern "C" void kernel_launch(void* const* d_in, const int* in_sizes, int n_in,
                              void* d_out, int out_size)
{
    const float* x      = (const float*)d_in[0];
    const float* W_attn = (const float*)d_in[1];
    const float* b_attn = (const float*)d_in[2];
    const float* W_proj = (const float*)d_in[3];
    const float* b_proj = (const float*)d_in[4];
    float* out = (float*)d_out;

    uint32_t *qkvp, *vt, *xp, *yp, *wt, *wt2;
    cudaGetSymbolAddress((void**)&qkvp, g_qkvp);
    cudaGetSymbolAddress((void**)&vt, g_vt);
    cudaGetSymbolAddress((void**)&xp, g_xp);
    cudaGetSymbolAddress((void**)&yp, g_yp);
    cudaGetSymbolAddress((void**)&wt, g_wt);
    cudaGetSymbolAddress((void**)&wt2, g_wt2);

    const int GEMM_SMEM  = 2 * 10240 * 4;   // 81920
    const int FLASH_SMEM = 2 * 9216 * 4;    // 73728
    cudaFuncSetAttribute(gemm_planes<0>,
                         cudaFuncAttributeMaxDynamicSharedMemorySize, GEMM_SMEM);
    cudaFuncSetAttribute(gemm_planes<1>,
                         cudaFuncAttributeMaxDynamicSharedMemorySize, GEMM_SMEM);
    cudaFuncSetAttribute(flash_planes,
                         cudaFuncAttributeMaxDynamicSharedMemorySize, FLASH_SMEM);

    // launch order chosen so ncu's "-s 5" lands on flash_planes (index 5)
    split_x<<<786432 / 256, 256>>>(x, xp, xp + PSZ);                       // 0
    transpose_split<<<dim3(C3 / 32, CC / 32), dim3(32, 8)>>>(              // 1
        W_attn, wt, wt + (size_t)C3 * CC / 2, CC, C3);
    transpose_split<<<dim3(CC / 32, CC / 32), dim3(32, 8)>>>(              // 2
        W_proj, wt2, wt2 + (size_t)CC * CC / 2, CC, CC);

    gemm_planes<0><<<dim3(C3 / 128, MTOT / 128), 256, GEMM_SMEM>>>(        // 3
        xp, xp + PSZ, wt, wt + (size_t)C3 * CC / 2, b_attn,
        nullptr, qkvp, MTOT, C3, CC);

    pack_vt<<<(2048 * 384) / 256, 256>>>(                                  // 4
        qkvp + (size_t)4 * PSZ, qkvp + (size_t)5 * PSZ, vt, vt + (size_t)2048 * 768);

    flash_planes<<<dim3(TT / 128, BB * HH), 256, FLASH_SMEM>>>(            // 5
        qkvp, vt, yp, yp + PSZ);

    gemm_planes<1><<<dim3(CC / 128, MTOT / 128), 256, GEMM_SMEM>>>(        // 6
        yp, yp + PSZ, wt2, wt2 + (size_t)CC * CC / 2, b_proj,
        out, nullptr, MTOT, CC, CC);
}

// round 10
// speedup vs baseline: 2.7866x; 1.1106x over previous
#include <cuda_runtime.h>
#include <cuda_bf16.h>
#include <cuda_fp16.h>
#include <math.h>
#include <cstdint>

#define BB 2
#define TT 2048
#define CC 768
#define HH 12
#define HS 64
#define C3 2304
#define MTOT (BB*TT)          // 4096
#define PSZ (4096*384)        // u32 per plane for [M][K/2] with K=768
#define QSCALE 0.18033688011112042f   // 0.125 * log2(e)

// Scratch (allocation-free contract)
__device__ uint32_t g_qkvp[6 * (size_t)PSZ];        // q_hi,q_lo,k_hi,k_lo,v_hi,v_lo (bf16 planes)
__device__ uint32_t g_vt[2 * (size_t)2048 * 768];   // V token-pair-major FP16 hi/lo planes
__device__ uint32_t g_xp[2 * (size_t)PSZ];          // x planes
__device__ uint32_t g_yp[2 * (size_t)PSZ];          // y planes
__device__ uint32_t g_wt[(size_t)CC * C3];          // W_attn^T planes (hi then lo)
__device__ uint32_t g_wt2[2 * (size_t)CC * CC / 2]; // W_proj^T planes (hi then lo)

// ---------------------------------------------------------------------------
// Helpers
// ---------------------------------------------------------------------------
__device__ __forceinline__ uint32_t smem_u32(const void* p) {
    uint32_t a;
    asm("{ .reg .u64 t; cvta.to.shared.u64 t, %1; cvt.u32.u64 %0, t; }"
        : "=r"(a) : "l"(p));
    return a;
}

__device__ __forceinline__ void mma_bf16(float c[4],
    uint32_t a0, uint32_t a1, uint32_t a2, uint32_t a3,
    uint32_t b0, uint32_t b1)
{
    asm("mma.sync.aligned.m16n8k16.row.col.f32.bf16.bf16.f32 "
        "{%0,%1,%2,%3}, {%4,%5,%6,%7}, {%8,%9}, {%0,%1,%2,%3};"
        : "+f"(c[0]), "+f"(c[1]), "+f"(c[2]), "+f"(c[3])
        : "r"(a0), "r"(a1), "r"(a2), "r"(a3), "r"(b0), "r"(b1));
}

__device__ __forceinline__ void mma_f16(float c[4],
    uint32_t a0, uint32_t a1, uint32_t a2, uint32_t a3,
    uint32_t b0, uint32_t b1)
{
    asm("mma.sync.aligned.m16n8k16.row.col.f32.f16.f16.f32 "
        "{%0,%1,%2,%3}, {%4,%5,%6,%7}, {%8,%9}, {%0,%1,%2,%3};"
        : "+f"(c[0]), "+f"(c[1]), "+f"(c[2]), "+f"(c[3])
        : "r"(a0), "r"(a1), "r"(a2), "r"(a3), "r"(b0), "r"(b1));
}

__device__ __forceinline__ void ldm_x4(uint32_t& r0, uint32_t& r1,
                                       uint32_t& r2, uint32_t& r3, uint32_t addr)
{
    asm volatile("ldmatrix.sync.aligned.m8n8.x4.shared.b16 {%0,%1,%2,%3}, [%4];"
        : "=r"(r0), "=r"(r1), "=r"(r2), "=r"(r3) : "r"(addr));
}

// fp32 pair -> bf16x2 hi + bf16x2 lo (residual)
__device__ __forceinline__ void split2(float x, float y, uint32_t& hi, uint32_t& lo)
{
    __nv_bfloat162 h = __floats2bfloat162_rn(x, y);
    hi = *reinterpret_cast<uint32_t*>(&h);
    float hx = __bfloat162float(h.x);
    float hy = __bfloat162float(h.y);
    __nv_bfloat162 l = __floats2bfloat162_rn(x - hx, y - hy);
    lo = *reinterpret_cast<uint32_t*>(&l);
}

// fp32 pair -> fp16x2 hi + fp16x2 lo (residual)
__device__ __forceinline__ void splitH(float x, float y, uint32_t& hi, uint32_t& lo)
{
    __half2 h = __floats2half2_rn(x, y);
    hi = *reinterpret_cast<uint32_t*>(&h);
    float hx = __low2float(h), hy = __high2float(h);
    __half2 l = __floats2half2_rn(x - hx, y - hy);
    lo = *reinterpret_cast<uint32_t*>(&l);
}

__device__ __forceinline__ uint32_t ex2_f16x2(uint32_t x) {
    uint32_t r;
    asm("ex2.approx.f16x2 %0, %1;" : "=r"(r) : "r"(x));
    return r;
}

__device__ __forceinline__ void cpasync16(uint32_t dst, const void* src) {
    asm volatile("cp.async.cg.shared.global [%0], [%1], 16;"
                 :: "r"(dst), "l"(src));
}
#define CP_COMMIT() asm volatile("cp.async.commit_group;" ::: "memory")
#define CP_WAIT1()  asm volatile("cp.async.wait_group 1;" ::: "memory")
#define CP_WAIT0()  asm volatile("cp.async.wait_group 0;" ::: "memory")

// ---------------------------------------------------------------------------
// Prep kernels
// ---------------------------------------------------------------------------
__global__ void split_x(const float* __restrict__ x,
                        uint32_t* __restrict__ xh, uint32_t* __restrict__ xl)
{
    int idx = blockIdx.x * 256 + threadIdx.x;
    int r = idx / 192, j2 = idx % 192;
    float4 v = *(const float4*)(x + (size_t)r * 768 + 4 * j2);
    uint32_t h0, l0, h1, l1;
    split2(v.x, v.y, h0, l0);
    split2(v.z, v.w, h1, l1);
    size_t o = (size_t)r * 384 + 2 * j2;
    *(uint2*)(xh + o) = make_uint2(h0, h1);
    *(uint2*)(xl + o) = make_uint2(l0, l1);
}

__global__ void transpose_split(const float* __restrict__ in,
                                uint32_t* __restrict__ out_hi,
                                uint32_t* __restrict__ out_lo,
                                int K, int N)
{
    __shared__ float t[32][33];
    int n0 = blockIdx.x << 5, k0 = blockIdx.y << 5;
    int x = threadIdx.x, y = threadIdx.y;
    #pragma unroll
    for (int i = 0; i < 32; i += 8)
        t[y + i][x] = in[(size_t)(k0 + y + i) * N + n0 + x];
    __syncthreads();
    const int xp = x & 15, plane = x >> 4;
    #pragma unroll
    for (int i = 0; i < 32; i += 8) {
        int n = n0 + y + i;
        uint32_t h, l;
        split2(t[2 * xp][y + i], t[2 * xp + 1][y + i], h, l);
        size_t o = (size_t)n * (K / 2) + k0 / 2 + xp;
        if (plane == 0) out_hi[o] = h;
        else            out_lo[o] = l;
    }
}

// V bf16 dim-pair planes -> token-pair-major FP16 hi/lo planes
__global__ void pack_vt(const uint32_t* __restrict__ vh,
                        const uint32_t* __restrict__ vl,
                        uint32_t* __restrict__ vth, uint32_t* __restrict__ vtl)
{
    int idx = blockIdx.x * 256 + threadIdx.x;
    int bp = idx / 384, j = idx % 384;
    size_t s0 = (size_t)(2 * bp) * 384 + j;
    size_t s1 = s0 + 384;
    __nv_bfloat162 ah = *reinterpret_cast<const __nv_bfloat162*>(&vh[s0]);
    __nv_bfloat162 al = *reinterpret_cast<const __nv_bfloat162*>(&vl[s0]);
    __nv_bfloat162 bh = *reinterpret_cast<const __nv_bfloat162*>(&vh[s1]);
    __nv_bfloat162 bl = *reinterpret_cast<const __nv_bfloat162*>(&vl[s1]);
    // reconstruct fp32 values: token 2bp (a), token 2bp+1 (b), dims 2j / 2j+1
    float a0 = __bfloat162float(ah.x) + __bfloat162float(al.x);
    float a1 = __bfloat162float(ah.y) + __bfloat162float(al.y);
    float b0 = __bfloat162float(bh.x) + __bfloat162float(bl.x);
    float b1 = __bfloat162float(bh.y) + __bfloat162float(bl.y);
    uint32_t H0, L0, H1, L1;
    splitH(a0, b0, H0, L0);   // dim 2j : (token even low, token odd high)
    splitH(a1, b1, H1, L1);   // dim 2j+1
    size_t o = (size_t)bp * 768 + 2 * j;
    vth[o]     = H0;
    vth[o + 1] = H1;
    vtl[o]     = L0;
    vtl[o + 1] = L1;
}

// ---------------------------------------------------------------------------
// Plane GEMM (ldmatrix fragment loads, occupancy-2)
// ---------------------------------------------------------------------------
__device__ __forceinline__ void gemm_issue(
    uint32_t st_u32,
    const uint32_t* Ah, const uint32_t* Al,
    const uint32_t* Bh, const uint32_t* Bl,
    int row0, int col0, int K2, int kp0, int tid)
{
    #pragma unroll
    for (int p = 0; p < 4; p++) {
        int idx = p * 256 + tid;
        const uint32_t* src = (idx < 512) ? Ah : Al;
        int rem = idx & 511;
        int r = rem >> 2, c = rem & 3;
        uint32_t dst = st_u32 + (((idx < 512) ? 0 : 2560) + r * 20 + c * 4) * 4;
        cpasync16(dst, src + (size_t)(row0 + r) * K2 + kp0 + c * 4);
    }
    #pragma unroll
    for (int p = 0; p < 4; p++) {
        int idx = p * 256 + tid;
        const uint32_t* src = (idx < 512) ? Bh : Bl;
        int rem = idx & 511;
        int r = rem >> 2, c = rem & 3;
        uint32_t dst = st_u32 + ((5120 + ((idx < 512) ? 0 : 2560)) + r * 20 + c * 4) * 4;
        cpasync16(dst, src + (size_t)(col0 + r) * K2 + kp0 + c * 4);
    }
}

template <int MODE>
__global__ __launch_bounds__(256, 2) void gemm_planes(
    const uint32_t* __restrict__ Ah, const uint32_t* __restrict__ Al,
    const uint32_t* __restrict__ Bh, const uint32_t* __restrict__ Bl,
    const float* __restrict__ bias,
    float* __restrict__ outf,
    uint32_t* __restrict__ qkvp,
    int M, int N, int K)
{
    extern __shared__ uint32_t sm[];     // 2 stages x 10240 u32
    const uint32_t sm_u = smem_u32(sm);

    const int tid  = threadIdx.x;
    const int wid  = tid >> 5, lane = tid & 31;
    const int gid  = lane >> 2, tig = lane & 3;
    const int wm   = wid & 3;
    const int wn   = wid >> 2;
    const int row0 = blockIdx.y * 128;
    const int col0 = blockIdx.x * 128;
    const int K2   = K >> 1;
    const int NK   = K >> 5;

    const int lane7 = lane & 7;
    const int aRow  = wm * 32 + lane7 + ((lane >> 3) & 1) * 8;
    const int aColB = ((lane >> 4) & 1) * 16;
    const uint32_t aOff = (uint32_t)(aRow * 80) + aColB;
    const int bRow  = wn * 64 + lane7 + ((lane >> 4) & 1) * 8;
    const int bColB = ((lane >> 3) & 1) * 16;
    const uint32_t bOff = 5120 * 4 + (uint32_t)(bRow * 80) + bColB;

    float cf[2][8][4];
    #pragma unroll
    for (int ma = 0; ma < 2; ma++)
        #pragma unroll
        for (int na = 0; na < 8; na++)
            #pragma unroll
            for (int r = 0; r < 4; r++) cf[ma][na][r] = 0.f;

    gemm_issue(sm_u, Ah, Al, Bh, Bl, row0, col0, K2, 0, tid);
    CP_COMMIT();

    for (int kt = 0; kt < NK; kt++) {
        const int s = kt & 1;
        if (kt + 1 < NK) {
            gemm_issue(sm_u + (s ^ 1) * 40960, Ah, Al, Bh, Bl,
                       row0, col0, K2, (kt + 1) << 4, tid);
            CP_COMMIT();
            CP_WAIT1();
        } else {
            CP_WAIT0();
        }
        __syncthreads();

        const uint32_t stage = sm_u + s * 40960;

        #pragma unroll
        for (int ss = 0; ss < 2; ss++) {
            const uint32_t ssb = ss * 32;
            uint32_t ah[2][4], al[2][4];
            #pragma unroll
            for (int ma = 0; ma < 2; ma++) {
                ldm_x4(ah[ma][0], ah[ma][1], ah[ma][2], ah[ma][3],
                       stage + aOff + ma * 1280 + ssb);
                ldm_x4(al[ma][0], al[ma][1], al[ma][2], al[ma][3],
                       stage + 2560 * 4 + aOff + ma * 1280 + ssb);
            }
            #pragma unroll
            for (int j = 0; j < 4; j++) {
                uint32_t bh0, bh1, bh2, bh3, bl0, bl1, bl2, bl3;
                ldm_x4(bh0, bh1, bh2, bh3, stage + bOff + j * 1280 + ssb);
                ldm_x4(bl0, bl1, bl2, bl3, stage + 2560 * 4 + bOff + j * 1280 + ssb);
                #pragma unroll
                for (int ma = 0; ma < 2; ma++) {
                    mma_bf16(cf[ma][2 * j], ah[ma][0], ah[ma][1], ah[ma][2], ah[ma][3], bh0, bh1);
                    mma_bf16(cf[ma][2 * j], ah[ma][0], ah[ma][1], ah[ma][2], ah[ma][3], bl0, bl1);
                    mma_bf16(cf[ma][2 * j], al[ma][0], al[ma][1], al[ma][2], al[ma][3], bh0, bh1);
                    mma_bf16(cf[ma][2 * j + 1], ah[ma][0], ah[ma][1], ah[ma][2], ah[ma][3], bh2, bh3);
                    mma_bf16(cf[ma][2 * j + 1], ah[ma][0], ah[ma][1], ah[ma][2], ah[ma][3], bl2, bl3);
                    mma_bf16(cf[ma][2 * j + 1], al[ma][0], al[ma][1], al[ma][2], al[ma][3], bh2, bh3);
                }
            }
        }
        __syncthreads();
    }

    if (MODE == 1) {
        #pragma unroll
        for (int ma = 0; ma < 2; ma++) {
            const int rg = row0 + wm * 32 + ma * 16 + gid;
            #pragma unroll
            for (int na = 0; na < 8; na++) {
                const int cg = col0 + wn * 64 + na * 8 + tig * 2;
                const float bx0 = bias[cg], bx1 = bias[cg + 1];
                *(float2*)(outf + (size_t)rg * N + cg) =
                    make_float2(cf[ma][na][0] + bx0, cf[ma][na][1] + bx1);
                *(float2*)(outf + (size_t)(rg + 8) * N + cg) =
                    make_float2(cf[ma][na][2] + bx0, cf[ma][na][3] + bx1);
            }
        }
    } else {
        const int which = col0 / 768;
        // Q columns are pre-scaled by 0.125*log2(e): flash computes logits in
        // log2 domain with zero extra per-element work.
        const float qs = (which == 0) ? QSCALE : 1.0f;
        uint32_t* dh = qkvp + (size_t)(which * 2 + 0) * PSZ;
        uint32_t* dl = qkvp + (size_t)(which * 2 + 1) * PSZ;
        const int lc0 = col0 - which * 768;
        #pragma unroll
        for (int ma = 0; ma < 2; ma++) {
            const int rg = row0 + wm * 32 + ma * 16 + gid;
            #pragma unroll
            for (int na = 0; na < 8; na++) {
                const int gc = col0 + wn * 64 + na * 8 + tig * 2;
                const int pr = (lc0 >> 1) + wn * 32 + na * 4 + tig;
                const float bx0 = bias[gc], bx1 = bias[gc + 1];
                uint32_t h, l;
                split2((cf[ma][na][0] + bx0) * qs, (cf[ma][na][1] + bx1) * qs, h, l);
                dh[(size_t)rg * 384 + pr] = h;
                dl[(size_t)rg * 384 + pr] = l;
                split2((cf[ma][na][2] + bx0) * qs, (cf[ma][na][3] + bx1) * qs, h, l);
                dh[(size_t)(rg + 8) * 384 + pr] = h;
                dl[(size_t)(rg + 8) * 384 + pr] = l;
            }
        }
    }
}

// ---------------------------------------------------------------------------
// Flash attention: log2-domain softmax, fp16 ex2 P, 2-product fp16 PV
// ---------------------------------------------------------------------------
__device__ __forceinline__ void flash_issue(
    uint32_t st_u32,
    const uint32_t* kh, const uint32_t* kl,
    const uint32_t* vth, const uint32_t* vtl,
    int tok0, int vrow0, int h, int tid)
{
    #pragma unroll
    for (int p = 0; p < 4; p++) {
        int idx = p * 256 + tid;
        const uint32_t* src = (idx < 512) ? kh : kl;
        int rem = idx & 511;
        int r = rem >> 3, c = rem & 7;
        uint32_t dst = st_u32 + (((idx < 512) ? 0 : 2304) + r * 36 + c * 4) * 4;
        cpasync16(dst, src + (size_t)(tok0 + r) * 384 + h * 32 + c * 4);
    }
    #pragma unroll
    for (int p = 0; p < 4; p++) {
        int idx = p * 256 + tid;
        const uint32_t* src = (idx < 512) ? vth : vtl;
        int rem = idx & 511;
        int r = rem >> 4, c = rem & 15;
        uint32_t dst = st_u32 + ((4608 + ((idx < 512) ? 0 : 2304)) + r * 72 + c * 4) * 4;
        cpasync16(dst, src + (size_t)(vrow0 + r) * 768 + h * 64 + c * 4);
    }
}

__global__ __launch_bounds__(256, 2) void flash_planes(
    const uint32_t* __restrict__ qkvp, const uint32_t* __restrict__ vt,
    uint32_t* __restrict__ yh, uint32_t* __restrict__ yl)
{
    extern __shared__ uint32_t sm[];       // 2 stages x 9216 u32
    const uint32_t sm_u = smem_u32(sm);

    const int tid = threadIdx.x;
    const int wid = tid >> 5, lane = tid & 31;
    const int gid = lane >> 2, tig = lane & 3;
    const int bx = (gridDim.x - 1) - blockIdx.x;   // heavy CTAs launch first
    const int b  = blockIdx.y / HH;
    const int h  = blockIdx.y % HH;
    const int q0 = bx * 128;

    const uint32_t* qph = qkvp;
    const uint32_t* qpl = qkvp + (size_t)PSZ;
    const uint32_t* kph = qkvp + (size_t)2 * PSZ;
    const uint32_t* kpl = qkvp + (size_t)3 * PSZ;
    const uint32_t* vth = vt;
    const uint32_t* vtl = vt + (size_t)2048 * 768;

    const int lane7 = lane & 7;
    const int kRow  = lane7 + ((lane >> 4) & 1) * 8;
    const int kColB = ((lane >> 3) & 1) * 16;
    const uint32_t kOff = (uint32_t)(kRow * 144) + kColB;

    const int grow0 = b * 2048 + q0 + wid * 16 + gid;
    uint32_t qh[4][4], ql[4][4];
    #pragma unroll
    for (int ks = 0; ks < 4; ks++) {
        const int pr = h * 32 + 8 * ks + tig;
        qh[ks][0] = qph[(size_t)grow0 * 384 + pr];
        qh[ks][1] = qph[(size_t)(grow0 + 8) * 384 + pr];
        qh[ks][2] = qph[(size_t)grow0 * 384 + pr + 4];
        qh[ks][3] = qph[(size_t)(grow0 + 8) * 384 + pr + 4];
        ql[ks][0] = qpl[(size_t)grow0 * 384 + pr];
        ql[ks][1] = qpl[(size_t)(grow0 + 8) * 384 + pr];
        ql[ks][2] = qpl[(size_t)grow0 * 384 + pr + 4];
        ql[ks][3] = qpl[(size_t)(grow0 + 8) * 384 + pr + 4];
    }

    float of[8][4];
    #pragma unroll
    for (int na = 0; na < 8; na++)
        #pragma unroll
        for (int r = 0; r < 4; r++) of[na][r] = 0.f;
    float m0 = -1e30f, m1 = -1e30f, l0 = 0.f, l1 = 0.f;
    const int r0g = q0 + wid * 16 + gid;
    const int r1g = r0g + 8;

    const int nkt = 2 * bx + 2;
    flash_issue(sm_u, kph, kpl, vth, vtl, b * 2048, b * 1024, h, tid);
    CP_COMMIT();

    for (int kt = 0; kt < nkt; kt++) {
        const int s = kt & 1;
        if (kt + 1 < nkt) {
            flash_issue(sm_u + (s ^ 1) * 9216 * 4, kph, kpl, vth, vtl,
                        b * 2048 + (kt + 1) * 64, b * 1024 + (kt + 1) * 32, h, tid);
            CP_COMMIT();
            CP_WAIT1();
        } else {
            CP_WAIT0();
        }
        __syncthreads();

        if (kt * 64 <= q0 + wid * 16 + 15) {
            const uint32_t stage = sm_u + s * 9216 * 4;
            const uint32_t* v_hi = sm + s * 9216 + 4608;
            const uint32_t* v_lo = v_hi + 2304;

            // ---- S(log2 domain) = Qscaled @ K^T ----
            float sf[8][4];
            #pragma unroll
            for (int na = 0; na < 8; na++)
                #pragma unroll
                for (int r = 0; r < 4; r++) sf[na][r] = 0.f;

            #pragma unroll
            for (int ks = 0; ks < 4; ks++) {
                const uint32_t ksb = ks * 32;
                #pragma unroll
                for (int j = 0; j < 4; j++) {
                    uint32_t bh0, bh1, bh2, bh3, bl0, bl1, bl2, bl3;
                    ldm_x4(bh0, bh1, bh2, bh3, stage + kOff + j * 2304 + ksb);
                    ldm_x4(bl0, bl1, bl2, bl3, stage + 2304 * 4 + kOff + j * 2304 + ksb);
                    mma_bf16(sf[2 * j], qh[ks][0], qh[ks][1], qh[ks][2], qh[ks][3], bh0, bh1);
                    mma_bf16(sf[2 * j], qh[ks][0], qh[ks][1], qh[ks][2], qh[ks][3], bl0, bl1);
                    mma_bf16(sf[2 * j], ql[ks][0], ql[ks][1], ql[ks][2], ql[ks][3], bh0, bh1);
                    mma_bf16(sf[2 * j + 1], qh[ks][0], qh[ks][1], qh[ks][2], qh[ks][3], bh2, bh3);
                    mma_bf16(sf[2 * j + 1], qh[ks][0], qh[ks][1], qh[ks][2], qh[ks][3], bl2, bl3);
                    mma_bf16(sf[2 * j + 1], ql[ks][0], ql[ks][1], ql[ks][2], ql[ks][3], bh2, bh3);
                }
            }

            // ---- causal mask (already log2-scaled) ----
            const bool need_mask = (kt >= 2 * bx);
            if (need_mask) {
                #pragma unroll
                for (int na = 0; na < 8; na++) {
                    const int cg = kt * 64 + na * 8 + tig * 2;
                    if (cg     > r0g) sf[na][0] = -1e30f;
                    if (cg + 1 > r0g) sf[na][1] = -1e30f;
                    if (cg     > r1g) sf[na][2] = -1e30f;
                    if (cg + 1 > r1g) sf[na][3] = -1e30f;
                }
            }

            // ---- online softmax (log2 domain, fp16 exp2) ----
            float rm0 = -1e30f, rm1 = -1e30f;
            #pragma unroll
            for (int na = 0; na < 8; na++) {
                rm0 = fmaxf(rm0, fmaxf(sf[na][0], sf[na][1]));
                rm1 = fmaxf(rm1, fmaxf(sf[na][2], sf[na][3]));
            }
            rm0 = fmaxf(rm0, __shfl_xor_sync(0xffffffffu, rm0, 1));
            rm0 = fmaxf(rm0, __shfl_xor_sync(0xffffffffu, rm0, 2));
            rm1 = fmaxf(rm1, __shfl_xor_sync(0xffffffffu, rm1, 1));
            rm1 = fmaxf(rm1, __shfl_xor_sync(0xffffffffu, rm1, 2));
            const float mn0 = fmaxf(m0, rm0), mn1 = fmaxf(m1, rm1);
            const float c0 = exp2f(m0 - mn0), c1 = exp2f(m1 - mn1);
            float rs0 = 0.f, rs1 = 0.f;
            uint32_t p01[8], p23[8];
            #pragma unroll
            for (int na = 0; na < 8; na++) {
                __half2 h01 = __floats2half2_rn(sf[na][0] - mn0, sf[na][1] - mn0);
                __half2 h23 = __floats2half2_rn(sf[na][2] - mn1, sf[na][3] - mn1);
                p01[na] = ex2_f16x2(*reinterpret_cast<uint32_t*>(&h01));
                p23[na] = ex2_f16x2(*reinterpret_cast<uint32_t*>(&h23));
                float2 f01 = __half22float2(*reinterpret_cast<__half2*>(&p01[na]));
                float2 f23 = __half22float2(*reinterpret_cast<__half2*>(&p23[na]));
                rs0 += f01.x + f01.y;
                rs1 += f23.x + f23.y;
            }
            rs0 += __shfl_xor_sync(0xffffffffu, rs0, 1);
            rs0 += __shfl_xor_sync(0xffffffffu, rs0, 2);
            rs1 += __shfl_xor_sync(0xffffffffu, rs1, 1);
            rs1 += __shfl_xor_sync(0xffffffffu, rs1, 2);
            l0 = l0 * c0 + rs0; m0 = mn0;
            l1 = l1 * c1 + rs1; m1 = mn1;
            #pragma unroll
            for (int na = 0; na < 8; na++) {
                of[na][0] *= c0; of[na][1] *= c0;
                of[na][2] *= c1; of[na][3] *= c1;
            }

            // ---- O += P @ V (fp16 P, fp16 hi/lo V: 2 products) ----
            #pragma unroll
            for (int ks = 0; ks < 4; ks++) {
                const uint32_t pa0 = p01[2 * ks],     pa1 = p23[2 * ks];
                const uint32_t pa2 = p01[2 * ks + 1], pa3 = p23[2 * ks + 1];
                #pragma unroll
                for (int na = 0; na < 8; na++) {
                    const int d = na * 8 + gid;
                    const int o0 = (8 * ks + tig) * 72 + d;
                    const int o1 = (8 * ks + tig + 4) * 72 + d;
                    mma_f16(of[na], pa0, pa1, pa2, pa3, v_hi[o0], v_hi[o1]);
                    mma_f16(of[na], pa0, pa1, pa2, pa3, v_lo[o0], v_lo[o1]);
                }
            }
        }
        __syncthreads();
    }

    // ---- epilogue: y planes ----
    const float i0 = 1.f / l0, i1 = 1.f / l1;
    const int gr0 = b * 2048 + r0g;
    #pragma unroll
    for (int na = 0; na < 8; na++) {
        const int pr = h * 32 + na * 4 + tig;
        uint32_t h0, lo0;
        split2(of[na][0] * i0, of[na][1] * i0, h0, lo0);
        yh[(size_t)gr0 * 384 + pr] = h0;
        yl[(size_t)gr0 * 384 + pr] = lo0;
        split2(of[na][2] * i1, of[na][3] * i1, h0, lo0);
        yh[(size_t)(gr0 + 8) * 384 + pr] = h0;
        yl[(size_t)(gr0 + 8) * 384 + pr] = lo0;
    }
}

extern "C" void kernel_launch(void* const* d_in, const int* in_sizes, int n_in,
                              void* d_out, int out_size)
{
    const float* x      = (const float*)d_in[0];
    const float* W_attn = (const float*)d_in[1];
    const float* b_attn = (const float*)d_in[2];
    const float* W_proj = (const float*)d_in[3];
    const float* b_proj = (const float*)d_in[4];
    float* out = (float*)d_out;

    uint32_t *qkvp, *vt, *xp, *yp, *wt, *wt2;
    cudaGetSymbolAddress((void**)&qkvp, g_qkvp);
    cudaGetSymbolAddress((void**)&vt, g_vt);
    cudaGetSymbolAddress((void**)&xp, g_xp);
    cudaGetSymbolAddress((void**)&yp, g_yp);
    cudaGetSymbolAddress((void**)&wt, g_wt);
    cudaGetSymbolAddress((void**)&wt2, g_wt2);

    const int GEMM_SMEM  = 2 * 10240 * 4;   // 81920
    const int FLASH_SMEM = 2 * 9216 * 4;    // 73728
    cudaFuncSetAttribute(gemm_planes<0>,
                         cudaFuncAttributeMaxDynamicSharedMemorySize, GEMM_SMEM);
    cudaFuncSetAttribute(gemm_planes<1>,
                         cudaFuncAttributeMaxDynamicSharedMemorySize, GEMM_SMEM);
    cudaFuncSetAttribute(flash_planes,
                         cudaFuncAttributeMaxDynamicSharedMemorySize, FLASH_SMEM);

    split_x<<<786432 / 256, 256>>>(x, xp, xp + PSZ);                       // 0
    transpose_split<<<dim3(C3 / 32, CC / 32), dim3(32, 8)>>>(              // 1
        W_attn, wt, wt + (size_t)C3 * CC / 2, CC, C3);
    transpose_split<<<dim3(CC / 32, CC / 32), dim3(32, 8)>>>(              // 2
        W_proj, wt2, wt2 + (size_t)CC * CC / 2, CC, CC);

    gemm_planes<0><<<dim3(C3 / 128, MTOT / 128), 256, GEMM_SMEM>>>(        // 3
        xp, xp + PSZ, wt, wt + (size_t)C3 * CC / 2, b_attn,
        nullptr, qkvp, MTOT, C3, CC);

    pack_vt<<<(2048 * 384) / 256, 256>>>(                                  // 4
        qkvp + (size_t)4 * PSZ, qkvp + (size_t)5 * PSZ, vt, vt + (size_t)2048 * 768);

    flash_planes<<<dim3(TT / 128, BB * HH), 256, FLASH_SMEM>>>(            // 5
        qkvp, vt, yp, yp + PSZ);

    gemm_planes<1><<<dim3(CC / 128, MTOT / 128), 256, GEMM_SMEM>>>(        // 6
        yp, yp + PSZ, wt2, wt2 + (size_t)CC * CC / 2, b_proj,
        out, nullptr, MTOT, CC, CC);
}

// round 11
// speedup vs baseline: 3.1236x; 1.1209x over previous
#include <cuda_runtime.h>
#include <cuda_bf16.h>
#include <cuda_fp16.h>
#include <math.h>
#include <cstdint>

#define BB 2
#define TT 2048
#define CC 768
#define HH 12
#define HS 64
#define C3 2304
#define MTOT (BB*TT)          // 4096
#define PSZ (4096*384)        // u32 per plane for [M][K/2] with K=768
#define QSCALE 0.18033688011112042f   // 0.125 * log2(e)

// Scratch (allocation-free contract)
__device__ uint32_t g_qkvp[6 * (size_t)PSZ];        // q_hi,q_lo,k_hi,k_lo,v_hi,v_lo (bf16 planes)
__device__ uint32_t g_vt[2 * (size_t)2048 * 768];   // V token-pair-major FP16 hi/lo planes
__device__ uint32_t g_xp[2 * (size_t)PSZ];          // x planes
__device__ uint32_t g_yp[2 * (size_t)PSZ];          // y planes
__device__ uint32_t g_wt[(size_t)CC * C3];          // W_attn^T planes (hi then lo)
__device__ uint32_t g_wt2[2 * (size_t)CC * CC / 2]; // W_proj^T planes (hi then lo)
// split-KV partials: [2 splits][24 bh][8 heavy blocks][128 rows][64 dims]
__device__ float g_po[(size_t)2 * 24 * 8 * 128 * 64];   // 12.6 MB
__device__ float g_ml[(size_t)2 * 24 * 8 * 128 * 2];

// ---------------------------------------------------------------------------
// Helpers
// ---------------------------------------------------------------------------
__device__ __forceinline__ uint32_t smem_u32(const void* p) {
    uint32_t a;
    asm("{ .reg .u64 t; cvta.to.shared.u64 t, %1; cvt.u32.u64 %0, t; }"
        : "=r"(a) : "l"(p));
    return a;
}

__device__ __forceinline__ void mma_bf16(float c[4],
    uint32_t a0, uint32_t a1, uint32_t a2, uint32_t a3,
    uint32_t b0, uint32_t b1)
{
    asm("mma.sync.aligned.m16n8k16.row.col.f32.bf16.bf16.f32 "
        "{%0,%1,%2,%3}, {%4,%5,%6,%7}, {%8,%9}, {%0,%1,%2,%3};"
        : "+f"(c[0]), "+f"(c[1]), "+f"(c[2]), "+f"(c[3])
        : "r"(a0), "r"(a1), "r"(a2), "r"(a3), "r"(b0), "r"(b1));
}

__device__ __forceinline__ void mma_f16(float c[4],
    uint32_t a0, uint32_t a1, uint32_t a2, uint32_t a3,
    uint32_t b0, uint32_t b1)
{
    asm("mma.sync.aligned.m16n8k16.row.col.f32.f16.f16.f32 "
        "{%0,%1,%2,%3}, {%4,%5,%6,%7}, {%8,%9}, {%0,%1,%2,%3};"
        : "+f"(c[0]), "+f"(c[1]), "+f"(c[2]), "+f"(c[3])
        : "r"(a0), "r"(a1), "r"(a2), "r"(a3), "r"(b0), "r"(b1));
}

__device__ __forceinline__ void ldm_x4(uint32_t& r0, uint32_t& r1,
                                       uint32_t& r2, uint32_t& r3, uint32_t addr)
{
    asm volatile("ldmatrix.sync.aligned.m8n8.x4.shared.b16 {%0,%1,%2,%3}, [%4];"
        : "=r"(r0), "=r"(r1), "=r"(r2), "=r"(r3) : "r"(addr));
}

// fp32 pair -> bf16x2 hi + bf16x2 lo (residual)
__device__ __forceinline__ void split2(float x, float y, uint32_t& hi, uint32_t& lo)
{
    __nv_bfloat162 h = __floats2bfloat162_rn(x, y);
    hi = *reinterpret_cast<uint32_t*>(&h);
    float hx = __bfloat162float(h.x);
    float hy = __bfloat162float(h.y);
    __nv_bfloat162 l = __floats2bfloat162_rn(x - hx, y - hy);
    lo = *reinterpret_cast<uint32_t*>(&l);
}

// fp32 pair -> fp16x2 hi + fp16x2 lo (residual)
__device__ __forceinline__ void splitH(float x, float y, uint32_t& hi, uint32_t& lo)
{
    __half2 h = __floats2half2_rn(x, y);
    hi = *reinterpret_cast<uint32_t*>(&h);
    float hx = __low2float(h), hy = __high2float(h);
    __half2 l = __floats2half2_rn(x - hx, y - hy);
    lo = *reinterpret_cast<uint32_t*>(&l);
}

__device__ __forceinline__ uint32_t ex2_f16x2(uint32_t x) {
    uint32_t r;
    asm("ex2.approx.f16x2 %0, %1;" : "=r"(r) : "r"(x));
    return r;
}

__device__ __forceinline__ void cpasync16(uint32_t dst, const void* src) {
    asm volatile("cp.async.cg.shared.global [%0], [%1], 16;"
                 :: "r"(dst), "l"(src));
}
#define CP_COMMIT() asm volatile("cp.async.commit_group;" ::: "memory")
#define CP_WAIT1()  asm volatile("cp.async.wait_group 1;" ::: "memory")
#define CP_WAIT0()  asm volatile("cp.async.wait_group 0;" ::: "memory")

// ---------------------------------------------------------------------------
// Prep kernels
// ---------------------------------------------------------------------------
__global__ void split_x(const float* __restrict__ x,
                        uint32_t* __restrict__ xh, uint32_t* __restrict__ xl)
{
    int idx = blockIdx.x * 256 + threadIdx.x;
    int r = idx / 192, j2 = idx % 192;
    float4 v = *(const float4*)(x + (size_t)r * 768 + 4 * j2);
    uint32_t h0, l0, h1, l1;
    split2(v.x, v.y, h0, l0);
    split2(v.z, v.w, h1, l1);
    size_t o = (size_t)r * 384 + 2 * j2;
    *(uint2*)(xh + o) = make_uint2(h0, h1);
    *(uint2*)(xl + o) = make_uint2(l0, l1);
}

__global__ void transpose_split(const float* __restrict__ in,
                                uint32_t* __restrict__ out_hi,
                                uint32_t* __restrict__ out_lo,
                                int K, int N)
{
    __shared__ float t[32][33];
    int n0 = blockIdx.x << 5, k0 = blockIdx.y << 5;
    int x = threadIdx.x, y = threadIdx.y;
    #pragma unroll
    for (int i = 0; i < 32; i += 8)
        t[y + i][x] = in[(size_t)(k0 + y + i) * N + n0 + x];
    __syncthreads();
    const int xp = x & 15, plane = x >> 4;
    #pragma unroll
    for (int i = 0; i < 32; i += 8) {
        int n = n0 + y + i;
        uint32_t h, l;
        split2(t[2 * xp][y + i], t[2 * xp + 1][y + i], h, l);
        size_t o = (size_t)n * (K / 2) + k0 / 2 + xp;
        if (plane == 0) out_hi[o] = h;
        else            out_lo[o] = l;
    }
}

// V bf16 dim-pair planes -> token-pair-major FP16 hi/lo planes
__global__ void pack_vt(const uint32_t* __restrict__ vh,
                        const uint32_t* __restrict__ vl,
                        uint32_t* __restrict__ vth, uint32_t* __restrict__ vtl)
{
    int idx = blockIdx.x * 256 + threadIdx.x;
    int bp = idx / 384, j = idx % 384;
    size_t s0 = (size_t)(2 * bp) * 384 + j;
    size_t s1 = s0 + 384;
    __nv_bfloat162 ah = *reinterpret_cast<const __nv_bfloat162*>(&vh[s0]);
    __nv_bfloat162 al = *reinterpret_cast<const __nv_bfloat162*>(&vl[s0]);
    __nv_bfloat162 bh = *reinterpret_cast<const __nv_bfloat162*>(&vh[s1]);
    __nv_bfloat162 bl = *reinterpret_cast<const __nv_bfloat162*>(&vl[s1]);
    float a0 = __bfloat162float(ah.x) + __bfloat162float(al.x);
    float a1 = __bfloat162float(ah.y) + __bfloat162float(al.y);
    float b0 = __bfloat162float(bh.x) + __bfloat162float(bl.x);
    float b1 = __bfloat162float(bh.y) + __bfloat162float(bl.y);
    uint32_t H0, L0, H1, L1;
    splitH(a0, b0, H0, L0);
    splitH(a1, b1, H1, L1);
    size_t o = (size_t)bp * 768 + 2 * j;
    vth[o]     = H0;
    vth[o + 1] = H1;
    vtl[o]     = L0;
    vtl[o + 1] = L1;
}

// ---------------------------------------------------------------------------
// Plane GEMM (ldmatrix fragment loads, occupancy-2)
// ---------------------------------------------------------------------------
__device__ __forceinline__ void gemm_issue(
    uint32_t st_u32,
    const uint32_t* Ah, const uint32_t* Al,
    const uint32_t* Bh, const uint32_t* Bl,
    int row0, int col0, int K2, int kp0, int tid)
{
    #pragma unroll
    for (int p = 0; p < 4; p++) {
        int idx = p * 256 + tid;
        const uint32_t* src = (idx < 512) ? Ah : Al;
        int rem = idx & 511;
        int r = rem >> 2, c = rem & 3;
        uint32_t dst = st_u32 + (((idx < 512) ? 0 : 2560) + r * 20 + c * 4) * 4;
        cpasync16(dst, src + (size_t)(row0 + r) * K2 + kp0 + c * 4);
    }
    #pragma unroll
    for (int p = 0; p < 4; p++) {
        int idx = p * 256 + tid;
        const uint32_t* src = (idx < 512) ? Bh : Bl;
        int rem = idx & 511;
        int r = rem >> 2, c = rem & 3;
        uint32_t dst = st_u32 + ((5120 + ((idx < 512) ? 0 : 2560)) + r * 20 + c * 4) * 4;
        cpasync16(dst, src + (size_t)(col0 + r) * K2 + kp0 + c * 4);
    }
}

template <int MODE>
__global__ __launch_bounds__(256, 2) void gemm_planes(
    const uint32_t* __restrict__ Ah, const uint32_t* __restrict__ Al,
    const uint32_t* __restrict__ Bh, const uint32_t* __restrict__ Bl,
    const float* __restrict__ bias,
    float* __restrict__ outf,
    uint32_t* __restrict__ qkvp,
    int M, int N, int K)
{
    extern __shared__ uint32_t sm[];     // 2 stages x 10240 u32
    const uint32_t sm_u = smem_u32(sm);

    const int tid  = threadIdx.x;
    const int wid  = tid >> 5, lane = tid & 31;
    const int gid  = lane >> 2, tig = lane & 3;
    const int wm   = wid & 3;
    const int wn   = wid >> 2;
    const int row0 = blockIdx.y * 128;
    const int col0 = blockIdx.x * 128;
    const int K2   = K >> 1;
    const int NK   = K >> 5;

    const int lane7 = lane & 7;
    const int aRow  = wm * 32 + lane7 + ((lane >> 3) & 1) * 8;
    const int aColB = ((lane >> 4) & 1) * 16;
    const uint32_t aOff = (uint32_t)(aRow * 80) + aColB;
    const int bRow  = wn * 64 + lane7 + ((lane >> 4) & 1) * 8;
    const int bColB = ((lane >> 3) & 1) * 16;
    const uint32_t bOff = 5120 * 4 + (uint32_t)(bRow * 80) + bColB;

    float cf[2][8][4];
    #pragma unroll
    for (int ma = 0; ma < 2; ma++)
        #pragma unroll
        for (int na = 0; na < 8; na++)
            #pragma unroll
            for (int r = 0; r < 4; r++) cf[ma][na][r] = 0.f;

    gemm_issue(sm_u, Ah, Al, Bh, Bl, row0, col0, K2, 0, tid);
    CP_COMMIT();

    for (int kt = 0; kt < NK; kt++) {
        const int s = kt & 1;
        if (kt + 1 < NK) {
            gemm_issue(sm_u + (s ^ 1) * 40960, Ah, Al, Bh, Bl,
                       row0, col0, K2, (kt + 1) << 4, tid);
            CP_COMMIT();
            CP_WAIT1();
        } else {
            CP_WAIT0();
        }
        __syncthreads();

        const uint32_t stage = sm_u + s * 40960;

        #pragma unroll
        for (int ss = 0; ss < 2; ss++) {
            const uint32_t ssb = ss * 32;
            uint32_t ah[2][4], al[2][4];
            #pragma unroll
            for (int ma = 0; ma < 2; ma++) {
                ldm_x4(ah[ma][0], ah[ma][1], ah[ma][2], ah[ma][3],
                       stage + aOff + ma * 1280 + ssb);
                ldm_x4(al[ma][0], al[ma][1], al[ma][2], al[ma][3],
                       stage + 2560 * 4 + aOff + ma * 1280 + ssb);
            }
            #pragma unroll
            for (int j = 0; j < 4; j++) {
                uint32_t bh0, bh1, bh2, bh3, bl0, bl1, bl2, bl3;
                ldm_x4(bh0, bh1, bh2, bh3, stage + bOff + j * 1280 + ssb);
                ldm_x4(bl0, bl1, bl2, bl3, stage + 2560 * 4 + bOff + j * 1280 + ssb);
                #pragma unroll
                for (int ma = 0; ma < 2; ma++) {
                    mma_bf16(cf[ma][2 * j], ah[ma][0], ah[ma][1], ah[ma][2], ah[ma][3], bh0, bh1);
                    mma_bf16(cf[ma][2 * j], ah[ma][0], ah[ma][1], ah[ma][2], ah[ma][3], bl0, bl1);
                    mma_bf16(cf[ma][2 * j], al[ma][0], al[ma][1], al[ma][2], al[ma][3], bh0, bh1);
                    mma_bf16(cf[ma][2 * j + 1], ah[ma][0], ah[ma][1], ah[ma][2], ah[ma][3], bh2, bh3);
                    mma_bf16(cf[ma][2 * j + 1], ah[ma][0], ah[ma][1], ah[ma][2], ah[ma][3], bl2, bl3);
                    mma_bf16(cf[ma][2 * j + 1], al[ma][0], al[ma][1], al[ma][2], al[ma][3], bh2, bh3);
                }
            }
        }
        __syncthreads();
    }

    if (MODE == 1) {
        #pragma unroll
        for (int ma = 0; ma < 2; ma++) {
            const int rg = row0 + wm * 32 + ma * 16 + gid;
            #pragma unroll
            for (int na = 0; na < 8; na++) {
                const int cg = col0 + wn * 64 + na * 8 + tig * 2;
                const float bx0 = bias[cg], bx1 = bias[cg + 1];
                *(float2*)(outf + (size_t)rg * N + cg) =
                    make_float2(cf[ma][na][0] + bx0, cf[ma][na][1] + bx1);
                *(float2*)(outf + (size_t)(rg + 8) * N + cg) =
                    make_float2(cf[ma][na][2] + bx0, cf[ma][na][3] + bx1);
            }
        }
    } else {
        const int which = col0 / 768;
        const float qs = (which == 0) ? QSCALE : 1.0f;
        uint32_t* dh = qkvp + (size_t)(which * 2 + 0) * PSZ;
        uint32_t* dl = qkvp + (size_t)(which * 2 + 1) * PSZ;
        const int lc0 = col0 - which * 768;
        #pragma unroll
        for (int ma = 0; ma < 2; ma++) {
            const int rg = row0 + wm * 32 + ma * 16 + gid;
            #pragma unroll
            for (int na = 0; na < 8; na++) {
                const int gc = col0 + wn * 64 + na * 8 + tig * 2;
                const int pr = (lc0 >> 1) + wn * 32 + na * 4 + tig;
                const float bx0 = bias[gc], bx1 = bias[gc + 1];
                uint32_t h, l;
                split2((cf[ma][na][0] + bx0) * qs, (cf[ma][na][1] + bx1) * qs, h, l);
                dh[(size_t)rg * 384 + pr] = h;
                dl[(size_t)rg * 384 + pr] = l;
                split2((cf[ma][na][2] + bx0) * qs, (cf[ma][na][3] + bx1) * qs, h, l);
                dh[(size_t)(rg + 8) * 384 + pr] = h;
                dl[(size_t)(rg + 8) * 384 + pr] = l;
            }
        }
    }
}

// ---------------------------------------------------------------------------
// Flash attention with split-KV load balancing.
// grid = (24 bh, 24 slots). Slot u < 16: heavy q-block bx = 8 + u/2,
// split = u&1 (each covers half the KV range, writes partial O/m/l).
// Slot u >= 16: light q-block bx = 23 - u (full range, writes y planes).
// All heavy halves occupy the lowest launch indices -> wave 1 is pure 16-unit
// CTAs; max CTA work 16 tiles < fleet average 22 -> balanced makespan.
// ---------------------------------------------------------------------------
__device__ __forceinline__ void flash_issue(
    uint32_t st_u32,
    const uint32_t* kh, const uint32_t* kl,
    const uint32_t* vth, const uint32_t* vtl,
    int tok0, int vrow0, int h, int tid)
{
    #pragma unroll
    for (int p = 0; p < 4; p++) {
        int idx = p * 256 + tid;
        const uint32_t* src = (idx < 512) ? kh : kl;
        int rem = idx & 511;
        int r = rem >> 3, c = rem & 7;
        uint32_t dst = st_u32 + (((idx < 512) ? 0 : 2304) + r * 36 + c * 4) * 4;
        cpasync16(dst, src + (size_t)(tok0 + r) * 384 + h * 32 + c * 4);
    }
    #pragma unroll
    for (int p = 0; p < 4; p++) {
        int idx = p * 256 + tid;
        const uint32_t* src = (idx < 512) ? vth : vtl;
        int rem = idx & 511;
        int r = rem >> 4, c = rem & 15;
        uint32_t dst = st_u32 + ((4608 + ((idx < 512) ? 0 : 2304)) + r * 72 + c * 4) * 4;
        cpasync16(dst, src + (size_t)(vrow0 + r) * 768 + h * 64 + c * 4);
    }
}

__global__ __launch_bounds__(256, 2) void flash_planes(
    const uint32_t* __restrict__ qkvp, const uint32_t* __restrict__ vt,
    uint32_t* __restrict__ yh, uint32_t* __restrict__ yl,
    float* __restrict__ po, float* __restrict__ ml)
{
    extern __shared__ uint32_t sm[];       // 2 stages x 9216 u32
    const uint32_t sm_u = smem_u32(sm);

    const int tid = threadIdx.x;
    const int wid = tid >> 5, lane = tid & 31;
    const int gid = lane >> 2, tig = lane & 3;
    const int bh = blockIdx.x;             // 0..23
    const int u  = blockIdx.y;             // 0..23 (heavy halves first)
    const int b  = bh / HH;
    const int h  = bh % HH;

    int bx, split, kt0, kt1;
    if (u < 16) {
        bx    = 8 + (u >> 1);
        split = u & 1;
        const int half = bx + 1;           // nkt/2 (nkt = 2bx+2, even)
        kt0 = split ? half : 0;
        kt1 = split ? (2 * bx + 2) : half;
    } else {
        bx = 23 - u;                       // 7 .. 0, descending work
        split = -1;
        kt0 = 0;
        kt1 = 2 * bx + 2;
    }
    const int q0 = bx * 128;

    const uint32_t* qph = qkvp;
    const uint32_t* qpl = qkvp + (size_t)PSZ;
    const uint32_t* kph = qkvp + (size_t)2 * PSZ;
    const uint32_t* kpl = qkvp + (size_t)3 * PSZ;
    const uint32_t* vth = vt;
    const uint32_t* vtl = vt + (size_t)2048 * 768;

    const int lane7 = lane & 7;
    const int kRow  = lane7 + ((lane >> 4) & 1) * 8;
    const int kColB = ((lane >> 3) & 1) * 16;
    const uint32_t kOff = (uint32_t)(kRow * 144) + kColB;

    const int grow0 = b * 2048 + q0 + wid * 16 + gid;
    uint32_t qh[4][4], ql[4][4];
    #pragma unroll
    for (int ks = 0; ks < 4; ks++) {
        const int pr = h * 32 + 8 * ks + tig;
        qh[ks][0] = qph[(size_t)grow0 * 384 + pr];
        qh[ks][1] = qph[(size_t)(grow0 + 8) * 384 + pr];
        qh[ks][2] = qph[(size_t)grow0 * 384 + pr + 4];
        qh[ks][3] = qph[(size_t)(grow0 + 8) * 384 + pr + 4];
        ql[ks][0] = qpl[(size_t)grow0 * 384 + pr];
        ql[ks][1] = qpl[(size_t)(grow0 + 8) * 384 + pr];
        ql[ks][2] = qpl[(size_t)grow0 * 384 + pr + 4];
        ql[ks][3] = qpl[(size_t)(grow0 + 8) * 384 + pr + 4];
    }

    float of[8][4];
    #pragma unroll
    for (int na = 0; na < 8; na++)
        #pragma unroll
        for (int r = 0; r < 4; r++) of[na][r] = 0.f;
    float m0 = -1e30f, m1 = -1e30f, l0 = 0.f, l1 = 0.f;
    const int r0g = q0 + wid * 16 + gid;
    const int r1g = r0g + 8;

    const int nloc = kt1 - kt0;
    flash_issue(sm_u, kph, kpl, vth, vtl,
                b * 2048 + kt0 * 64, b * 1024 + kt0 * 32, h, tid);
    CP_COMMIT();

    for (int ki = 0; ki < nloc; ki++) {
        const int kt = kt0 + ki;
        const int s = ki & 1;
        if (ki + 1 < nloc) {
            flash_issue(sm_u + (s ^ 1) * 9216 * 4, kph, kpl, vth, vtl,
                        b * 2048 + (kt + 1) * 64, b * 1024 + (kt + 1) * 32, h, tid);
            CP_COMMIT();
            CP_WAIT1();
        } else {
            CP_WAIT0();
        }
        __syncthreads();

        if (kt * 64 <= q0 + wid * 16 + 15) {
            const uint32_t stage = sm_u + s * 9216 * 4;
            const uint32_t* v_hi = sm + s * 9216 + 4608;
            const uint32_t* v_lo = v_hi + 2304;

            // ---- S(log2 domain) = Qscaled @ K^T ----
            float sf[8][4];
            #pragma unroll
            for (int na = 0; na < 8; na++)
                #pragma unroll
                for (int r = 0; r < 4; r++) sf[na][r] = 0.f;

            #pragma unroll
            for (int ks = 0; ks < 4; ks++) {
                const uint32_t ksb = ks * 32;
                #pragma unroll
                for (int j = 0; j < 4; j++) {
                    uint32_t bh0, bh1, bh2, bh3, bl0, bl1, bl2, bl3;
                    ldm_x4(bh0, bh1, bh2, bh3, stage + kOff + j * 2304 + ksb);
                    ldm_x4(bl0, bl1, bl2, bl3, stage + 2304 * 4 + kOff + j * 2304 + ksb);
                    mma_bf16(sf[2 * j], qh[ks][0], qh[ks][1], qh[ks][2], qh[ks][3], bh0, bh1);
                    mma_bf16(sf[2 * j], qh[ks][0], qh[ks][1], qh[ks][2], qh[ks][3], bl0, bl1);
                    mma_bf16(sf[2 * j], ql[ks][0], ql[ks][1], ql[ks][2], ql[ks][3], bh0, bh1);
                    mma_bf16(sf[2 * j + 1], qh[ks][0], qh[ks][1], qh[ks][2], qh[ks][3], bh2, bh3);
                    mma_bf16(sf[2 * j + 1], qh[ks][0], qh[ks][1], qh[ks][2], qh[ks][3], bl2, bl3);
                    mma_bf16(sf[2 * j + 1], ql[ks][0], ql[ks][1], ql[ks][2], ql[ks][3], bh2, bh3);
                }
            }

            // ---- causal mask (log2-scaled logits) ----
            const bool need_mask = (kt >= 2 * bx);
            if (need_mask) {
                #pragma unroll
                for (int na = 0; na < 8; na++) {
                    const int cg = kt * 64 + na * 8 + tig * 2;
                    if (cg     > r0g) sf[na][0] = -1e30f;
                    if (cg + 1 > r0g) sf[na][1] = -1e30f;
                    if (cg     > r1g) sf[na][2] = -1e30f;
                    if (cg + 1 > r1g) sf[na][3] = -1e30f;
                }
            }

            // ---- online softmax (log2 domain, fp16 exp2) ----
            float rm0 = -1e30f, rm1 = -1e30f;
            #pragma unroll
            for (int na = 0; na < 8; na++) {
                rm0 = fmaxf(rm0, fmaxf(sf[na][0], sf[na][1]));
                rm1 = fmaxf(rm1, fmaxf(sf[na][2], sf[na][3]));
            }
            rm0 = fmaxf(rm0, __shfl_xor_sync(0xffffffffu, rm0, 1));
            rm0 = fmaxf(rm0, __shfl_xor_sync(0xffffffffu, rm0, 2));
            rm1 = fmaxf(rm1, __shfl_xor_sync(0xffffffffu, rm1, 1));
            rm1 = fmaxf(rm1, __shfl_xor_sync(0xffffffffu, rm1, 2));
            const float mn0 = fmaxf(m0, rm0), mn1 = fmaxf(m1, rm1);
            const float c0 = exp2f(m0 - mn0), c1 = exp2f(m1 - mn1);
            float rs0 = 0.f, rs1 = 0.f;
            uint32_t p01[8], p23[8];
            #pragma unroll
            for (int na = 0; na < 8; na++) {
                __half2 h01 = __floats2half2_rn(sf[na][0] - mn0, sf[na][1] - mn0);
                __half2 h23 = __floats2half2_rn(sf[na][2] - mn1, sf[na][3] - mn1);
                p01[na] = ex2_f16x2(*reinterpret_cast<uint32_t*>(&h01));
                p23[na] = ex2_f16x2(*reinterpret_cast<uint32_t*>(&h23));
                float2 f01 = __half22float2(*reinterpret_cast<__half2*>(&p01[na]));
                float2 f23 = __half22float2(*reinterpret_cast<__half2*>(&p23[na]));
                rs0 += f01.x + f01.y;
                rs1 += f23.x + f23.y;
            }
            rs0 += __shfl_xor_sync(0xffffffffu, rs0, 1);
            rs0 += __shfl_xor_sync(0xffffffffu, rs0, 2);
            rs1 += __shfl_xor_sync(0xffffffffu, rs1, 1);
            rs1 += __shfl_xor_sync(0xffffffffu, rs1, 2);
            l0 = l0 * c0 + rs0; m0 = mn0;
            l1 = l1 * c1 + rs1; m1 = mn1;
            #pragma unroll
            for (int na = 0; na < 8; na++) {
                of[na][0] *= c0; of[na][1] *= c0;
                of[na][2] *= c1; of[na][3] *= c1;
            }

            // ---- O += P @ V (fp16 P, fp16 hi/lo V: 2 products) ----
            #pragma unroll
            for (int ks = 0; ks < 4; ks++) {
                const uint32_t pa0 = p01[2 * ks],     pa1 = p23[2 * ks];
                const uint32_t pa2 = p01[2 * ks + 1], pa3 = p23[2 * ks + 1];
                #pragma unroll
                for (int na = 0; na < 8; na++) {
                    const int d = na * 8 + gid;
                    const int o0 = (8 * ks + tig) * 72 + d;
                    const int o1 = (8 * ks + tig + 4) * 72 + d;
                    mma_f16(of[na], pa0, pa1, pa2, pa3, v_hi[o0], v_hi[o1]);
                    mma_f16(of[na], pa0, pa1, pa2, pa3, v_lo[o0], v_lo[o1]);
                }
            }
        }
        __syncthreads();
    }

    if (split < 0) {
        // light: normalize and write y planes
        const float i0 = 1.f / l0, i1 = 1.f / l1;
        const int gr0 = b * 2048 + r0g;
        #pragma unroll
        for (int na = 0; na < 8; na++) {
            const int pr = h * 32 + na * 4 + tig;
            uint32_t h0, lo0;
            split2(of[na][0] * i0, of[na][1] * i0, h0, lo0);
            yh[(size_t)gr0 * 384 + pr] = h0;
            yl[(size_t)gr0 * 384 + pr] = lo0;
            split2(of[na][2] * i1, of[na][3] * i1, h0, lo0);
            yh[(size_t)(gr0 + 8) * 384 + pr] = h0;
            yl[(size_t)(gr0 + 8) * 384 + pr] = lo0;
        }
    } else {
        // heavy: write unnormalized partial (of, m, l)
        const int hb = bx - 8;
        const int r0 = wid * 16 + gid;
        float* pob = po + ((((size_t)split * 24 + bh) * 8 + hb) * 128) * 64;
        #pragma unroll
        for (int na = 0; na < 8; na++) {
            *(float2*)(pob + (size_t)r0 * 64 + na * 8 + 2 * tig) =
                make_float2(of[na][0], of[na][1]);
            *(float2*)(pob + (size_t)(r0 + 8) * 64 + na * 8 + 2 * tig) =
                make_float2(of[na][2], of[na][3]);
        }
        if (tig == 0) {
            float* mlb = ml + ((((size_t)split * 24 + bh) * 8 + hb) * 128) * 2;
            mlb[r0 * 2]           = m0;
            mlb[r0 * 2 + 1]       = l0;
            mlb[(r0 + 8) * 2]     = m1;
            mlb[(r0 + 8) * 2 + 1] = l1;
        }
    }
}

// ---------------------------------------------------------------------------
// Merge split-KV partials into y planes (heavy q-blocks only).
// ---------------------------------------------------------------------------
__global__ void merge_heavy(const float* __restrict__ po,
                            const float* __restrict__ ml,
                            uint32_t* __restrict__ yh, uint32_t* __restrict__ yl)
{
    int idx = blockIdx.x * 256 + threadIdx.x;  // 24*8*128*16 = 393216
    int d4 = idx & 15;
    int r  = (idx >> 4) & 127;
    int hb = (idx >> 11) & 7;
    int bh = idx >> 14;                        // 0..23
    int b = bh / HH, h = bh % HH;

    size_t rowA = (((size_t)0 * 24 + bh) * 8 + hb) * 128 + r;
    size_t rowB = (((size_t)1 * 24 + bh) * 8 + hb) * 128 + r;
    float mA = ml[rowA * 2], lA = ml[rowA * 2 + 1];
    float mB = ml[rowB * 2], lB = ml[rowB * 2 + 1];
    float m = fmaxf(mA, mB);
    float sA = exp2f(mA - m), sB = exp2f(mB - m);
    float inv = 1.f / (lA * sA + lB * sB);

    float4 oA = *(const float4*)(po + rowA * 64 + 4 * d4);
    float4 oB = *(const float4*)(po + rowB * 64 + 4 * d4);
    float v0 = (oA.x * sA + oB.x * sB) * inv;
    float v1 = (oA.y * sA + oB.y * sB) * inv;
    float v2 = (oA.z * sA + oB.z * sB) * inv;
    float v3 = (oA.w * sA + oB.w * sB) * inv;

    int grow = b * 2048 + (8 + hb) * 128 + r;
    int pr = h * 32 + 2 * d4;
    uint32_t hi, lo;
    split2(v0, v1, hi, lo);
    yh[(size_t)grow * 384 + pr]     = hi;
    yl[(size_t)grow * 384 + pr]     = lo;
    split2(v2, v3, hi, lo);
    yh[(size_t)grow * 384 + pr + 1] = hi;
    yl[(size_t)grow * 384 + pr + 1] = lo;
}

extern "C" void kernel_launch(void* const* d_in, const int* in_sizes, int n_in,
                              void* d_out, int out_size)
{
    const float* x      = (const float*)d_in[0];
    const float* W_attn = (const float*)d_in[1];
    const float* b_attn = (const float*)d_in[2];
    const float* W_proj = (const float*)d_in[3];
    const float* b_proj = (const float*)d_in[4];
    float* out = (float*)d_out;

    uint32_t *qkvp, *vt, *xp, *yp, *wt, *wt2;
    float *po, *mlb;
    cudaGetSymbolAddress((void**)&qkvp, g_qkvp);
    cudaGetSymbolAddress((void**)&vt, g_vt);
    cudaGetSymbolAddress((void**)&xp, g_xp);
    cudaGetSymbolAddress((void**)&yp, g_yp);
    cudaGetSymbolAddress((void**)&wt, g_wt);
    cudaGetSymbolAddress((void**)&wt2, g_wt2);
    cudaGetSymbolAddress((void**)&po, g_po);
    cudaGetSymbolAddress((void**)&mlb, g_ml);

    const int GEMM_SMEM  = 2 * 10240 * 4;   // 81920
    const int FLASH_SMEM = 2 * 9216 * 4;    // 73728
    cudaFuncSetAttribute(gemm_planes<0>,
                         cudaFuncAttributeMaxDynamicSharedMemorySize, GEMM_SMEM);
    cudaFuncSetAttribute(gemm_planes<1>,
                         cudaFuncAttributeMaxDynamicSharedMemorySize, GEMM_SMEM);
    cudaFuncSetAttribute(flash_planes,
                         cudaFuncAttributeMaxDynamicSharedMemorySize, FLASH_SMEM);

    split_x<<<786432 / 256, 256>>>(x, xp, xp + PSZ);                       // 0
    transpose_split<<<dim3(C3 / 32, CC / 32), dim3(32, 8)>>>(              // 1
        W_attn, wt, wt + (size_t)C3 * CC / 2, CC, C3);
    transpose_split<<<dim3(CC / 32, CC / 32), dim3(32, 8)>>>(              // 2
        W_proj, wt2, wt2 + (size_t)CC * CC / 2, CC, CC);

    gemm_planes<0><<<dim3(C3 / 128, MTOT / 128), 256, GEMM_SMEM>>>(        // 3
        xp, xp + PSZ, wt, wt + (size_t)C3 * CC / 2, b_attn,
        nullptr, qkvp, MTOT, C3, CC);

    pack_vt<<<(2048 * 384) / 256, 256>>>(                                  // 4
        qkvp + (size_t)4 * PSZ, qkvp + (size_t)5 * PSZ, vt, vt + (size_t)2048 * 768);

    flash_planes<<<dim3(24, 24), 256, FLASH_SMEM>>>(                       // 5
        qkvp, vt, yp, yp + PSZ, po, mlb);

    merge_heavy<<<393216 / 256, 256>>>(po, mlb, yp, yp + PSZ);             // 6

    gemm_planes<1><<<dim3(CC / 128, MTOT / 128), 256, GEMM_SMEM>>>(        // 7
        yp, yp + PSZ, wt2, wt2 + (size_t)CC * CC / 2, b_proj,
        out, nullptr, MTOT, CC, CC);
}

// round 12
// speedup vs baseline: 4.0446x; 1.2949x over previous
#include <cuda_runtime.h>
#include <cuda_bf16.h>
#include <cuda_fp16.h>
#include <math.h>
#include <cstdint>

#define BB 2
#define TT 2048
#define CC 768
#define HH 12
#define HS 64
#define C3 2304
#define MTOT (BB*TT)          // 4096
#define PSZ (4096*384)        // u32 per plane for [M][768 cols] fp16x2 pairs
#define QSCALE 0.18033688011112042f   // 0.125 * log2(e)

// Scratch (allocation-free contract) — all planes are fp16x2-packed u32
__device__ uint32_t g_qkvp[5 * (size_t)PSZ];        // q_hi,q_lo,k,v_hi,v_lo
__device__ uint32_t g_vt[2 * (size_t)2048 * 768];   // V token-pair-major fp16 hi/lo
__device__ uint32_t g_xp[(size_t)PSZ];              // x single fp16 plane
__device__ uint32_t g_yp[(size_t)PSZ];              // y single fp16 plane
__device__ uint32_t g_wt[(size_t)CC * C3];          // W_attn^T fp16 hi/lo planes
__device__ uint32_t g_wt2[2 * (size_t)CC * CC / 2]; // W_proj^T fp16 hi/lo planes
// split-KV partials: [2 splits][24 bh][8 heavy blocks][128 rows][64 dims]
__device__ float g_po[(size_t)2 * 24 * 8 * 128 * 64];
__device__ float g_ml[(size_t)2 * 24 * 8 * 128 * 2];

// ---------------------------------------------------------------------------
// Helpers
// ---------------------------------------------------------------------------
__device__ __forceinline__ uint32_t smem_u32(const void* p) {
    uint32_t a;
    asm("{ .reg .u64 t; cvta.to.shared.u64 t, %1; cvt.u32.u64 %0, t; }"
        : "=r"(a) : "l"(p));
    return a;
}

__device__ __forceinline__ void mma_f16(float c[4],
    uint32_t a0, uint32_t a1, uint32_t a2, uint32_t a3,
    uint32_t b0, uint32_t b1)
{
    asm("mma.sync.aligned.m16n8k16.row.col.f32.f16.f16.f32 "
        "{%0,%1,%2,%3}, {%4,%5,%6,%7}, {%8,%9}, {%0,%1,%2,%3};"
        : "+f"(c[0]), "+f"(c[1]), "+f"(c[2]), "+f"(c[3])
        : "r"(a0), "r"(a1), "r"(a2), "r"(a3), "r"(b0), "r"(b1));
}

__device__ __forceinline__ void ldm_x4(uint32_t& r0, uint32_t& r1,
                                       uint32_t& r2, uint32_t& r3, uint32_t addr)
{
    asm volatile("ldmatrix.sync.aligned.m8n8.x4.shared.b16 {%0,%1,%2,%3}, [%4];"
        : "=r"(r0), "=r"(r1), "=r"(r2), "=r"(r3) : "r"(addr));
}

// fp32 pair -> fp16x2 (round)
__device__ __forceinline__ uint32_t cvtH(float x, float y)
{
    __half2 h = __floats2half2_rn(x, y);
    return *reinterpret_cast<uint32_t*>(&h);
}

// fp32 pair -> fp16x2 hi + fp16x2 lo (residual)
__device__ __forceinline__ void splitH(float x, float y, uint32_t& hi, uint32_t& lo)
{
    __half2 h = __floats2half2_rn(x, y);
    hi = *reinterpret_cast<uint32_t*>(&h);
    float hx = __low2float(h), hy = __high2float(h);
    __half2 l = __floats2half2_rn(x - hx, y - hy);
    lo = *reinterpret_cast<uint32_t*>(&l);
}

__device__ __forceinline__ uint32_t ex2_f16x2(uint32_t x) {
    uint32_t r;
    asm("ex2.approx.f16x2 %0, %1;" : "=r"(r) : "r"(x));
    return r;
}

__device__ __forceinline__ void cpasync16(uint32_t dst, const void* src) {
    asm volatile("cp.async.cg.shared.global [%0], [%1], 16;"
                 :: "r"(dst), "l"(src));
}
#define CP_COMMIT() asm volatile("cp.async.commit_group;" ::: "memory")
#define CP_WAIT1()  asm volatile("cp.async.wait_group 1;" ::: "memory")
#define CP_WAIT0()  asm volatile("cp.async.wait_group 0;" ::: "memory")

// ---------------------------------------------------------------------------
// Prep kernels
// ---------------------------------------------------------------------------
// x [4096][768] fp32 -> single fp16 plane [4096][384]
__global__ void split_x(const float* __restrict__ x, uint32_t* __restrict__ xh)
{
    int idx = blockIdx.x * 256 + threadIdx.x;
    int r = idx / 192, j2 = idx % 192;
    float4 v = *(const float4*)(x + (size_t)r * 768 + 4 * j2);
    *(uint2*)(xh + (size_t)r * 384 + 2 * j2) =
        make_uint2(cvtH(v.x, v.y), cvtH(v.z, v.w));
}

// W [K][N] fp32 -> transposed fp16 hi/lo pair planes [N][K/2]
__global__ void transpose_splitH(const float* __restrict__ in,
                                 uint32_t* __restrict__ out_hi,
                                 uint32_t* __restrict__ out_lo,
                                 int K, int N)
{
    __shared__ float t[32][33];
    int n0 = blockIdx.x << 5, k0 = blockIdx.y << 5;
    int x = threadIdx.x, y = threadIdx.y;
    #pragma unroll
    for (int i = 0; i < 32; i += 8)
        t[y + i][x] = in[(size_t)(k0 + y + i) * N + n0 + x];
    __syncthreads();
    const int xp = x & 15, plane = x >> 4;
    #pragma unroll
    for (int i = 0; i < 32; i += 8) {
        int n = n0 + y + i;
        uint32_t h, l;
        splitH(t[2 * xp][y + i], t[2 * xp + 1][y + i], h, l);
        size_t o = (size_t)n * (K / 2) + k0 / 2 + xp;
        if (plane == 0) out_hi[o] = h;
        else            out_lo[o] = l;
    }
}

// V fp16 dim-pair planes -> token-pair-major fp16 hi/lo planes (pure permute)
__global__ void pack_vt(const uint32_t* __restrict__ vh,
                        const uint32_t* __restrict__ vl,
                        uint32_t* __restrict__ vth, uint32_t* __restrict__ vtl)
{
    int idx = blockIdx.x * 256 + threadIdx.x;
    int bp = idx / 384, j = idx % 384;
    size_t s0 = (size_t)(2 * bp) * 384 + j;
    size_t s1 = s0 + 384;
    uint32_t ah = vh[s0], bh = vh[s1];
    uint32_t al = vl[s0], bl = vl[s1];
    size_t o = (size_t)bp * 768 + 2 * j;
    vth[o]     = __byte_perm(ah, bh, 0x5410);
    vth[o + 1] = __byte_perm(ah, bh, 0x7632);
    vtl[o]     = __byte_perm(al, bl, 0x5410);
    vtl[o + 1] = __byte_perm(al, bl, 0x7632);
}

// ---------------------------------------------------------------------------
// fp16 2-product GEMM: out = A(fp16) @ (Wh+Wl)^T + bias.
// CTA 128x128, BK=32 floats, 8 warps 4(m)x2(n), cp.async 2-stage.
// Stage layout (u32): A@0 [128][20], Bh@2560, Bl@5120. Stage = 7680 u32.
// ---------------------------------------------------------------------------
__device__ __forceinline__ void gemm_issue(
    uint32_t st_u32,
    const uint32_t* Ah,
    const uint32_t* Bh, const uint32_t* Bl,
    int row0, int col0, int K2, int kp0, int tid)
{
    #pragma unroll
    for (int p = 0; p < 2; p++) {
        int idx = p * 256 + tid;          // 0..511
        int r = idx >> 2, c = idx & 3;
        uint32_t dst = st_u32 + (r * 20 + c * 4) * 4;
        cpasync16(dst, Ah + (size_t)(row0 + r) * K2 + kp0 + c * 4);
    }
    #pragma unroll
    for (int p = 0; p < 4; p++) {
        int idx = p * 256 + tid;          // 0..1023
        const uint32_t* src = (idx < 512) ? Bh : Bl;
        int rem = idx & 511;
        int r = rem >> 2, c = rem & 3;
        uint32_t dst = st_u32 + ((2560 + ((idx < 512) ? 0 : 2560)) + r * 20 + c * 4) * 4;
        cpasync16(dst, src + (size_t)(col0 + r) * K2 + kp0 + c * 4);
    }
}

template <int MODE>
__global__ __launch_bounds__(256, 2) void gemm_planes(
    const uint32_t* __restrict__ Ah,
    const uint32_t* __restrict__ Bh, const uint32_t* __restrict__ Bl,
    const float* __restrict__ bias,
    float* __restrict__ outf,
    uint32_t* __restrict__ qkvp,
    int M, int N, int K)
{
    extern __shared__ uint32_t sm[];     // 2 stages x 7680 u32
    const uint32_t sm_u = smem_u32(sm);

    const int tid  = threadIdx.x;
    const int wid  = tid >> 5, lane = tid & 31;
    const int gid  = lane >> 2, tig = lane & 3;
    const int wm   = wid & 3;
    const int wn   = wid >> 2;
    const int row0 = blockIdx.y * 128;
    const int col0 = blockIdx.x * 128;
    const int K2   = K >> 1;
    const int NK   = K >> 5;

    const int lane7 = lane & 7;
    const int aRow  = wm * 32 + lane7 + ((lane >> 3) & 1) * 8;
    const int aColB = ((lane >> 4) & 1) * 16;
    const uint32_t aOff = (uint32_t)(aRow * 80) + aColB;
    const int bRow  = wn * 64 + lane7 + ((lane >> 4) & 1) * 8;
    const int bColB = ((lane >> 3) & 1) * 16;
    const uint32_t bOff = 2560 * 4 + (uint32_t)(bRow * 80) + bColB;

    float cf[2][8][4];
    #pragma unroll
    for (int ma = 0; ma < 2; ma++)
        #pragma unroll
        for (int na = 0; na < 8; na++)
            #pragma unroll
            for (int r = 0; r < 4; r++) cf[ma][na][r] = 0.f;

    gemm_issue(sm_u, Ah, Bh, Bl, row0, col0, K2, 0, tid);
    CP_COMMIT();

    for (int kt = 0; kt < NK; kt++) {
        const int s = kt & 1;
        if (kt + 1 < NK) {
            gemm_issue(sm_u + (s ^ 1) * 30720, Ah, Bh, Bl,
                       row0, col0, K2, (kt + 1) << 4, tid);
            CP_COMMIT();
            CP_WAIT1();
        } else {
            CP_WAIT0();
        }
        __syncthreads();

        const uint32_t stage = sm_u + s * 30720;

        #pragma unroll
        for (int ss = 0; ss < 2; ss++) {
            const uint32_t ssb = ss * 32;
            uint32_t a[2][4];
            #pragma unroll
            for (int ma = 0; ma < 2; ma++)
                ldm_x4(a[ma][0], a[ma][1], a[ma][2], a[ma][3],
                       stage + aOff + ma * 1280 + ssb);
            #pragma unroll
            for (int j = 0; j < 4; j++) {
                uint32_t bh0, bh1, bh2, bh3, bl0, bl1, bl2, bl3;
                ldm_x4(bh0, bh1, bh2, bh3, stage + bOff + j * 1280 + ssb);
                ldm_x4(bl0, bl1, bl2, bl3, stage + 2560 * 4 + bOff + j * 1280 + ssb);
                #pragma unroll
                for (int ma = 0; ma < 2; ma++) {
                    mma_f16(cf[ma][2 * j],     a[ma][0], a[ma][1], a[ma][2], a[ma][3], bh0, bh1);
                    mma_f16(cf[ma][2 * j],     a[ma][0], a[ma][1], a[ma][2], a[ma][3], bl0, bl1);
                    mma_f16(cf[ma][2 * j + 1], a[ma][0], a[ma][1], a[ma][2], a[ma][3], bh2, bh3);
                    mma_f16(cf[ma][2 * j + 1], a[ma][0], a[ma][1], a[ma][2], a[ma][3], bl2, bl3);
                }
            }
        }
        __syncthreads();
    }

    if (MODE == 1) {
        #pragma unroll
        for (int ma = 0; ma < 2; ma++) {
            const int rg = row0 + wm * 32 + ma * 16 + gid;
            #pragma unroll
            for (int na = 0; na < 8; na++) {
                const int cg = col0 + wn * 64 + na * 8 + tig * 2;
                const float bx0 = bias[cg], bx1 = bias[cg + 1];
                *(float2*)(outf + (size_t)rg * N + cg) =
                    make_float2(cf[ma][na][0] + bx0, cf[ma][na][1] + bx1);
                *(float2*)(outf + (size_t)(rg + 8) * N + cg) =
                    make_float2(cf[ma][na][2] + bx0, cf[ma][na][3] + bx1);
            }
        }
    } else {
        // scatter: Q (fp16 hi/lo, pre-scaled), K (single fp16), V (fp16 hi/lo)
        const int which = col0 / 768;
        const int lc0 = col0 - which * 768;
        #pragma unroll
        for (int ma = 0; ma < 2; ma++) {
            const int rg = row0 + wm * 32 + ma * 16 + gid;
            #pragma unroll
            for (int na = 0; na < 8; na++) {
                const int gc = col0 + wn * 64 + na * 8 + tig * 2;
                const int pr = (lc0 >> 1) + wn * 32 + na * 4 + tig;
                const float bx0 = bias[gc], bx1 = bias[gc + 1];
                float v0 = cf[ma][na][0] + bx0, v1 = cf[ma][na][1] + bx1;
                float v2 = cf[ma][na][2] + bx0, v3 = cf[ma][na][3] + bx1;
                if (which == 0) {
                    uint32_t h, l;
                    splitH(v0 * QSCALE, v1 * QSCALE, h, l);
                    qkvp[(size_t)rg * 384 + pr] = h;
                    qkvp[(size_t)PSZ + (size_t)rg * 384 + pr] = l;
                    splitH(v2 * QSCALE, v3 * QSCALE, h, l);
                    qkvp[(size_t)(rg + 8) * 384 + pr] = h;
                    qkvp[(size_t)PSZ + (size_t)(rg + 8) * 384 + pr] = l;
                } else if (which == 1) {
                    qkvp[(size_t)2 * PSZ + (size_t)rg * 384 + pr] = cvtH(v0, v1);
                    qkvp[(size_t)2 * PSZ + (size_t)(rg + 8) * 384 + pr] = cvtH(v2, v3);
                } else {
                    uint32_t h, l;
                    splitH(v0, v1, h, l);
                    qkvp[(size_t)3 * PSZ + (size_t)rg * 384 + pr] = h;
                    qkvp[(size_t)4 * PSZ + (size_t)rg * 384 + pr] = l;
                    splitH(v2, v3, h, l);
                    qkvp[(size_t)3 * PSZ + (size_t)(rg + 8) * 384 + pr] = h;
                    qkvp[(size_t)4 * PSZ + (size_t)(rg + 8) * 384 + pr] = l;
                }
            }
        }
    }
}

// ---------------------------------------------------------------------------
// Flash attention: fp16 2-product QK, fp16 2-product PV, split-KV balancing.
// Stage layout (u32): K@0 [64][36], Vh@2304 [32][72], Vl@4608. Stage 6912 u32.
// ---------------------------------------------------------------------------
__device__ __forceinline__ void flash_issue(
    uint32_t st_u32,
    const uint32_t* kp,
    const uint32_t* vth, const uint32_t* vtl,
    int tok0, int vrow0, int h, int tid)
{
    #pragma unroll
    for (int p = 0; p < 2; p++) {
        int idx = p * 256 + tid;          // 0..511
        int r = idx >> 3, c = idx & 7;
        uint32_t dst = st_u32 + (r * 36 + c * 4) * 4;
        cpasync16(dst, kp + (size_t)(tok0 + r) * 384 + h * 32 + c * 4);
    }
    #pragma unroll
    for (int p = 0; p < 4; p++) {
        int idx = p * 256 + tid;          // 0..1023
        const uint32_t* src = (idx < 512) ? vth : vtl;
        int rem = idx & 511;
        int r = rem >> 4, c = rem & 15;
        uint32_t dst = st_u32 + ((2304 + ((idx < 512) ? 0 : 2304)) + r * 72 + c * 4) * 4;
        cpasync16(dst, src + (size_t)(vrow0 + r) * 768 + h * 64 + c * 4);
    }
}

__global__ __launch_bounds__(256, 2) void flash_planes(
    const uint32_t* __restrict__ qkvp, const uint32_t* __restrict__ vt,
    uint32_t* __restrict__ yp,
    float* __restrict__ po, float* __restrict__ ml)
{
    extern __shared__ uint32_t sm[];       // 2 stages x 6912 u32
    const uint32_t sm_u = smem_u32(sm);

    const int tid = threadIdx.x;
    const int wid = tid >> 5, lane = tid & 31;
    const int gid = lane >> 2, tig = lane & 3;
    const int bh = blockIdx.x;             // 0..23
    const int u  = blockIdx.y;             // 0..23 (heavy halves first)
    const int b  = bh / HH;
    const int h  = bh % HH;

    int bx, split, kt0, kt1;
    if (u < 16) {
        bx    = 8 + (u >> 1);
        split = u & 1;
        const int half = bx + 1;
        kt0 = split ? half : 0;
        kt1 = split ? (2 * bx + 2) : half;
    } else {
        bx = 23 - u;
        split = -1;
        kt0 = 0;
        kt1 = 2 * bx + 2;
    }
    const int q0 = bx * 128;

    const uint32_t* qph = qkvp;
    const uint32_t* qpl = qkvp + (size_t)PSZ;
    const uint32_t* kp  = qkvp + (size_t)2 * PSZ;
    const uint32_t* vth = vt;
    const uint32_t* vtl = vt + (size_t)2048 * 768;

    const int lane7 = lane & 7;
    const int kRow  = lane7 + ((lane >> 4) & 1) * 8;
    const int kColB = ((lane >> 3) & 1) * 16;
    const uint32_t kOff = (uint32_t)(kRow * 144) + kColB;

    const int grow0 = b * 2048 + q0 + wid * 16 + gid;
    uint32_t qh[4][4], ql[4][4];
    #pragma unroll
    for (int ks = 0; ks < 4; ks++) {
        const int pr = h * 32 + 8 * ks + tig;
        qh[ks][0] = qph[(size_t)grow0 * 384 + pr];
        qh[ks][1] = qph[(size_t)(grow0 + 8) * 384 + pr];
        qh[ks][2] = qph[(size_t)grow0 * 384 + pr + 4];
        qh[ks][3] = qph[(size_t)(grow0 + 8) * 384 + pr + 4];
        ql[ks][0] = qpl[(size_t)grow0 * 384 + pr];
        ql[ks][1] = qpl[(size_t)(grow0 + 8) * 384 + pr];
        ql[ks][2] = qpl[(size_t)grow0 * 384 + pr + 4];
        ql[ks][3] = qpl[(size_t)(grow0 + 8) * 384 + pr + 4];
    }

    float of[8][4];
    #pragma unroll
    for (int na = 0; na < 8; na++)
        #pragma unroll
        for (int r = 0; r < 4; r++) of[na][r] = 0.f;
    float m0 = -1e30f, m1 = -1e30f, l0 = 0.f, l1 = 0.f;
    const int r0g = q0 + wid * 16 + gid;
    const int r1g = r0g + 8;

    const int nloc = kt1 - kt0;
    flash_issue(sm_u, kp, vth, vtl,
                b * 2048 + kt0 * 64, b * 1024 + kt0 * 32, h, tid);
    CP_COMMIT();

    for (int ki = 0; ki < nloc; ki++) {
        const int kt = kt0 + ki;
        const int s = ki & 1;
        if (ki + 1 < nloc) {
            flash_issue(sm_u + (s ^ 1) * 27648, kp, vth, vtl,
                        b * 2048 + (kt + 1) * 64, b * 1024 + (kt + 1) * 32, h, tid);
            CP_COMMIT();
            CP_WAIT1();
        } else {
            CP_WAIT0();
        }
        __syncthreads();

        if (kt * 64 <= q0 + wid * 16 + 15) {
            const uint32_t stage = sm_u + s * 27648;
            const uint32_t* v_hi = sm + s * 6912 + 2304;
            const uint32_t* v_lo = v_hi + 2304;

            // ---- S(log2 domain) = Qscaled @ K^T (fp16, 2 products) ----
            float sf[8][4];
            #pragma unroll
            for (int na = 0; na < 8; na++)
                #pragma unroll
                for (int r = 0; r < 4; r++) sf[na][r] = 0.f;

            #pragma unroll
            for (int ks = 0; ks < 4; ks++) {
                const uint32_t ksb = ks * 32;
                #pragma unroll
                for (int j = 0; j < 4; j++) {
                    uint32_t b0, b1, b2, b3;
                    ldm_x4(b0, b1, b2, b3, stage + kOff + j * 2304 + ksb);
                    mma_f16(sf[2 * j],     qh[ks][0], qh[ks][1], qh[ks][2], qh[ks][3], b0, b1);
                    mma_f16(sf[2 * j],     ql[ks][0], ql[ks][1], ql[ks][2], ql[ks][3], b0, b1);
                    mma_f16(sf[2 * j + 1], qh[ks][0], qh[ks][1], qh[ks][2], qh[ks][3], b2, b3);
                    mma_f16(sf[2 * j + 1], ql[ks][0], ql[ks][1], ql[ks][2], ql[ks][3], b2, b3);
                }
            }

            // ---- causal mask ----
            const bool need_mask = (kt >= 2 * bx);
            if (need_mask) {
                #pragma unroll
                for (int na = 0; na < 8; na++) {
                    const int cg = kt * 64 + na * 8 + tig * 2;
                    if (cg     > r0g) sf[na][0] = -1e30f;
                    if (cg + 1 > r0g) sf[na][1] = -1e30f;
                    if (cg     > r1g) sf[na][2] = -1e30f;
                    if (cg + 1 > r1g) sf[na][3] = -1e30f;
                }
            }

            // ---- online softmax (log2 domain, fp16 exp2) ----
            float rm0 = -1e30f, rm1 = -1e30f;
            #pragma unroll
            for (int na = 0; na < 8; na++) {
                rm0 = fmaxf(rm0, fmaxf(sf[na][0], sf[na][1]));
                rm1 = fmaxf(rm1, fmaxf(sf[na][2], sf[na][3]));
            }
            rm0 = fmaxf(rm0, __shfl_xor_sync(0xffffffffu, rm0, 1));
            rm0 = fmaxf(rm0, __shfl_xor_sync(0xffffffffu, rm0, 2));
            rm1 = fmaxf(rm1, __shfl_xor_sync(0xffffffffu, rm1, 1));
            rm1 = fmaxf(rm1, __shfl_xor_sync(0xffffffffu, rm1, 2));
            const float mn0 = fmaxf(m0, rm0), mn1 = fmaxf(m1, rm1);
            const float c0 = exp2f(m0 - mn0), c1 = exp2f(m1 - mn1);
            float rs0 = 0.f, rs1 = 0.f;
            uint32_t p01[8], p23[8];
            #pragma unroll
            for (int na = 0; na < 8; na++) {
                __half2 h01 = __floats2half2_rn(sf[na][0] - mn0, sf[na][1] - mn0);
                __half2 h23 = __floats2half2_rn(sf[na][2] - mn1, sf[na][3] - mn1);
                p01[na] = ex2_f16x2(*reinterpret_cast<uint32_t*>(&h01));
                p23[na] = ex2_f16x2(*reinterpret_cast<uint32_t*>(&h23));
                float2 f01 = __half22float2(*reinterpret_cast<__half2*>(&p01[na]));
                float2 f23 = __half22float2(*reinterpret_cast<__half2*>(&p23[na]));
                rs0 += f01.x + f01.y;
                rs1 += f23.x + f23.y;
            }
            rs0 += __shfl_xor_sync(0xffffffffu, rs0, 1);
            rs0 += __shfl_xor_sync(0xffffffffu, rs0, 2);
            rs1 += __shfl_xor_sync(0xffffffffu, rs1, 1);
            rs1 += __shfl_xor_sync(0xffffffffu, rs1, 2);
            l0 = l0 * c0 + rs0; m0 = mn0;
            l1 = l1 * c1 + rs1; m1 = mn1;
            #pragma unroll
            for (int na = 0; na < 8; na++) {
                of[na][0] *= c0; of[na][1] *= c0;
                of[na][2] *= c1; of[na][3] *= c1;
            }

            // ---- O += P @ V (fp16 P, fp16 hi/lo V) ----
            #pragma unroll
            for (int ks = 0; ks < 4; ks++) {
                const uint32_t pa0 = p01[2 * ks],     pa1 = p23[2 * ks];
                const uint32_t pa2 = p01[2 * ks + 1], pa3 = p23[2 * ks + 1];
                #pragma unroll
                for (int na = 0; na < 8; na++) {
                    const int d = na * 8 + gid;
                    const int o0 = (8 * ks + tig) * 72 + d;
                    const int o1 = (8 * ks + tig + 4) * 72 + d;
                    mma_f16(of[na], pa0, pa1, pa2, pa3, v_hi[o0], v_hi[o1]);
                    mma_f16(of[na], pa0, pa1, pa2, pa3, v_lo[o0], v_lo[o1]);
                }
            }
        }
        __syncthreads();
    }

    if (split < 0) {
        // light: normalize and write y plane (single fp16)
        const float i0 = 1.f / l0, i1 = 1.f / l1;
        const int gr0 = b * 2048 + r0g;
        #pragma unroll
        for (int na = 0; na < 8; na++) {
            const int pr = h * 32 + na * 4 + tig;
            yp[(size_t)gr0 * 384 + pr] = cvtH(of[na][0] * i0, of[na][1] * i0);
            yp[(size_t)(gr0 + 8) * 384 + pr] = cvtH(of[na][2] * i1, of[na][3] * i1);
        }
    } else {
        const int hb = bx - 8;
        const int r0 = wid * 16 + gid;
        float* pob = po + ((((size_t)split * 24 + bh) * 8 + hb) * 128) * 64;
        #pragma unroll
        for (int na = 0; na < 8; na++) {
            *(float2*)(pob + (size_t)r0 * 64 + na * 8 + 2 * tig) =
                make_float2(of[na][0], of[na][1]);
            *(float2*)(pob + (size_t)(r0 + 8) * 64 + na * 8 + 2 * tig) =
                make_float2(of[na][2], of[na][3]);
        }
        if (tig == 0) {
            float* mlb = ml + ((((size_t)split * 24 + bh) * 8 + hb) * 128) * 2;
            mlb[r0 * 2]           = m0;
            mlb[r0 * 2 + 1]       = l0;
            mlb[(r0 + 8) * 2]     = m1;
            mlb[(r0 + 8) * 2 + 1] = l1;
        }
    }
}

// ---------------------------------------------------------------------------
// Merge split-KV partials into y plane (heavy q-blocks only).
// ---------------------------------------------------------------------------
__global__ void merge_heavy(const float* __restrict__ po,
                            const float* __restrict__ ml,
                            uint32_t* __restrict__ yp)
{
    int idx = blockIdx.x * 256 + threadIdx.x;  // 393216
    int d4 = idx & 15;
    int r  = (idx >> 4) & 127;
    int hb = (idx >> 11) & 7;
    int bh = idx >> 14;
    int b = bh / HH, h = bh % HH;

    size_t rowA = (((size_t)0 * 24 + bh) * 8 + hb) * 128 + r;
    size_t rowB = (((size_t)1 * 24 + bh) * 8 + hb) * 128 + r;
    float mA = ml[rowA * 2], lA = ml[rowA * 2 + 1];
    float mB = ml[rowB * 2], lB = ml[rowB * 2 + 1];
    float m = fmaxf(mA, mB);
    float sA = exp2f(mA - m), sB = exp2f(mB - m);
    float inv = 1.f / (lA * sA + lB * sB);

    float4 oA = *(const float4*)(po + rowA * 64 + 4 * d4);
    float4 oB = *(const float4*)(po + rowB * 64 + 4 * d4);
    float v0 = (oA.x * sA + oB.x * sB) * inv;
    float v1 = (oA.y * sA + oB.y * sB) * inv;
    float v2 = (oA.z * sA + oB.z * sB) * inv;
    float v3 = (oA.w * sA + oB.w * sB) * inv;

    int grow = b * 2048 + (8 + hb) * 128 + r;
    int pr = h * 32 + 2 * d4;
    yp[(size_t)grow * 384 + pr]     = cvtH(v0, v1);
    yp[(size_t)grow * 384 + pr + 1] = cvtH(v2, v3);
}

extern "C" void kernel_launch(void* const* d_in, const int* in_sizes, int n_in,
                              void* d_out, int out_size)
{
    const float* x      = (const float*)d_in[0];
    const float* W_attn = (const float*)d_in[1];
    const float* b_attn = (const float*)d_in[2];
    const float* W_proj = (const float*)d_in[3];
    const float* b_proj = (const float*)d_in[4];
    float* out = (float*)d_out;

    uint32_t *qkvp, *vt, *xp, *yp, *wt, *wt2;
    float *po, *mlb;
    cudaGetSymbolAddress((void**)&qkvp, g_qkvp);
    cudaGetSymbolAddress((void**)&vt, g_vt);
    cudaGetSymbolAddress((void**)&xp, g_xp);
    cudaGetSymbolAddress((void**)&yp, g_yp);
    cudaGetSymbolAddress((void**)&wt, g_wt);
    cudaGetSymbolAddress((void**)&wt2, g_wt2);
    cudaGetSymbolAddress((void**)&po, g_po);
    cudaGetSymbolAddress((void**)&mlb, g_ml);

    const int GEMM_SMEM  = 2 * 7680 * 4;    // 61440
    const int FLASH_SMEM = 2 * 6912 * 4;    // 55296
    cudaFuncSetAttribute(gemm_planes<0>,
                         cudaFuncAttributeMaxDynamicSharedMemorySize, GEMM_SMEM);
    cudaFuncSetAttribute(gemm_planes<1>,
                         cudaFuncAttributeMaxDynamicSharedMemorySize, GEMM_SMEM);
    cudaFuncSetAttribute(flash_planes,
                         cudaFuncAttributeMaxDynamicSharedMemorySize, FLASH_SMEM);

    split_x<<<786432 / 256, 256>>>(x, xp);                                 // 0
    transpose_splitH<<<dim3(C3 / 32, CC / 32), dim3(32, 8)>>>(             // 1
        W_attn, wt, wt + (size_t)C3 * CC / 2, CC, C3);
    transpose_splitH<<<dim3(CC / 32, CC / 32), dim3(32, 8)>>>(             // 2
        W_proj, wt2, wt2 + (size_t)CC * CC / 2, CC, CC);

    gemm_planes<0><<<dim3(C3 / 128, MTOT / 128), 256, GEMM_SMEM>>>(        // 3
        xp, wt, wt + (size_t)C3 * CC / 2, b_attn,
        nullptr, qkvp, MTOT, C3, CC);

    pack_vt<<<(2048 * 384) / 256, 256>>>(                                  // 4
        qkvp + (size_t)3 * PSZ, qkvp + (size_t)4 * PSZ, vt, vt + (size_t)2048 * 768);

    flash_planes<<<dim3(24, 24), 256, FLASH_SMEM>>>(                       // 5
        qkvp, vt, yp, po, mlb);

    merge_heavy<<<393216 / 256, 256>>>(po, mlb, yp);                       // 6

    gemm_planes<1><<<dim3(CC / 128, MTOT / 128), 256, GEMM_SMEM>>>(        // 7
        yp, wt2, wt2 + (size_t)CC * CC / 2, b_proj,
        out, nullptr, MTOT, CC, CC);
}

// round 13
// speedup vs baseline: 4.0792x; 1.0085x over previous
#include <cuda_runtime.h>
#include <cuda_bf16.h>
#include <cuda_fp16.h>
#include <math.h>
#include <cstdint>

#define BB 2
#define TT 2048
#define CC 768
#define HH 12
#define HS 64
#define C3 2304
#define MTOT (BB*TT)          // 4096
#define PSZ (4096*384)        // u32 per plane for [M][768 cols] fp16x2 pairs
#define QSCALE 0.18033688011112042f   // 0.125 * log2(e)

// Scratch (allocation-free contract) — all planes are fp16x2-packed u32
__device__ uint32_t g_qkvp[5 * (size_t)PSZ];        // q_hi,q_lo,k,v_hi,v_lo
__device__ uint32_t g_vt[2 * (size_t)2048 * 768];   // V token-pair-major fp16 hi/lo
__device__ uint32_t g_xp[(size_t)PSZ];              // x single fp16 plane
__device__ uint32_t g_yp[(size_t)PSZ];              // y single fp16 plane
__device__ uint32_t g_wt[(size_t)CC * C3];          // W_attn^T fp16 hi/lo planes
__device__ uint32_t g_wt2[2 * (size_t)CC * CC / 2]; // W_proj^T fp16 hi/lo planes
// split-KV partials: [2 splits][24 bh][8 heavy blocks][128 rows][64 dims]
__device__ float g_po[(size_t)2 * 24 * 8 * 128 * 64];
__device__ float g_ml[(size_t)2 * 24 * 8 * 128 * 2];

// ---------------------------------------------------------------------------
// Helpers
// ---------------------------------------------------------------------------
__device__ __forceinline__ uint32_t smem_u32(const void* p) {
    uint32_t a;
    asm("{ .reg .u64 t; cvta.to.shared.u64 t, %1; cvt.u32.u64 %0, t; }"
        : "=r"(a) : "l"(p));
    return a;
}

__device__ __forceinline__ void mma_f16(float c[4],
    uint32_t a0, uint32_t a1, uint32_t a2, uint32_t a3,
    uint32_t b0, uint32_t b1)
{
    asm("mma.sync.aligned.m16n8k16.row.col.f32.f16.f16.f32 "
        "{%0,%1,%2,%3}, {%4,%5,%6,%7}, {%8,%9}, {%0,%1,%2,%3};"
        : "+f"(c[0]), "+f"(c[1]), "+f"(c[2]), "+f"(c[3])
        : "r"(a0), "r"(a1), "r"(a2), "r"(a3), "r"(b0), "r"(b1));
}

__device__ __forceinline__ void ldm_x4(uint32_t& r0, uint32_t& r1,
                                       uint32_t& r2, uint32_t& r3, uint32_t addr)
{
    asm volatile("ldmatrix.sync.aligned.m8n8.x4.shared.b16 {%0,%1,%2,%3}, [%4];"
        : "=r"(r0), "=r"(r1), "=r"(r2), "=r"(r3) : "r"(addr));
}

// fp32 pair -> fp16x2 (round)
__device__ __forceinline__ uint32_t cvtH(float x, float y)
{
    __half2 h = __floats2half2_rn(x, y);
    return *reinterpret_cast<uint32_t*>(&h);
}

// fp32 pair -> fp16x2 hi + fp16x2 lo (residual)
__device__ __forceinline__ void splitH(float x, float y, uint32_t& hi, uint32_t& lo)
{
    __half2 h = __floats2half2_rn(x, y);
    hi = *reinterpret_cast<uint32_t*>(&h);
    float hx = __low2float(h), hy = __high2float(h);
    __half2 l = __floats2half2_rn(x - hx, y - hy);
    lo = *reinterpret_cast<uint32_t*>(&l);
}

__device__ __forceinline__ uint32_t ex2_f16x2(uint32_t x) {
    uint32_t r;
    asm("ex2.approx.f16x2 %0, %1;" : "=r"(r) : "r"(x));
    return r;
}

__device__ __forceinline__ void cpasync16(uint32_t dst, const void* src) {
    asm volatile("cp.async.cg.shared.global [%0], [%1], 16;"
                 :: "r"(dst), "l"(src));
}
#define CP_COMMIT() asm volatile("cp.async.commit_group;" ::: "memory")
#define CP_WAIT1()  asm volatile("cp.async.wait_group 1;" ::: "memory")
#define CP_WAIT0()  asm volatile("cp.async.wait_group 0;" ::: "memory")

// ---------------------------------------------------------------------------
// Prep kernels
// ---------------------------------------------------------------------------
__global__ void split_x(const float* __restrict__ x, uint32_t* __restrict__ xh)
{
    int idx = blockIdx.x * 256 + threadIdx.x;
    int r = idx / 192, j2 = idx % 192;
    float4 v = *(const float4*)(x + (size_t)r * 768 + 4 * j2);
    *(uint2*)(xh + (size_t)r * 384 + 2 * j2) =
        make_uint2(cvtH(v.x, v.y), cvtH(v.z, v.w));
}

__global__ void transpose_splitH(const float* __restrict__ in,
                                 uint32_t* __restrict__ out_hi,
                                 uint32_t* __restrict__ out_lo,
                                 int K, int N)
{
    __shared__ float t[32][33];
    int n0 = blockIdx.x << 5, k0 = blockIdx.y << 5;
    int x = threadIdx.x, y = threadIdx.y;
    #pragma unroll
    for (int i = 0; i < 32; i += 8)
        t[y + i][x] = in[(size_t)(k0 + y + i) * N + n0 + x];
    __syncthreads();
    const int xp = x & 15, plane = x >> 4;
    #pragma unroll
    for (int i = 0; i < 32; i += 8) {
        int n = n0 + y + i;
        uint32_t h, l;
        splitH(t[2 * xp][y + i], t[2 * xp + 1][y + i], h, l);
        size_t o = (size_t)n * (K / 2) + k0 / 2 + xp;
        if (plane == 0) out_hi[o] = h;
        else            out_lo[o] = l;
    }
}

__global__ void pack_vt(const uint32_t* __restrict__ vh,
                        const uint32_t* __restrict__ vl,
                        uint32_t* __restrict__ vth, uint32_t* __restrict__ vtl)
{
    int idx = blockIdx.x * 256 + threadIdx.x;
    int bp = idx / 384, j = idx % 384;
    size_t s0 = (size_t)(2 * bp) * 384 + j;
    size_t s1 = s0 + 384;
    uint32_t ah = vh[s0], bh = vh[s1];
    uint32_t al = vl[s0], bl = vl[s1];
    size_t o = (size_t)bp * 768 + 2 * j;
    vth[o]     = __byte_perm(ah, bh, 0x5410);
    vth[o + 1] = __byte_perm(ah, bh, 0x7632);
    vtl[o]     = __byte_perm(al, bl, 0x5410);
    vtl[o + 1] = __byte_perm(al, bl, 0x7632);
}

// ---------------------------------------------------------------------------
// fp16 2-product GEMM, hi/lo passes reordered for independent accumulators.
// ---------------------------------------------------------------------------
__device__ __forceinline__ void gemm_issue(
    uint32_t st_u32,
    const uint32_t* Ah,
    const uint32_t* Bh, const uint32_t* Bl,
    int row0, int col0, int K2, int kp0, int tid)
{
    #pragma unroll
    for (int p = 0; p < 2; p++) {
        int idx = p * 256 + tid;
        int r = idx >> 2, c = idx & 3;
        uint32_t dst = st_u32 + (r * 20 + c * 4) * 4;
        cpasync16(dst, Ah + (size_t)(row0 + r) * K2 + kp0 + c * 4);
    }
    #pragma unroll
    for (int p = 0; p < 4; p++) {
        int idx = p * 256 + tid;
        const uint32_t* src = (idx < 512) ? Bh : Bl;
        int rem = idx & 511;
        int r = rem >> 2, c = rem & 3;
        uint32_t dst = st_u32 + ((2560 + ((idx < 512) ? 0 : 2560)) + r * 20 + c * 4) * 4;
        cpasync16(dst, src + (size_t)(col0 + r) * K2 + kp0 + c * 4);
    }
}

template <int MODE>
__global__ __launch_bounds__(256, 2) void gemm_planes(
    const uint32_t* __restrict__ Ah,
    const uint32_t* __restrict__ Bh, const uint32_t* __restrict__ Bl,
    const float* __restrict__ bias,
    float* __restrict__ outf,
    uint32_t* __restrict__ qkvp,
    int M, int N, int K)
{
    extern __shared__ uint32_t sm[];     // 2 stages x 7680 u32
    const uint32_t sm_u = smem_u32(sm);

    const int tid  = threadIdx.x;
    const int wid  = tid >> 5, lane = tid & 31;
    const int gid  = lane >> 2, tig = lane & 3;
    const int wm   = wid & 3;
    const int wn   = wid >> 2;
    const int row0 = blockIdx.y * 128;
    const int col0 = blockIdx.x * 128;
    const int K2   = K >> 1;
    const int NK   = K >> 5;

    const int lane7 = lane & 7;
    const int aRow  = wm * 32 + lane7 + ((lane >> 3) & 1) * 8;
    const int aColB = ((lane >> 4) & 1) * 16;
    const uint32_t aOff = (uint32_t)(aRow * 80) + aColB;
    const int bRow  = wn * 64 + lane7 + ((lane >> 4) & 1) * 8;
    const int bColB = ((lane >> 3) & 1) * 16;
    const uint32_t bOff = 2560 * 4 + (uint32_t)(bRow * 80) + bColB;

    float cf[2][8][4];
    #pragma unroll
    for (int ma = 0; ma < 2; ma++)
        #pragma unroll
        for (int na = 0; na < 8; na++)
            #pragma unroll
            for (int r = 0; r < 4; r++) cf[ma][na][r] = 0.f;

    gemm_issue(sm_u, Ah, Bh, Bl, row0, col0, K2, 0, tid);
    CP_COMMIT();

    for (int kt = 0; kt < NK; kt++) {
        const int s = kt & 1;
        if (kt + 1 < NK) {
            gemm_issue(sm_u + (s ^ 1) * 30720, Ah, Bh, Bl,
                       row0, col0, K2, (kt + 1) << 4, tid);
            CP_COMMIT();
            CP_WAIT1();
        } else {
            CP_WAIT0();
        }
        __syncthreads();

        const uint32_t stage = sm_u + s * 30720;

        #pragma unroll
        for (int ss = 0; ss < 2; ss++) {
            const uint32_t ssb = ss * 32;
            uint32_t a[2][4];
            #pragma unroll
            for (int ma = 0; ma < 2; ma++)
                ldm_x4(a[ma][0], a[ma][1], a[ma][2], a[ma][3],
                       stage + aOff + ma * 1280 + ssb);
            // process j in pairs: hi pass (8 independent accumulators), then lo
            #pragma unroll
            for (int jp = 0; jp < 2; jp++) {
                uint32_t bh[2][4], bl[2][4];
                #pragma unroll
                for (int jj = 0; jj < 2; jj++) {
                    const int j = 2 * jp + jj;
                    ldm_x4(bh[jj][0], bh[jj][1], bh[jj][2], bh[jj][3],
                           stage + bOff + j * 1280 + ssb);
                    ldm_x4(bl[jj][0], bl[jj][1], bl[jj][2], bl[jj][3],
                           stage + 2560 * 4 + bOff + j * 1280 + ssb);
                }
                // hi pass: all 8 target accumulators distinct
                #pragma unroll
                for (int jj = 0; jj < 2; jj++) {
                    const int j = 2 * jp + jj;
                    #pragma unroll
                    for (int ma = 0; ma < 2; ma++) {
                        mma_f16(cf[ma][2 * j],     a[ma][0], a[ma][1], a[ma][2], a[ma][3], bh[jj][0], bh[jj][1]);
                        mma_f16(cf[ma][2 * j + 1], a[ma][0], a[ma][1], a[ma][2], a[ma][3], bh[jj][2], bh[jj][3]);
                    }
                }
                // lo pass (same per-accumulator order: hi then lo -> bit-identical)
                #pragma unroll
                for (int jj = 0; jj < 2; jj++) {
                    const int j = 2 * jp + jj;
                    #pragma unroll
                    for (int ma = 0; ma < 2; ma++) {
                        mma_f16(cf[ma][2 * j],     a[ma][0], a[ma][1], a[ma][2], a[ma][3], bl[jj][0], bl[jj][1]);
                        mma_f16(cf[ma][2 * j + 1], a[ma][0], a[ma][1], a[ma][2], a[ma][3], bl[jj][2], bl[jj][3]);
                    }
                }
            }
        }
        __syncthreads();
    }

    if (MODE == 1) {
        #pragma unroll
        for (int ma = 0; ma < 2; ma++) {
            const int rg = row0 + wm * 32 + ma * 16 + gid;
            #pragma unroll
            for (int na = 0; na < 8; na++) {
                const int cg = col0 + wn * 64 + na * 8 + tig * 2;
                const float bx0 = bias[cg], bx1 = bias[cg + 1];
                *(float2*)(outf + (size_t)rg * N + cg) =
                    make_float2(cf[ma][na][0] + bx0, cf[ma][na][1] + bx1);
                *(float2*)(outf + (size_t)(rg + 8) * N + cg) =
                    make_float2(cf[ma][na][2] + bx0, cf[ma][na][3] + bx1);
            }
        }
    } else {
        const int which = col0 / 768;
        const int lc0 = col0 - which * 768;
        #pragma unroll
        for (int ma = 0; ma < 2; ma++) {
            const int rg = row0 + wm * 32 + ma * 16 + gid;
            #pragma unroll
            for (int na = 0; na < 8; na++) {
                const int gc = col0 + wn * 64 + na * 8 + tig * 2;
                const int pr = (lc0 >> 1) + wn * 32 + na * 4 + tig;
                const float bx0 = bias[gc], bx1 = bias[gc + 1];
                float v0 = cf[ma][na][0] + bx0, v1 = cf[ma][na][1] + bx1;
                float v2 = cf[ma][na][2] + bx0, v3 = cf[ma][na][3] + bx1;
                if (which == 0) {
                    uint32_t h, l;
                    splitH(v0 * QSCALE, v1 * QSCALE, h, l);
                    qkvp[(size_t)rg * 384 + pr] = h;
                    qkvp[(size_t)PSZ + (size_t)rg * 384 + pr] = l;
                    splitH(v2 * QSCALE, v3 * QSCALE, h, l);
                    qkvp[(size_t)(rg + 8) * 384 + pr] = h;
                    qkvp[(size_t)PSZ + (size_t)(rg + 8) * 384 + pr] = l;
                } else if (which == 1) {
                    qkvp[(size_t)2 * PSZ + (size_t)rg * 384 + pr] = cvtH(v0, v1);
                    qkvp[(size_t)2 * PSZ + (size_t)(rg + 8) * 384 + pr] = cvtH(v2, v3);
                } else {
                    uint32_t h, l;
                    splitH(v0, v1, h, l);
                    qkvp[(size_t)3 * PSZ + (size_t)rg * 384 + pr] = h;
                    qkvp[(size_t)4 * PSZ + (size_t)rg * 384 + pr] = l;
                    splitH(v2, v3, h, l);
                    qkvp[(size_t)3 * PSZ + (size_t)(rg + 8) * 384 + pr] = h;
                    qkvp[(size_t)4 * PSZ + (size_t)(rg + 8) * 384 + pr] = l;
                }
            }
        }
    }
}

// ---------------------------------------------------------------------------
// Flash attention: hi/lo passes reordered; split-KV balancing.
// ---------------------------------------------------------------------------
__device__ __forceinline__ void flash_issue(
    uint32_t st_u32,
    const uint32_t* kp,
    const uint32_t* vth, const uint32_t* vtl,
    int tok0, int vrow0, int h, int tid)
{
    #pragma unroll
    for (int p = 0; p < 2; p++) {
        int idx = p * 256 + tid;
        int r = idx >> 3, c = idx & 7;
        uint32_t dst = st_u32 + (r * 36 + c * 4) * 4;
        cpasync16(dst, kp + (size_t)(tok0 + r) * 384 + h * 32 + c * 4);
    }
    #pragma unroll
    for (int p = 0; p < 4; p++) {
        int idx = p * 256 + tid;
        const uint32_t* src = (idx < 512) ? vth : vtl;
        int rem = idx & 511;
        int r = rem >> 4, c = rem & 15;
        uint32_t dst = st_u32 + ((2304 + ((idx < 512) ? 0 : 2304)) + r * 72 + c * 4) * 4;
        cpasync16(dst, src + (size_t)(vrow0 + r) * 768 + h * 64 + c * 4);
    }
}

__global__ __launch_bounds__(256, 2) void flash_planes(
    const uint32_t* __restrict__ qkvp, const uint32_t* __restrict__ vt,
    uint32_t* __restrict__ yp,
    float* __restrict__ po, float* __restrict__ ml)
{
    extern __shared__ uint32_t sm[];       // 2 stages x 6912 u32
    const uint32_t sm_u = smem_u32(sm);

    const int tid = threadIdx.x;
    const int wid = tid >> 5, lane = tid & 31;
    const int gid = lane >> 2, tig = lane & 3;
    const int bh = blockIdx.x;
    const int u  = blockIdx.y;
    const int b  = bh / HH;
    const int h  = bh % HH;

    int bx, split, kt0, kt1;
    if (u < 16) {
        bx    = 8 + (u >> 1);
        split = u & 1;
        const int half = bx + 1;
        kt0 = split ? half : 0;
        kt1 = split ? (2 * bx + 2) : half;
    } else {
        bx = 23 - u;
        split = -1;
        kt0 = 0;
        kt1 = 2 * bx + 2;
    }
    const int q0 = bx * 128;

    const uint32_t* qph = qkvp;
    const uint32_t* qpl = qkvp + (size_t)PSZ;
    const uint32_t* kp  = qkvp + (size_t)2 * PSZ;
    const uint32_t* vth = vt;
    const uint32_t* vtl = vt + (size_t)2048 * 768;

    const int lane7 = lane & 7;
    const int kRow  = lane7 + ((lane >> 4) & 1) * 8;
    const int kColB = ((lane >> 3) & 1) * 16;
    const uint32_t kOff = (uint32_t)(kRow * 144) + kColB;

    const int grow0 = b * 2048 + q0 + wid * 16 + gid;
    uint32_t qh[4][4], ql[4][4];
    #pragma unroll
    for (int ks = 0; ks < 4; ks++) {
        const int pr = h * 32 + 8 * ks + tig;
        qh[ks][0] = qph[(size_t)grow0 * 384 + pr];
        qh[ks][1] = qph[(size_t)(grow0 + 8) * 384 + pr];
        qh[ks][2] = qph[(size_t)grow0 * 384 + pr + 4];
        qh[ks][3] = qph[(size_t)(grow0 + 8) * 384 + pr + 4];
        ql[ks][0] = qpl[(size_t)grow0 * 384 + pr];
        ql[ks][1] = qpl[(size_t)(grow0 + 8) * 384 + pr];
        ql[ks][2] = qpl[(size_t)grow0 * 384 + pr + 4];
        ql[ks][3] = qpl[(size_t)(grow0 + 8) * 384 + pr + 4];
    }

    float of[8][4];
    #pragma unroll
    for (int na = 0; na < 8; na++)
        #pragma unroll
        for (int r = 0; r < 4; r++) of[na][r] = 0.f;
    float m0 = -1e30f, m1 = -1e30f, l0 = 0.f, l1 = 0.f;
    const int r0g = q0 + wid * 16 + gid;
    const int r1g = r0g + 8;

    const int nloc = kt1 - kt0;
    flash_issue(sm_u, kp, vth, vtl,
                b * 2048 + kt0 * 64, b * 1024 + kt0 * 32, h, tid);
    CP_COMMIT();

    for (int ki = 0; ki < nloc; ki++) {
        const int kt = kt0 + ki;
        const int s = ki & 1;
        if (ki + 1 < nloc) {
            flash_issue(sm_u + (s ^ 1) * 27648, kp, vth, vtl,
                        b * 2048 + (kt + 1) * 64, b * 1024 + (kt + 1) * 32, h, tid);
            CP_COMMIT();
            CP_WAIT1();
        } else {
            CP_WAIT0();
        }
        __syncthreads();

        if (kt * 64 <= q0 + wid * 16 + 15) {
            const uint32_t stage = sm_u + s * 27648;
            const uint32_t* v_hi = sm + s * 6912 + 2304;
            const uint32_t* v_lo = v_hi + 2304;

            // ---- S(log2) = Qscaled @ K^T: qh pass then ql pass ----
            float sf[8][4];
            #pragma unroll
            for (int na = 0; na < 8; na++)
                #pragma unroll
                for (int r = 0; r < 4; r++) sf[na][r] = 0.f;

            #pragma unroll
            for (int ks = 0; ks < 4; ks++) {
                const uint32_t ksb = ks * 32;
                uint32_t bk[4][4];
                #pragma unroll
                for (int j = 0; j < 4; j++)
                    ldm_x4(bk[j][0], bk[j][1], bk[j][2], bk[j][3],
                           stage + kOff + j * 2304 + ksb);
                #pragma unroll
                for (int j = 0; j < 4; j++) {
                    mma_f16(sf[2 * j],     qh[ks][0], qh[ks][1], qh[ks][2], qh[ks][3], bk[j][0], bk[j][1]);
                    mma_f16(sf[2 * j + 1], qh[ks][0], qh[ks][1], qh[ks][2], qh[ks][3], bk[j][2], bk[j][3]);
                }
                #pragma unroll
                for (int j = 0; j < 4; j++) {
                    mma_f16(sf[2 * j],     ql[ks][0], ql[ks][1], ql[ks][2], ql[ks][3], bk[j][0], bk[j][1]);
                    mma_f16(sf[2 * j + 1], ql[ks][0], ql[ks][1], ql[ks][2], ql[ks][3], bk[j][2], bk[j][3]);
                }
            }

            // ---- causal mask ----
            const bool need_mask = (kt >= 2 * bx);
            if (need_mask) {
                #pragma unroll
                for (int na = 0; na < 8; na++) {
                    const int cg = kt * 64 + na * 8 + tig * 2;
                    if (cg     > r0g) sf[na][0] = -1e30f;
                    if (cg + 1 > r0g) sf[na][1] = -1e30f;
                    if (cg     > r1g) sf[na][2] = -1e30f;
                    if (cg + 1 > r1g) sf[na][3] = -1e30f;
                }
            }

            // ---- online softmax (log2 domain, fp16 exp2) ----
            float rm0 = -1e30f, rm1 = -1e30f;
            #pragma unroll
            for (int na = 0; na < 8; na++) {
                rm0 = fmaxf(rm0, fmaxf(sf[na][0], sf[na][1]));
                rm1 = fmaxf(rm1, fmaxf(sf[na][2], sf[na][3]));
            }
            rm0 = fmaxf(rm0, __shfl_xor_sync(0xffffffffu, rm0, 1));
            rm0 = fmaxf(rm0, __shfl_xor_sync(0xffffffffu, rm0, 2));
            rm1 = fmaxf(rm1, __shfl_xor_sync(0xffffffffu, rm1, 1));
            rm1 = fmaxf(rm1, __shfl_xor_sync(0xffffffffu, rm1, 2));
            const float mn0 = fmaxf(m0, rm0), mn1 = fmaxf(m1, rm1);
            const float c0 = exp2f(m0 - mn0), c1 = exp2f(m1 - mn1);
            float rs0 = 0.f, rs1 = 0.f;
            uint32_t p01[8], p23[8];
            #pragma unroll
            for (int na = 0; na < 8; na++) {
                __half2 h01 = __floats2half2_rn(sf[na][0] - mn0, sf[na][1] - mn0);
                __half2 h23 = __floats2half2_rn(sf[na][2] - mn1, sf[na][3] - mn1);
                p01[na] = ex2_f16x2(*reinterpret_cast<uint32_t*>(&h01));
                p23[na] = ex2_f16x2(*reinterpret_cast<uint32_t*>(&h23));
                float2 f01 = __half22float2(*reinterpret_cast<__half2*>(&p01[na]));
                float2 f23 = __half22float2(*reinterpret_cast<__half2*>(&p23[na]));
                rs0 += f01.x + f01.y;
                rs1 += f23.x + f23.y;
            }
            rs0 += __shfl_xor_sync(0xffffffffu, rs0, 1);
            rs0 += __shfl_xor_sync(0xffffffffu, rs0, 2);
            rs1 += __shfl_xor_sync(0xffffffffu, rs1, 1);
            rs1 += __shfl_xor_sync(0xffffffffu, rs1, 2);
            l0 = l0 * c0 + rs0; m0 = mn0;
            l1 = l1 * c1 + rs1; m1 = mn1;
            #pragma unroll
            for (int na = 0; na < 8; na++) {
                of[na][0] *= c0; of[na][1] *= c0;
                of[na][2] *= c1; of[na][3] *= c1;
            }

            // ---- O += P @ V: hi pass over 8 na, then lo pass ----
            #pragma unroll
            for (int ks = 0; ks < 4; ks++) {
                const uint32_t pa0 = p01[2 * ks],     pa1 = p23[2 * ks];
                const uint32_t pa2 = p01[2 * ks + 1], pa3 = p23[2 * ks + 1];
                #pragma unroll
                for (int na = 0; na < 8; na++) {
                    const int d = na * 8 + gid;
                    mma_f16(of[na], pa0, pa1, pa2, pa3,
                            v_hi[(8 * ks + tig) * 72 + d], v_hi[(8 * ks + tig + 4) * 72 + d]);
                }
                #pragma unroll
                for (int na = 0; na < 8; na++) {
                    const int d = na * 8 + gid;
                    mma_f16(of[na], pa0, pa1, pa2, pa3,
                            v_lo[(8 * ks + tig) * 72 + d], v_lo[(8 * ks + tig + 4) * 72 + d]);
                }
            }
        }
        __syncthreads();
    }

    if (split < 0) {
        const float i0 = 1.f / l0, i1 = 1.f / l1;
        const int gr0 = b * 2048 + r0g;
        #pragma unroll
        for (int na = 0; na < 8; na++) {
            const int pr = h * 32 + na * 4 + tig;
            yp[(size_t)gr0 * 384 + pr] = cvtH(of[na][0] * i0, of[na][1] * i0);
            yp[(size_t)(gr0 + 8) * 384 + pr] = cvtH(of[na][2] * i1, of[na][3] * i1);
        }
    } else {
        const int hb = bx - 8;
        const int r0 = wid * 16 + gid;
        float* pob = po + ((((size_t)split * 24 + bh) * 8 + hb) * 128) * 64;
        #pragma unroll
        for (int na = 0; na < 8; na++) {
            *(float2*)(pob + (size_t)r0 * 64 + na * 8 + 2 * tig) =
                make_float2(of[na][0], of[na][1]);
            *(float2*)(pob + (size_t)(r0 + 8) * 64 + na * 8 + 2 * tig) =
                make_float2(of[na][2], of[na][3]);
        }
        if (tig == 0) {
            float* mlb = ml + ((((size_t)split * 24 + bh) * 8 + hb) * 128) * 2;
            mlb[r0 * 2]           = m0;
            mlb[r0 * 2 + 1]       = l0;
            mlb[(r0 + 8) * 2]     = m1;
            mlb[(r0 + 8) * 2 + 1] = l1;
        }
    }
}

// ---------------------------------------------------------------------------
// Merge split-KV partials into y plane (heavy q-blocks only).
// ---------------------------------------------------------------------------
__global__ void merge_heavy(const float* __restrict__ po,
                            const float* __restrict__ ml,
                            uint32_t* __restrict__ yp)
{
    int idx = blockIdx.x * 256 + threadIdx.x;
    int d4 = idx & 15;
    int r  = (idx >> 4) & 127;
    int hb = (idx >> 11) & 7;
    int bh = idx >> 14;
    int b = bh / HH, h = bh % HH;

    size_t rowA = (((size_t)0 * 24 + bh) * 8 + hb) * 128 + r;
    size_t rowB = (((size_t)1 * 24 + bh) * 8 + hb) * 128 + r;
    float mA = ml[rowA * 2], lA = ml[rowA * 2 + 1];
    float mB = ml[rowB * 2], lB = ml[rowB * 2 + 1];
    float m = fmaxf(mA, mB);
    float sA = exp2f(mA - m), sB = exp2f(mB - m);
    float inv = 1.f / (lA * sA + lB * sB);

    float4 oA = *(const float4*)(po + rowA * 64 + 4 * d4);
    float4 oB = *(const float4*)(po + rowB * 64 + 4 * d4);
    float v0 = (oA.x * sA + oB.x * sB) * inv;
    float v1 = (oA.y * sA + oB.y * sB) * inv;
    float v2 = (oA.z * sA + oB.z * sB) * inv;
    float v3 = (oA.w * sA + oB.w * sB) * inv;

    int grow = b * 2048 + (8 + hb) * 128 + r;
    int pr = h * 32 + 2 * d4;
    yp[(size_t)grow * 384 + pr]     = cvtH(v0, v1);
    yp[(size_t)grow * 384 + pr + 1] = cvtH(v2, v3);
}

extern "C" void kernel_launch(void* const* d_in, const int* in_sizes, int n_in,
                              void* d_out, int out_size)
{
    const float* x      = (const float*)d_in[0];
    const float* W_attn = (const float*)d_in[1];
    const float* b_attn = (const float*)d_in[2];
    const float* W_proj = (const float*)d_in[3];
    const float* b_proj = (const float*)d_in[4];
    float* out = (float*)d_out;

    uint32_t *qkvp, *vt, *xp, *yp, *wt, *wt2;
    float *po, *mlb;
    cudaGetSymbolAddress((void**)&qkvp, g_qkvp);
    cudaGetSymbolAddress((void**)&vt, g_vt);
    cudaGetSymbolAddress((void**)&xp, g_xp);
    cudaGetSymbolAddress((void**)&yp, g_yp);
    cudaGetSymbolAddress((void**)&wt, g_wt);
    cudaGetSymbolAddress((void**)&wt2, g_wt2);
    cudaGetSymbolAddress((void**)&po, g_po);
    cudaGetSymbolAddress((void**)&mlb, g_ml);

    const int GEMM_SMEM  = 2 * 7680 * 4;    // 61440
    const int FLASH_SMEM = 2 * 6912 * 4;    // 55296
    cudaFuncSetAttribute(gemm_planes<0>,
                         cudaFuncAttributeMaxDynamicSharedMemorySize, GEMM_SMEM);
    cudaFuncSetAttribute(gemm_planes<1>,
                         cudaFuncAttributeMaxDynamicSharedMemorySize, GEMM_SMEM);
    cudaFuncSetAttribute(flash_planes,
                         cudaFuncAttributeMaxDynamicSharedMemorySize, FLASH_SMEM);

    split_x<<<786432 / 256, 256>>>(x, xp);                                 // 0
    transpose_splitH<<<dim3(C3 / 32, CC / 32), dim3(32, 8)>>>(             // 1
        W_attn, wt, wt + (size_t)C3 * CC / 2, CC, C3);
    transpose_splitH<<<dim3(CC / 32, CC / 32), dim3(32, 8)>>>(             // 2
        W_proj, wt2, wt2 + (size_t)CC * CC / 2, CC, CC);

    gemm_planes<0><<<dim3(C3 / 128, MTOT / 128), 256, GEMM_SMEM>>>(        // 3
        xp, wt, wt + (size_t)C3 * CC / 2, b_attn,
        nullptr, qkvp, MTOT, C3, CC);

    pack_vt<<<(2048 * 384) / 256, 256>>>(                                  // 4
        qkvp + (size_t)3 * PSZ, qkvp + (size_t)4 * PSZ, vt, vt + (size_t)2048 * 768);

    flash_planes<<<dim3(24, 24), 256, FLASH_SMEM>>>(                       // 5
        qkvp, vt, yp, po, mlb);

    merge_heavy<<<393216 / 256, 256>>>(po, mlb, yp);                       // 6

    gemm_planes<1><<<dim3(CC / 128, MTOT / 128), 256, GEMM_SMEM>>>(        // 7
        yp, wt2, wt2 + (size_t)CC * CC / 2, b_proj,
        out, nullptr, MTOT, CC, CC);
}

// round 14
// speedup vs baseline: 5.7413x; 1.4075x over previous
#include <cuda_runtime.h>
#include <cuda_bf16.h>
#include <cuda_fp16.h>
#include <math.h>
#include <cstdint>

#define BB 2
#define TT 2048
#define CC 768
#define HH 12
#define HS 64
#define C3 2304
#define MTOT (BB*TT)          // 4096
#define PSZ (4096*384)        // u32 per plane for [M][768 cols] fp16x2 pairs
#define QSCALE 0.18033688011112042f   // 0.125 * log2(e)

// Scratch (allocation-free contract) — all planes are fp16x2-packed u32
__device__ uint32_t g_qkvp[4 * (size_t)PSZ];        // q_hi, q_lo, k, v
__device__ uint32_t g_vt[(size_t)2048 * 768];       // V token-pair-major (single fp16)
__device__ uint32_t g_xp[(size_t)PSZ];              // x single fp16 plane
__device__ uint32_t g_yp[(size_t)PSZ];              // y single fp16 plane
__device__ uint32_t g_wt[(size_t)C3 * CC / 2];      // W_attn^T single fp16 plane
__device__ uint32_t g_wt2[(size_t)CC * CC / 2];     // W_proj^T single fp16 plane
// split-KV partials: [2 splits][24 bh][8 heavy blocks][128 rows][64 dims]
__device__ float g_po[(size_t)2 * 24 * 8 * 128 * 64];
__device__ float g_ml[(size_t)2 * 24 * 8 * 128 * 2];

// ---------------------------------------------------------------------------
// Helpers
// ---------------------------------------------------------------------------
__device__ __forceinline__ uint32_t smem_u32(const void* p) {
    uint32_t a;
    asm("{ .reg .u64 t; cvta.to.shared.u64 t, %1; cvt.u32.u64 %0, t; }"
        : "=r"(a) : "l"(p));
    return a;
}

__device__ __forceinline__ void mma_f16(float c[4],
    uint32_t a0, uint32_t a1, uint32_t a2, uint32_t a3,
    uint32_t b0, uint32_t b1)
{
    asm("mma.sync.aligned.m16n8k16.row.col.f32.f16.f16.f32 "
        "{%0,%1,%2,%3}, {%4,%5,%6,%7}, {%8,%9}, {%0,%1,%2,%3};"
        : "+f"(c[0]), "+f"(c[1]), "+f"(c[2]), "+f"(c[3])
        : "r"(a0), "r"(a1), "r"(a2), "r"(a3), "r"(b0), "r"(b1));
}

__device__ __forceinline__ void ldm_x4(uint32_t& r0, uint32_t& r1,
                                       uint32_t& r2, uint32_t& r3, uint32_t addr)
{
    asm volatile("ldmatrix.sync.aligned.m8n8.x4.shared.b16 {%0,%1,%2,%3}, [%4];"
        : "=r"(r0), "=r"(r1), "=r"(r2), "=r"(r3) : "r"(addr));
}

__device__ __forceinline__ uint32_t cvtH(float x, float y)
{
    __half2 h = __floats2half2_rn(x, y);
    return *reinterpret_cast<uint32_t*>(&h);
}

__device__ __forceinline__ void splitH(float x, float y, uint32_t& hi, uint32_t& lo)
{
    __half2 h = __floats2half2_rn(x, y);
    hi = *reinterpret_cast<uint32_t*>(&h);
    float hx = __low2float(h), hy = __high2float(h);
    __half2 l = __floats2half2_rn(x - hx, y - hy);
    lo = *reinterpret_cast<uint32_t*>(&l);
}

__device__ __forceinline__ uint32_t ex2_f16x2(uint32_t x) {
    uint32_t r;
    asm("ex2.approx.f16x2 %0, %1;" : "=r"(r) : "r"(x));
    return r;
}

__device__ __forceinline__ void cpasync16(uint32_t dst, const void* src) {
    asm volatile("cp.async.cg.shared.global [%0], [%1], 16;"
                 :: "r"(dst), "l"(src));
}
#define CP_COMMIT() asm volatile("cp.async.commit_group;" ::: "memory")
#define CP_WAIT1()  asm volatile("cp.async.wait_group 1;" ::: "memory")
#define CP_WAIT0()  asm volatile("cp.async.wait_group 0;" ::: "memory")

// ---------------------------------------------------------------------------
// Prep kernels
// ---------------------------------------------------------------------------
__global__ void split_x(const float* __restrict__ x, uint32_t* __restrict__ xh)
{
    int idx = blockIdx.x * 256 + threadIdx.x;
    int r = idx / 192, j2 = idx % 192;
    float4 v = *(const float4*)(x + (size_t)r * 768 + 4 * j2);
    *(uint2*)(xh + (size_t)r * 384 + 2 * j2) =
        make_uint2(cvtH(v.x, v.y), cvtH(v.z, v.w));
}

// W [K][N] fp32 -> transposed single fp16 pair plane [N][K/2]
__global__ void transpose_cvtH(const float* __restrict__ in,
                               uint32_t* __restrict__ outp,
                               int K, int N)
{
    __shared__ float t[32][33];
    int n0 = blockIdx.x << 5, k0 = blockIdx.y << 5;
    int x = threadIdx.x, y = threadIdx.y;
    #pragma unroll
    for (int i = 0; i < 32; i += 8)
        t[y + i][x] = in[(size_t)(k0 + y + i) * N + n0 + x];
    __syncthreads();
    if (x < 16) {
        #pragma unroll
        for (int i = 0; i < 32; i += 8) {
            int n = n0 + y + i;
            outp[(size_t)n * (K / 2) + k0 / 2 + x] =
                cvtH(t[2 * x][y + i], t[2 * x + 1][y + i]);
        }
    }
}

// V fp16 dim-pair plane -> token-pair-major plane (pure permute)
__global__ void pack_vt(const uint32_t* __restrict__ vp,
                        uint32_t* __restrict__ vtp)
{
    int idx = blockIdx.x * 256 + threadIdx.x;
    int bp = idx / 384, j = idx % 384;
    size_t s0 = (size_t)(2 * bp) * 384 + j;
    uint32_t a = vp[s0], b = vp[s0 + 384];
    size_t o = (size_t)bp * 768 + 2 * j;
    vtp[o]     = __byte_perm(a, b, 0x5410);
    vtp[o + 1] = __byte_perm(a, b, 0x7632);
}

// ---------------------------------------------------------------------------
// fp16 single-product GEMM: out = A(fp16) @ W(fp16)^T + bias.
// CTA 128x128, BK=32 floats, 8 warps 4(m)x2(n), cp.async 2-stage.
// Stage layout (u32): A@0 [128][20], B@2560 [128][20]. Stage = 5120 u32.
// ---------------------------------------------------------------------------
__device__ __forceinline__ void gemm_issue(
    uint32_t st_u32,
    const uint32_t* Ah, const uint32_t* Bp,
    int row0, int col0, int K2, int kp0, int tid)
{
    #pragma unroll
    for (int p = 0; p < 2; p++) {
        int idx = p * 256 + tid;
        int r = idx >> 2, c = idx & 3;
        uint32_t dst = st_u32 + (r * 20 + c * 4) * 4;
        cpasync16(dst, Ah + (size_t)(row0 + r) * K2 + kp0 + c * 4);
    }
    #pragma unroll
    for (int p = 0; p < 2; p++) {
        int idx = p * 256 + tid;
        int r = idx >> 2, c = idx & 3;
        uint32_t dst = st_u32 + ((2560 + r * 20 + c * 4)) * 4;
        cpasync16(dst, Bp + (size_t)(col0 + r) * K2 + kp0 + c * 4);
    }
}

template <int MODE>
__global__ __launch_bounds__(256, 2) void gemm_planes(
    const uint32_t* __restrict__ Ah, const uint32_t* __restrict__ Bp,
    const float* __restrict__ bias,
    float* __restrict__ outf,
    uint32_t* __restrict__ qkvp,
    int M, int N, int K)
{
    extern __shared__ uint32_t sm[];     // 2 stages x 5120 u32
    const uint32_t sm_u = smem_u32(sm);

    const int tid  = threadIdx.x;
    const int wid  = tid >> 5, lane = tid & 31;
    const int gid  = lane >> 2, tig = lane & 3;
    const int wm   = wid & 3;
    const int wn   = wid >> 2;
    const int row0 = blockIdx.y * 128;
    const int col0 = blockIdx.x * 128;
    const int K2   = K >> 1;
    const int NK   = K >> 5;

    const int lane7 = lane & 7;
    const int aRow  = wm * 32 + lane7 + ((lane >> 3) & 1) * 8;
    const int aColB = ((lane >> 4) & 1) * 16;
    const uint32_t aOff = (uint32_t)(aRow * 80) + aColB;
    const int bRow  = wn * 64 + lane7 + ((lane >> 4) & 1) * 8;
    const int bColB = ((lane >> 3) & 1) * 16;
    const uint32_t bOff = 2560 * 4 + (uint32_t)(bRow * 80) + bColB;

    float cf[2][8][4];
    #pragma unroll
    for (int ma = 0; ma < 2; ma++)
        #pragma unroll
        for (int na = 0; na < 8; na++)
            #pragma unroll
            for (int r = 0; r < 4; r++) cf[ma][na][r] = 0.f;

    gemm_issue(sm_u, Ah, Bp, row0, col0, K2, 0, tid);
    CP_COMMIT();

    for (int kt = 0; kt < NK; kt++) {
        const int s = kt & 1;
        if (kt + 1 < NK) {
            gemm_issue(sm_u + (s ^ 1) * 20480, Ah, Bp,
                       row0, col0, K2, (kt + 1) << 4, tid);
            CP_COMMIT();
            CP_WAIT1();
        } else {
            CP_WAIT0();
        }
        __syncthreads();

        const uint32_t stage = sm_u + s * 20480;

        #pragma unroll
        for (int ss = 0; ss < 2; ss++) {
            const uint32_t ssb = ss * 32;
            uint32_t a[2][4];
            #pragma unroll
            for (int ma = 0; ma < 2; ma++)
                ldm_x4(a[ma][0], a[ma][1], a[ma][2], a[ma][3],
                       stage + aOff + ma * 1280 + ssb);
            #pragma unroll
            for (int j = 0; j < 4; j++) {
                uint32_t b0, b1, b2, b3;
                ldm_x4(b0, b1, b2, b3, stage + bOff + j * 1280 + ssb);
                #pragma unroll
                for (int ma = 0; ma < 2; ma++) {
                    mma_f16(cf[ma][2 * j],     a[ma][0], a[ma][1], a[ma][2], a[ma][3], b0, b1);
                    mma_f16(cf[ma][2 * j + 1], a[ma][0], a[ma][1], a[ma][2], a[ma][3], b2, b3);
                }
            }
        }
        __syncthreads();
    }

    if (MODE == 1) {
        #pragma unroll
        for (int ma = 0; ma < 2; ma++) {
            const int rg = row0 + wm * 32 + ma * 16 + gid;
            #pragma unroll
            for (int na = 0; na < 8; na++) {
                const int cg = col0 + wn * 64 + na * 8 + tig * 2;
                const float bx0 = bias[cg], bx1 = bias[cg + 1];
                *(float2*)(outf + (size_t)rg * N + cg) =
                    make_float2(cf[ma][na][0] + bx0, cf[ma][na][1] + bx1);
                *(float2*)(outf + (size_t)(rg + 8) * N + cg) =
                    make_float2(cf[ma][na][2] + bx0, cf[ma][na][3] + bx1);
            }
        }
    } else {
        // scatter: Q (fp16 hi/lo, pre-scaled), K (single fp16), V (single fp16)
        const int which = col0 / 768;
        const int lc0 = col0 - which * 768;
        #pragma unroll
        for (int ma = 0; ma < 2; ma++) {
            const int rg = row0 + wm * 32 + ma * 16 + gid;
            #pragma unroll
            for (int na = 0; na < 8; na++) {
                const int gc = col0 + wn * 64 + na * 8 + tig * 2;
                const int pr = (lc0 >> 1) + wn * 32 + na * 4 + tig;
                const float bx0 = bias[gc], bx1 = bias[gc + 1];
                float v0 = cf[ma][na][0] + bx0, v1 = cf[ma][na][1] + bx1;
                float v2 = cf[ma][na][2] + bx0, v3 = cf[ma][na][3] + bx1;
                if (which == 0) {
                    uint32_t h, l;
                    splitH(v0 * QSCALE, v1 * QSCALE, h, l);
                    qkvp[(size_t)rg * 384 + pr] = h;
                    qkvp[(size_t)PSZ + (size_t)rg * 384 + pr] = l;
                    splitH(v2 * QSCALE, v3 * QSCALE, h, l);
                    qkvp[(size_t)(rg + 8) * 384 + pr] = h;
                    qkvp[(size_t)PSZ + (size_t)(rg + 8) * 384 + pr] = l;
                } else if (which == 1) {
                    qkvp[(size_t)2 * PSZ + (size_t)rg * 384 + pr] = cvtH(v0, v1);
                    qkvp[(size_t)2 * PSZ + (size_t)(rg + 8) * 384 + pr] = cvtH(v2, v3);
                } else {
                    qkvp[(size_t)3 * PSZ + (size_t)rg * 384 + pr] = cvtH(v0, v1);
                    qkvp[(size_t)3 * PSZ + (size_t)(rg + 8) * 384 + pr] = cvtH(v2, v3);
                }
            }
        }
    }
}

// ---------------------------------------------------------------------------
// Flash attention: 2-product QK (Q hi/lo), single-product PV, split-KV.
// Stage layout (u32): K@0 [64][36], V@2304 [32][72]. Stage = 4608 u32.
// ---------------------------------------------------------------------------
__device__ __forceinline__ void flash_issue(
    uint32_t st_u32,
    const uint32_t* kp, const uint32_t* vtp,
    int tok0, int vrow0, int h, int tid)
{
    #pragma unroll
    for (int p = 0; p < 2; p++) {
        int idx = p * 256 + tid;
        int r = idx >> 3, c = idx & 7;
        uint32_t dst = st_u32 + (r * 36 + c * 4) * 4;
        cpasync16(dst, kp + (size_t)(tok0 + r) * 384 + h * 32 + c * 4);
    }
    #pragma unroll
    for (int p = 0; p < 2; p++) {
        int idx = p * 256 + tid;
        int r = idx >> 4, c = idx & 15;
        uint32_t dst = st_u32 + ((2304 + r * 72 + c * 4)) * 4;
        cpasync16(dst, vtp + (size_t)(vrow0 + r) * 768 + h * 64 + c * 4);
    }
}

__global__ __launch_bounds__(256, 2) void flash_planes(
    const uint32_t* __restrict__ qkvp, const uint32_t* __restrict__ vt,
    uint32_t* __restrict__ yp,
    float* __restrict__ po, float* __restrict__ ml)
{
    extern __shared__ uint32_t sm[];       // 2 stages x 4608 u32
    const uint32_t sm_u = smem_u32(sm);

    const int tid = threadIdx.x;
    const int wid = tid >> 5, lane = tid & 31;
    const int gid = lane >> 2, tig = lane & 3;
    const int bh = blockIdx.x;
    const int u  = blockIdx.y;
    const int b  = bh / HH;
    const int h  = bh % HH;

    int bx, split, kt0, kt1;
    if (u < 16) {
        bx    = 8 + (u >> 1);
        split = u & 1;
        const int half = bx + 1;
        kt0 = split ? half : 0;
        kt1 = split ? (2 * bx + 2) : half;
    } else {
        bx = 23 - u;
        split = -1;
        kt0 = 0;
        kt1 = 2 * bx + 2;
    }
    const int q0 = bx * 128;

    const uint32_t* qph = qkvp;
    const uint32_t* qpl = qkvp + (size_t)PSZ;
    const uint32_t* kp  = qkvp + (size_t)2 * PSZ;

    const int lane7 = lane & 7;
    const int kRow  = lane7 + ((lane >> 4) & 1) * 8;
    const int kColB = ((lane >> 3) & 1) * 16;
    const uint32_t kOff = (uint32_t)(kRow * 144) + kColB;

    const int grow0 = b * 2048 + q0 + wid * 16 + gid;
    uint32_t qh[4][4], ql[4][4];
    #pragma unroll
    for (int ks = 0; ks < 4; ks++) {
        const int pr = h * 32 + 8 * ks + tig;
        qh[ks][0] = qph[(size_t)grow0 * 384 + pr];
        qh[ks][1] = qph[(size_t)(grow0 + 8) * 384 + pr];
        qh[ks][2] = qph[(size_t)grow0 * 384 + pr + 4];
        qh[ks][3] = qph[(size_t)(grow0 + 8) * 384 + pr + 4];
        ql[ks][0] = qpl[(size_t)grow0 * 384 + pr];
        ql[ks][1] = qpl[(size_t)(grow0 + 8) * 384 + pr];
        ql[ks][2] = qpl[(size_t)grow0 * 384 + pr + 4];
        ql[ks][3] = qpl[(size_t)(grow0 + 8) * 384 + pr + 4];
    }

    float of[8][4];
    #pragma unroll
    for (int na = 0; na < 8; na++)
        #pragma unroll
        for (int r = 0; r < 4; r++) of[na][r] = 0.f;
    float m0 = -1e30f, m1 = -1e30f, l0 = 0.f, l1 = 0.f;
    const int r0g = q0 + wid * 16 + gid;
    const int r1g = r0g + 8;

    const int nloc = kt1 - kt0;
    flash_issue(sm_u, kp, vt,
                b * 2048 + kt0 * 64, b * 1024 + kt0 * 32, h, tid);
    CP_COMMIT();

    for (int ki = 0; ki < nloc; ki++) {
        const int kt = kt0 + ki;
        const int s = ki & 1;
        if (ki + 1 < nloc) {
            flash_issue(sm_u + (s ^ 1) * 18432, kp, vt,
                        b * 2048 + (kt + 1) * 64, b * 1024 + (kt + 1) * 32, h, tid);
            CP_COMMIT();
            CP_WAIT1();
        } else {
            CP_WAIT0();
        }
        __syncthreads();

        if (kt * 64 <= q0 + wid * 16 + 15) {
            const uint32_t stage = sm_u + s * 18432;
            const uint32_t* v_sh = sm + s * 4608 + 2304;

            // ---- S(log2) = Qscaled @ K^T (Q hi/lo, K single) ----
            float sf[8][4];
            #pragma unroll
            for (int na = 0; na < 8; na++)
                #pragma unroll
                for (int r = 0; r < 4; r++) sf[na][r] = 0.f;

            #pragma unroll
            for (int ks = 0; ks < 4; ks++) {
                const uint32_t ksb = ks * 32;
                #pragma unroll
                for (int j = 0; j < 4; j++) {
                    uint32_t b0, b1, b2, b3;
                    ldm_x4(b0, b1, b2, b3, stage + kOff + j * 2304 + ksb);
                    mma_f16(sf[2 * j],     qh[ks][0], qh[ks][1], qh[ks][2], qh[ks][3], b0, b1);
                    mma_f16(sf[2 * j],     ql[ks][0], ql[ks][1], ql[ks][2], ql[ks][3], b0, b1);
                    mma_f16(sf[2 * j + 1], qh[ks][0], qh[ks][1], qh[ks][2], qh[ks][3], b2, b3);
                    mma_f16(sf[2 * j + 1], ql[ks][0], ql[ks][1], ql[ks][2], ql[ks][3], b2, b3);
                }
            }

            // ---- causal mask ----
            const bool need_mask = (kt >= 2 * bx);
            if (need_mask) {
                #pragma unroll
                for (int na = 0; na < 8; na++) {
                    const int cg = kt * 64 + na * 8 + tig * 2;
                    if (cg     > r0g) sf[na][0] = -1e30f;
                    if (cg + 1 > r0g) sf[na][1] = -1e30f;
                    if (cg     > r1g) sf[na][2] = -1e30f;
                    if (cg + 1 > r1g) sf[na][3] = -1e30f;
                }
            }

            // ---- online softmax (log2 domain, fp16 exp2) ----
            float rm0 = -1e30f, rm1 = -1e30f;
            #pragma unroll
            for (int na = 0; na < 8; na++) {
                rm0 = fmaxf(rm0, fmaxf(sf[na][0], sf[na][1]));
                rm1 = fmaxf(rm1, fmaxf(sf[na][2], sf[na][3]));
            }
            rm0 = fmaxf(rm0, __shfl_xor_sync(0xffffffffu, rm0, 1));
            rm0 = fmaxf(rm0, __shfl_xor_sync(0xffffffffu, rm0, 2));
            rm1 = fmaxf(rm1, __shfl_xor_sync(0xffffffffu, rm1, 1));
            rm1 = fmaxf(rm1, __shfl_xor_sync(0xffffffffu, rm1, 2));
            const float mn0 = fmaxf(m0, rm0), mn1 = fmaxf(m1, rm1);
            const float c0 = exp2f(m0 - mn0), c1 = exp2f(m1 - mn1);
            float rs0 = 0.f, rs1 = 0.f;
            uint32_t p01[8], p23[8];
            #pragma unroll
            for (int na = 0; na < 8; na++) {
                __half2 h01 = __floats2half2_rn(sf[na][0] - mn0, sf[na][1] - mn0);
                __half2 h23 = __floats2half2_rn(sf[na][2] - mn1, sf[na][3] - mn1);
                p01[na] = ex2_f16x2(*reinterpret_cast<uint32_t*>(&h01));
                p23[na] = ex2_f16x2(*reinterpret_cast<uint32_t*>(&h23));
                float2 f01 = __half22float2(*reinterpret_cast<__half2*>(&p01[na]));
                float2 f23 = __half22float2(*reinterpret_cast<__half2*>(&p23[na]));
                rs0 += f01.x + f01.y;
                rs1 += f23.x + f23.y;
            }
            rs0 += __shfl_xor_sync(0xffffffffu, rs0, 1);
            rs0 += __shfl_xor_sync(0xffffffffu, rs0, 2);
            rs1 += __shfl_xor_sync(0xffffffffu, rs1, 1);
            rs1 += __shfl_xor_sync(0xffffffffu, rs1, 2);
            l0 = l0 * c0 + rs0; m0 = mn0;
            l1 = l1 * c1 + rs1; m1 = mn1;
            #pragma unroll
            for (int na = 0; na < 8; na++) {
                of[na][0] *= c0; of[na][1] *= c0;
                of[na][2] *= c1; of[na][3] *= c1;
            }

            // ---- O += P @ V (single fp16 V) ----
            #pragma unroll
            for (int ks = 0; ks < 4; ks++) {
                const uint32_t pa0 = p01[2 * ks],     pa1 = p23[2 * ks];
                const uint32_t pa2 = p01[2 * ks + 1], pa3 = p23[2 * ks + 1];
                #pragma unroll
                for (int na = 0; na < 8; na++) {
                    const int d = na * 8 + gid;
                    mma_f16(of[na], pa0, pa1, pa2, pa3,
                            v_sh[(8 * ks + tig) * 72 + d],
                            v_sh[(8 * ks + tig + 4) * 72 + d]);
                }
            }
        }
        __syncthreads();
    }

    if (split < 0) {
        const float i0 = 1.f / l0, i1 = 1.f / l1;
        const int gr0 = b * 2048 + r0g;
        #pragma unroll
        for (int na = 0; na < 8; na++) {
            const int pr = h * 32 + na * 4 + tig;
            yp[(size_t)gr0 * 384 + pr] = cvtH(of[na][0] * i0, of[na][1] * i0);
            yp[(size_t)(gr0 + 8) * 384 + pr] = cvtH(of[na][2] * i1, of[na][3] * i1);
        }
    } else {
        const int hb = bx - 8;
        const int r0 = wid * 16 + gid;
        float* pob = po + ((((size_t)split * 24 + bh) * 8 + hb) * 128) * 64;
        #pragma unroll
        for (int na = 0; na < 8; na++) {
            *(float2*)(pob + (size_t)r0 * 64 + na * 8 + 2 * tig) =
                make_float2(of[na][0], of[na][1]);
            *(float2*)(pob + (size_t)(r0 + 8) * 64 + na * 8 + 2 * tig) =
                make_float2(of[na][2], of[na][3]);
        }
        if (tig == 0) {
            float* mlb = ml + ((((size_t)split * 24 + bh) * 8 + hb) * 128) * 2;
            mlb[r0 * 2]           = m0;
            mlb[r0 * 2 + 1]       = l0;
            mlb[(r0 + 8) * 2]     = m1;
            mlb[(r0 + 8) * 2 + 1] = l1;
        }
    }
}

// ---------------------------------------------------------------------------
// Merge split-KV partials into y plane (heavy q-blocks only).
// ---------------------------------------------------------------------------
__global__ void merge_heavy(const float* __restrict__ po,
                            const float* __restrict__ ml,
                            uint32_t* __restrict__ yp)
{
    int idx = blockIdx.x * 256 + threadIdx.x;
    int d4 = idx & 15;
    int r  = (idx >> 4) & 127;
    int hb = (idx >> 11) & 7;
    int bh = idx >> 14;
    int b = bh / HH, h = bh % HH;

    size_t rowA = (((size_t)0 * 24 + bh) * 8 + hb) * 128 + r;
    size_t rowB = (((size_t)1 * 24 + bh) * 8 + hb) * 128 + r;
    float mA = ml[rowA * 2], lA = ml[rowA * 2 + 1];
    float mB = ml[rowB * 2], lB = ml[rowB * 2 + 1];
    float m = fmaxf(mA, mB);
    float sA = exp2f(mA - m), sB = exp2f(mB - m);
    float inv = 1.f / (lA * sA + lB * sB);

    float4 oA = *(const float4*)(po + rowA * 64 + 4 * d4);
    float4 oB = *(const float4*)(po + rowB * 64 + 4 * d4);
    float v0 = (oA.x * sA + oB.x * sB) * inv;
    float v1 = (oA.y * sA + oB.y * sB) * inv;
    float v2 = (oA.z * sA + oB.z * sB) * inv;
    float v3 = (oA.w * sA + oB.w * sB) * inv;

    int grow = b * 2048 + (8 + hb) * 128 + r;
    int pr = h * 32 + 2 * d4;
    yp[(size_t)grow * 384 + pr]     = cvtH(v0, v1);
    yp[(size_t)grow * 384 + pr + 1] = cvtH(v2, v3);
}

extern "C" void kernel_launch(void* const* d_in, const int* in_sizes, int n_in,
                              void* d_out, int out_size)
{
    const float* x      = (const float*)d_in[0];
    const float* W_attn = (const float*)d_in[1];
    const float* b_attn = (const float*)d_in[2];
    const float* W_proj = (const float*)d_in[3];
    const float* b_proj = (const float*)d_in[4];
    float* out = (float*)d_out;

    uint32_t *qkvp, *vt, *xp, *yp, *wt, *wt2;
    float *po, *mlb;
    cudaGetSymbolAddress((void**)&qkvp, g_qkvp);
    cudaGetSymbolAddress((void**)&vt, g_vt);
    cudaGetSymbolAddress((void**)&xp, g_xp);
    cudaGetSymbolAddress((void**)&yp, g_yp);
    cudaGetSymbolAddress((void**)&wt, g_wt);
    cudaGetSymbolAddress((void**)&wt2, g_wt2);
    cudaGetSymbolAddress((void**)&po, g_po);
    cudaGetSymbolAddress((void**)&mlb, g_ml);

    const int GEMM_SMEM  = 2 * 5120 * 4;    // 40960
    const int FLASH_SMEM = 2 * 4608 * 4;    // 36864
    cudaFuncSetAttribute(gemm_planes<0>,
                         cudaFuncAttributeMaxDynamicSharedMemorySize, GEMM_SMEM);
    cudaFuncSetAttribute(gemm_planes<1>,
                         cudaFuncAttributeMaxDynamicSharedMemorySize, GEMM_SMEM);
    cudaFuncSetAttribute(flash_planes,
                         cudaFuncAttributeMaxDynamicSharedMemorySize, FLASH_SMEM);

    split_x<<<786432 / 256, 256>>>(x, xp);                                 // 0
    transpose_cvtH<<<dim3(C3 / 32, CC / 32), dim3(32, 8)>>>(               // 1
        W_attn, wt, CC, C3);
    transpose_cvtH<<<dim3(CC / 32, CC / 32), dim3(32, 8)>>>(               // 2
        W_proj, wt2, CC, CC);

    gemm_planes<0><<<dim3(C3 / 128, MTOT / 128), 256, GEMM_SMEM>>>(        // 3
        xp, wt, b_attn, nullptr, qkvp, MTOT, C3, CC);

    pack_vt<<<(2048 * 384) / 256, 256>>>(qkvp + (size_t)3 * PSZ, vt);      // 4

    flash_planes<<<dim3(24, 24), 256, FLASH_SMEM>>>(                       // 5
        qkvp, vt, yp, po, mlb);

    merge_heavy<<<393216 / 256, 256>>>(po, mlb, yp);                       // 6

    gemm_planes<1><<<dim3(CC / 128, MTOT / 128), 256, GEMM_SMEM>>>(        // 7
        yp, wt2, b_proj, out, nullptr, MTOT, CC, CC);
}

// round 15
// speedup vs baseline: 6.0159x; 1.0478x over previous
#include <cuda_runtime.h>
#include <cuda_bf16.h>
#include <cuda_fp16.h>
#include <math.h>
#include <cstdint>

#define BB 2
#define TT 2048
#define CC 768
#define HH 12
#define HS 64
#define C3 2304
#define MTOT (BB*TT)          // 4096
#define PSZ (4096*384)        // u32 per plane for [M][768 cols] fp16x2 pairs
#define QSCALE 0.18033688011112042f   // 0.125 * log2(e)

// Scratch (allocation-free contract) — all planes are fp16x2-packed u32
__device__ uint32_t g_qkvp[4 * (size_t)PSZ];        // q_hi, q_lo, k, v
__device__ uint32_t g_vt[(size_t)2048 * 768];       // V token-pair-major (single fp16)
__device__ uint32_t g_xp[(size_t)PSZ];              // x single fp16 plane
__device__ uint32_t g_yp[(size_t)PSZ];              // y single fp16 plane
__device__ uint32_t g_wt[(size_t)C3 * CC / 2];      // W_attn^T single fp16 plane
__device__ uint32_t g_wt2[(size_t)CC * CC / 2];     // W_proj^T single fp16 plane
// split-KV partials: [2 splits][24 bh][8 heavy blocks][128 rows][64 dims]
__device__ float g_po[(size_t)2 * 24 * 8 * 128 * 64];
__device__ float g_ml[(size_t)2 * 24 * 8 * 128 * 2];

// ---------------------------------------------------------------------------
// Helpers
// ---------------------------------------------------------------------------
__device__ __forceinline__ uint32_t smem_u32(const void* p) {
    uint32_t a;
    asm("{ .reg .u64 t; cvta.to.shared.u64 t, %1; cvt.u32.u64 %0, t; }"
        : "=r"(a) : "l"(p));
    return a;
}

__device__ __forceinline__ void mma_f16(float c[4],
    uint32_t a0, uint32_t a1, uint32_t a2, uint32_t a3,
    uint32_t b0, uint32_t b1)
{
    asm("mma.sync.aligned.m16n8k16.row.col.f32.f16.f16.f32 "
        "{%0,%1,%2,%3}, {%4,%5,%6,%7}, {%8,%9}, {%0,%1,%2,%3};"
        : "+f"(c[0]), "+f"(c[1]), "+f"(c[2]), "+f"(c[3])
        : "r"(a0), "r"(a1), "r"(a2), "r"(a3), "r"(b0), "r"(b1));
}

__device__ __forceinline__ void ldm_x4(uint32_t& r0, uint32_t& r1,
                                       uint32_t& r2, uint32_t& r3, uint32_t addr)
{
    asm volatile("ldmatrix.sync.aligned.m8n8.x4.shared.b16 {%0,%1,%2,%3}, [%4];"
        : "=r"(r0), "=r"(r1), "=r"(r2), "=r"(r3) : "r"(addr));
}

__device__ __forceinline__ uint32_t cvtH(float x, float y)
{
    __half2 h = __floats2half2_rn(x, y);
    return *reinterpret_cast<uint32_t*>(&h);
}

__device__ __forceinline__ void splitH(float x, float y, uint32_t& hi, uint32_t& lo)
{
    __half2 h = __floats2half2_rn(x, y);
    hi = *reinterpret_cast<uint32_t*>(&h);
    float hx = __low2float(h), hy = __high2float(h);
    __half2 l = __floats2half2_rn(x - hx, y - hy);
    lo = *reinterpret_cast<uint32_t*>(&l);
}

__device__ __forceinline__ uint32_t ex2_f16x2(uint32_t x) {
    uint32_t r;
    asm("ex2.approx.f16x2 %0, %1;" : "=r"(r) : "r"(x));
    return r;
}

__device__ __forceinline__ void cpasync16(uint32_t dst, const void* src) {
    asm volatile("cp.async.cg.shared.global [%0], [%1], 16;"
                 :: "r"(dst), "l"(src));
}
#define CP_COMMIT() asm volatile("cp.async.commit_group;" ::: "memory")
#define CP_WAIT1()  asm volatile("cp.async.wait_group 1;" ::: "memory")
#define CP_WAIT0()  asm volatile("cp.async.wait_group 0;" ::: "memory")

// ---------------------------------------------------------------------------
// Prep kernels
// ---------------------------------------------------------------------------
__global__ void split_x(const float* __restrict__ x, uint32_t* __restrict__ xh)
{
    int idx = blockIdx.x * 256 + threadIdx.x;
    int r = idx / 192, j2 = idx % 192;
    float4 v = *(const float4*)(x + (size_t)r * 768 + 4 * j2);
    *(uint2*)(xh + (size_t)r * 384 + 2 * j2) =
        make_uint2(cvtH(v.x, v.y), cvtH(v.z, v.w));
}

__global__ void transpose_cvtH(const float* __restrict__ in,
                               uint32_t* __restrict__ outp,
                               int K, int N)
{
    __shared__ float t[32][33];
    int n0 = blockIdx.x << 5, k0 = blockIdx.y << 5;
    int x = threadIdx.x, y = threadIdx.y;
    #pragma unroll
    for (int i = 0; i < 32; i += 8)
        t[y + i][x] = in[(size_t)(k0 + y + i) * N + n0 + x];
    __syncthreads();
    if (x < 16) {
        #pragma unroll
        for (int i = 0; i < 32; i += 8) {
            int n = n0 + y + i;
            outp[(size_t)n * (K / 2) + k0 / 2 + x] =
                cvtH(t[2 * x][y + i], t[2 * x + 1][y + i]);
        }
    }
}

__global__ void pack_vt(const uint32_t* __restrict__ vp,
                        uint32_t* __restrict__ vtp)
{
    int idx = blockIdx.x * 256 + threadIdx.x;
    int bp = idx / 384, j = idx % 384;
    size_t s0 = (size_t)(2 * bp) * 384 + j;
    uint32_t a = vp[s0], b = vp[s0 + 384];
    size_t o = (size_t)bp * 768 + 2 * j;
    vtp[o]     = __byte_perm(a, b, 0x5410);
    vtp[o + 1] = __byte_perm(a, b, 0x7632);
}

// ---------------------------------------------------------------------------
// fp16 single-product GEMM, BK=64 stages (NK=12): halved barrier count.
// Stage layout (u32): A@0 [128][36], B@4608 [128][36]. Stage = 9216 u32.
// ---------------------------------------------------------------------------
__device__ __forceinline__ void gemm_issue(
    uint32_t st_u32,
    const uint32_t* Ah, const uint32_t* Bp,
    int row0, int col0, int K2, int kp0, int tid)
{
    #pragma unroll
    for (int p = 0; p < 4; p++) {
        int idx = p * 256 + tid;          // 0..1023
        int r = idx >> 3, c = idx & 7;
        uint32_t dst = st_u32 + (r * 36 + c * 4) * 4;
        cpasync16(dst, Ah + (size_t)(row0 + r) * K2 + kp0 + c * 4);
    }
    #pragma unroll
    for (int p = 0; p < 4; p++) {
        int idx = p * 256 + tid;
        int r = idx >> 3, c = idx & 7;
        uint32_t dst = st_u32 + (4608 + r * 36 + c * 4) * 4;
        cpasync16(dst, Bp + (size_t)(col0 + r) * K2 + kp0 + c * 4);
    }
}

template <int MODE>
__global__ __launch_bounds__(256, 2) void gemm_planes(
    const uint32_t* __restrict__ Ah, const uint32_t* __restrict__ Bp,
    const float* __restrict__ bias,
    float* __restrict__ outf,
    uint32_t* __restrict__ qkvp,
    int M, int N, int K)
{
    extern __shared__ uint32_t sm[];     // 2 stages x 9216 u32
    const uint32_t sm_u = smem_u32(sm);

    const int tid  = threadIdx.x;
    const int wid  = tid >> 5, lane = tid & 31;
    const int gid  = lane >> 2, tig = lane & 3;
    const int wm   = wid & 3;
    const int wn   = wid >> 2;
    const int row0 = blockIdx.y * 128;
    const int col0 = blockIdx.x * 128;
    const int K2   = K >> 1;
    const int NK   = K >> 6;             // BK = 64 floats

    const int lane7 = lane & 7;
    const int aRow  = wm * 32 + lane7 + ((lane >> 3) & 1) * 8;
    const int aColB = ((lane >> 4) & 1) * 16;
    const uint32_t aOff = (uint32_t)(aRow * 144) + aColB;
    const int bRow  = wn * 64 + lane7 + ((lane >> 4) & 1) * 8;
    const int bColB = ((lane >> 3) & 1) * 16;
    const uint32_t bOff = 4608 * 4 + (uint32_t)(bRow * 144) + bColB;

    float cf[2][8][4];
    #pragma unroll
    for (int ma = 0; ma < 2; ma++)
        #pragma unroll
        for (int na = 0; na < 8; na++)
            #pragma unroll
            for (int r = 0; r < 4; r++) cf[ma][na][r] = 0.f;

    gemm_issue(sm_u, Ah, Bp, row0, col0, K2, 0, tid);
    CP_COMMIT();

    for (int kt = 0; kt < NK; kt++) {
        const int s = kt & 1;
        if (kt + 1 < NK) {
            gemm_issue(sm_u + (s ^ 1) * 36864, Ah, Bp,
                       row0, col0, K2, (kt + 1) << 5, tid);
            CP_COMMIT();
            CP_WAIT1();
        } else {
            CP_WAIT0();
        }
        __syncthreads();

        const uint32_t stage = sm_u + s * 36864;

        #pragma unroll
        for (int ss = 0; ss < 4; ss++) {
            const uint32_t ssb = ss * 32;
            uint32_t a[2][4];
            #pragma unroll
            for (int ma = 0; ma < 2; ma++)
                ldm_x4(a[ma][0], a[ma][1], a[ma][2], a[ma][3],
                       stage + aOff + ma * 2304 + ssb);
            #pragma unroll
            for (int j = 0; j < 4; j++) {
                uint32_t b0, b1, b2, b3;
                ldm_x4(b0, b1, b2, b3, stage + bOff + j * 2304 + ssb);
                #pragma unroll
                for (int ma = 0; ma < 2; ma++) {
                    mma_f16(cf[ma][2 * j],     a[ma][0], a[ma][1], a[ma][2], a[ma][3], b0, b1);
                    mma_f16(cf[ma][2 * j + 1], a[ma][0], a[ma][1], a[ma][2], a[ma][3], b2, b3);
                }
            }
        }
        __syncthreads();
    }

    if (MODE == 1) {
        #pragma unroll
        for (int ma = 0; ma < 2; ma++) {
            const int rg = row0 + wm * 32 + ma * 16 + gid;
            #pragma unroll
            for (int na = 0; na < 8; na++) {
                const int cg = col0 + wn * 64 + na * 8 + tig * 2;
                const float bx0 = bias[cg], bx1 = bias[cg + 1];
                *(float2*)(outf + (size_t)rg * N + cg) =
                    make_float2(cf[ma][na][0] + bx0, cf[ma][na][1] + bx1);
                *(float2*)(outf + (size_t)(rg + 8) * N + cg) =
                    make_float2(cf[ma][na][2] + bx0, cf[ma][na][3] + bx1);
            }
        }
    } else {
        const int which = col0 / 768;
        const int lc0 = col0 - which * 768;
        #pragma unroll
        for (int ma = 0; ma < 2; ma++) {
            const int rg = row0 + wm * 32 + ma * 16 + gid;
            #pragma unroll
            for (int na = 0; na < 8; na++) {
                const int gc = col0 + wn * 64 + na * 8 + tig * 2;
                const int pr = (lc0 >> 1) + wn * 32 + na * 4 + tig;
                const float bx0 = bias[gc], bx1 = bias[gc + 1];
                float v0 = cf[ma][na][0] + bx0, v1 = cf[ma][na][1] + bx1;
                float v2 = cf[ma][na][2] + bx0, v3 = cf[ma][na][3] + bx1;
                if (which == 0) {
                    uint32_t h, l;
                    splitH(v0 * QSCALE, v1 * QSCALE, h, l);
                    qkvp[(size_t)rg * 384 + pr] = h;
                    qkvp[(size_t)PSZ + (size_t)rg * 384 + pr] = l;
                    splitH(v2 * QSCALE, v3 * QSCALE, h, l);
                    qkvp[(size_t)(rg + 8) * 384 + pr] = h;
                    qkvp[(size_t)PSZ + (size_t)(rg + 8) * 384 + pr] = l;
                } else if (which == 1) {
                    qkvp[(size_t)2 * PSZ + (size_t)rg * 384 + pr] = cvtH(v0, v1);
                    qkvp[(size_t)2 * PSZ + (size_t)(rg + 8) * 384 + pr] = cvtH(v2, v3);
                } else {
                    qkvp[(size_t)3 * PSZ + (size_t)rg * 384 + pr] = cvtH(v0, v1);
                    qkvp[(size_t)3 * PSZ + (size_t)(rg + 8) * 384 + pr] = cvtH(v2, v3);
                }
            }
        }
    }
}

// ---------------------------------------------------------------------------
// Flash attention: 128-token KV stages, two 64-token compute passes per stage.
// Stage layout (u32): K@0 [128][36], V@4608 [64][72]. Stage = 9216 u32.
// ---------------------------------------------------------------------------
__device__ __forceinline__ void flash_issue(
    uint32_t st_u32,
    const uint32_t* kp, const uint32_t* vtp,
    int tok0, int vrow0, int h, int tid)
{
    #pragma unroll
    for (int p = 0; p < 4; p++) {
        int idx = p * 256 + tid;          // 0..1023 : 128 K tokens
        int r = idx >> 3, c = idx & 7;
        uint32_t dst = st_u32 + (r * 36 + c * 4) * 4;
        cpasync16(dst, kp + (size_t)(tok0 + r) * 384 + h * 32 + c * 4);
    }
    #pragma unroll
    for (int p = 0; p < 4; p++) {
        int idx = p * 256 + tid;          // 0..1023 : 64 V token-pairs
        int r = idx >> 4, c = idx & 15;
        uint32_t dst = st_u32 + (4608 + r * 72 + c * 4) * 4;
        cpasync16(dst, vtp + (size_t)(vrow0 + r) * 768 + h * 64 + c * 4);
    }
}

__global__ __launch_bounds__(256, 2) void flash_planes(
    const uint32_t* __restrict__ qkvp, const uint32_t* __restrict__ vt,
    uint32_t* __restrict__ yp,
    float* __restrict__ po, float* __restrict__ ml)
{
    extern __shared__ uint32_t sm[];       // 2 stages x 9216 u32
    const uint32_t sm_u = smem_u32(sm);

    const int tid = threadIdx.x;
    const int wid = tid >> 5, lane = tid & 31;
    const int gid = lane >> 2, tig = lane & 3;
    const int bh = blockIdx.x;
    const int u  = blockIdx.y;
    const int b  = bh / HH;
    const int h  = bh % HH;

    int bx, split, kt0, kt1;
    if (u < 16) {
        bx    = 8 + (u >> 1);
        split = u & 1;
        const int half = bx + 1;
        kt0 = split ? half : 0;
        kt1 = split ? (2 * bx + 2) : half;
    } else {
        bx = 23 - u;
        split = -1;
        kt0 = 0;
        kt1 = 2 * bx + 2;
    }
    const int q0 = bx * 128;

    const uint32_t* qph = qkvp;
    const uint32_t* qpl = qkvp + (size_t)PSZ;
    const uint32_t* kp  = qkvp + (size_t)2 * PSZ;

    const int lane7 = lane & 7;
    const int kRow  = lane7 + ((lane >> 4) & 1) * 8;
    const int kColB = ((lane >> 3) & 1) * 16;
    const uint32_t kOff = (uint32_t)(kRow * 144) + kColB;

    const int grow0 = b * 2048 + q0 + wid * 16 + gid;
    uint32_t qh[4][4], ql[4][4];
    #pragma unroll
    for (int ks = 0; ks < 4; ks++) {
        const int pr = h * 32 + 8 * ks + tig;
        qh[ks][0] = qph[(size_t)grow0 * 384 + pr];
        qh[ks][1] = qph[(size_t)(grow0 + 8) * 384 + pr];
        qh[ks][2] = qph[(size_t)grow0 * 384 + pr + 4];
        qh[ks][3] = qph[(size_t)(grow0 + 8) * 384 + pr + 4];
        ql[ks][0] = qpl[(size_t)grow0 * 384 + pr];
        ql[ks][1] = qpl[(size_t)(grow0 + 8) * 384 + pr];
        ql[ks][2] = qpl[(size_t)grow0 * 384 + pr + 4];
        ql[ks][3] = qpl[(size_t)(grow0 + 8) * 384 + pr + 4];
    }

    float of[8][4];
    #pragma unroll
    for (int na = 0; na < 8; na++)
        #pragma unroll
        for (int r = 0; r < 4; r++) of[na][r] = 0.f;
    float m0 = -1e30f, m1 = -1e30f, l0 = 0.f, l1 = 0.f;
    const int r0g = q0 + wid * 16 + gid;
    const int r1g = r0g + 8;

    const int nloc = kt1 - kt0;
    const int nst  = (nloc + 1) >> 1;      // 128-token stages
    flash_issue(sm_u, kp, vt,
                b * 2048 + kt0 * 64, b * 1024 + kt0 * 32, h, tid);
    CP_COMMIT();

    for (int si = 0; si < nst; si++) {
        const int s = si & 1;
        if (si + 1 < nst) {
            const int kn = kt0 + 2 * (si + 1);
            flash_issue(sm_u + (s ^ 1) * 36864, kp, vt,
                        b * 2048 + kn * 64, b * 1024 + kn * 32, h, tid);
            CP_COMMIT();
            CP_WAIT1();
        } else {
            CP_WAIT0();
        }
        __syncthreads();

        #pragma unroll
        for (int sub = 0; sub < 2; sub++) {
            const int kt = kt0 + 2 * si + sub;
            if (kt >= kt1) break;
            if (kt * 64 > q0 + wid * 16 + 15) continue;

            const uint32_t stage = sm_u + s * 36864 + (uint32_t)sub * 64 * 144;
            const uint32_t* v_sh = sm + s * 9216 + 4608 + sub * 32 * 72;

            // ---- S(log2) = Qscaled @ K^T (Q hi/lo, K single) ----
            float sf[8][4];
            #pragma unroll
            for (int na = 0; na < 8; na++)
                #pragma unroll
                for (int r = 0; r < 4; r++) sf[na][r] = 0.f;

            #pragma unroll
            for (int ks = 0; ks < 4; ks++) {
                const uint32_t ksb = ks * 32;
                #pragma unroll
                for (int j = 0; j < 4; j++) {
                    uint32_t b0, b1, b2, b3;
                    ldm_x4(b0, b1, b2, b3, stage + kOff + j * 2304 + ksb);
                    mma_f16(sf[2 * j],     qh[ks][0], qh[ks][1], qh[ks][2], qh[ks][3], b0, b1);
                    mma_f16(sf[2 * j],     ql[ks][0], ql[ks][1], ql[ks][2], ql[ks][3], b0, b1);
                    mma_f16(sf[2 * j + 1], qh[ks][0], qh[ks][1], qh[ks][2], qh[ks][3], b2, b3);
                    mma_f16(sf[2 * j + 1], ql[ks][0], ql[ks][1], ql[ks][2], ql[ks][3], b2, b3);
                }
            }

            // ---- causal mask ----
            const bool need_mask = (kt >= 2 * bx);
            if (need_mask) {
                #pragma unroll
                for (int na = 0; na < 8; na++) {
                    const int cg = kt * 64 + na * 8 + tig * 2;
                    if (cg     > r0g) sf[na][0] = -1e30f;
                    if (cg + 1 > r0g) sf[na][1] = -1e30f;
                    if (cg     > r1g) sf[na][2] = -1e30f;
                    if (cg + 1 > r1g) sf[na][3] = -1e30f;
                }
            }

            // ---- online softmax (log2 domain, fp16 exp2) ----
            float rm0 = -1e30f, rm1 = -1e30f;
            #pragma unroll
            for (int na = 0; na < 8; na++) {
                rm0 = fmaxf(rm0, fmaxf(sf[na][0], sf[na][1]));
                rm1 = fmaxf(rm1, fmaxf(sf[na][2], sf[na][3]));
            }
            rm0 = fmaxf(rm0, __shfl_xor_sync(0xffffffffu, rm0, 1));
            rm0 = fmaxf(rm0, __shfl_xor_sync(0xffffffffu, rm0, 2));
            rm1 = fmaxf(rm1, __shfl_xor_sync(0xffffffffu, rm1, 1));
            rm1 = fmaxf(rm1, __shfl_xor_sync(0xffffffffu, rm1, 2));
            const float mn0 = fmaxf(m0, rm0), mn1 = fmaxf(m1, rm1);
            const float c0 = exp2f(m0 - mn0), c1 = exp2f(m1 - mn1);
            float rs0 = 0.f, rs1 = 0.f;
            uint32_t p01[8], p23[8];
            #pragma unroll
            for (int na = 0; na < 8; na++) {
                __half2 h01 = __floats2half2_rn(sf[na][0] - mn0, sf[na][1] - mn0);
                __half2 h23 = __floats2half2_rn(sf[na][2] - mn1, sf[na][3] - mn1);
                p01[na] = ex2_f16x2(*reinterpret_cast<uint32_t*>(&h01));
                p23[na] = ex2_f16x2(*reinterpret_cast<uint32_t*>(&h23));
                float2 f01 = __half22float2(*reinterpret_cast<__half2*>(&p01[na]));
                float2 f23 = __half22float2(*reinterpret_cast<__half2*>(&p23[na]));
                rs0 += f01.x + f01.y;
                rs1 += f23.x + f23.y;
            }
            rs0 += __shfl_xor_sync(0xffffffffu, rs0, 1);
            rs0 += __shfl_xor_sync(0xffffffffu, rs0, 2);
            rs1 += __shfl_xor_sync(0xffffffffu, rs1, 1);
            rs1 += __shfl_xor_sync(0xffffffffu, rs1, 2);
            l0 = l0 * c0 + rs0; m0 = mn0;
            l1 = l1 * c1 + rs1; m1 = mn1;
            #pragma unroll
            for (int na = 0; na < 8; na++) {
                of[na][0] *= c0; of[na][1] *= c0;
                of[na][2] *= c1; of[na][3] *= c1;
            }

            // ---- O += P @ V (single fp16 V) ----
            #pragma unroll
            for (int ks = 0; ks < 4; ks++) {
                const uint32_t pa0 = p01[2 * ks],     pa1 = p23[2 * ks];
                const uint32_t pa2 = p01[2 * ks + 1], pa3 = p23[2 * ks + 1];
                #pragma unroll
                for (int na = 0; na < 8; na++) {
                    const int d = na * 8 + gid;
                    mma_f16(of[na], pa0, pa1, pa2, pa3,
                            v_sh[(8 * ks + tig) * 72 + d],
                            v_sh[(8 * ks + tig + 4) * 72 + d]);
                }
            }
        }
        __syncthreads();
    }

    if (split < 0) {
        const float i0 = 1.f / l0, i1 = 1.f / l1;
        const int gr0 = b * 2048 + r0g;
        #pragma unroll
        for (int na = 0; na < 8; na++) {
            const int pr = h * 32 + na * 4 + tig;
            yp[(size_t)gr0 * 384 + pr] = cvtH(of[na][0] * i0, of[na][1] * i0);
            yp[(size_t)(gr0 + 8) * 384 + pr] = cvtH(of[na][2] * i1, of[na][3] * i1);
        }
    } else {
        const int hb = bx - 8;
        const int r0 = wid * 16 + gid;
        float* pob = po + ((((size_t)split * 24 + bh) * 8 + hb) * 128) * 64;
        #pragma unroll
        for (int na = 0; na < 8; na++) {
            *(float2*)(pob + (size_t)r0 * 64 + na * 8 + 2 * tig) =
                make_float2(of[na][0], of[na][1]);
            *(float2*)(pob + (size_t)(r0 + 8) * 64 + na * 8 + 2 * tig) =
                make_float2(of[na][2], of[na][3]);
        }
        if (tig == 0) {
            float* mlb = ml + ((((size_t)split * 24 + bh) * 8 + hb) * 128) * 2;
            mlb[r0 * 2]           = m0;
            mlb[r0 * 2 + 1]       = l0;
            mlb[(r0 + 8) * 2]     = m1;
            mlb[(r0 + 8) * 2 + 1] = l1;
        }
    }
}

// ---------------------------------------------------------------------------
// Merge split-KV partials into y plane (heavy q-blocks only).
// ---------------------------------------------------------------------------
__global__ void merge_heavy(const float* __restrict__ po,
                            const float* __restrict__ ml,
                            uint32_t* __restrict__ yp)
{
    int idx = blockIdx.x * 256 + threadIdx.x;
    int d4 = idx & 15;
    int r  = (idx >> 4) & 127;
    int hb = (idx >> 11) & 7;
    int bh = idx >> 14;
    int b = bh / HH, h = bh % HH;

    size_t rowA = (((size_t)0 * 24 + bh) * 8 + hb) * 128 + r;
    size_t rowB = (((size_t)1 * 24 + bh) * 8 + hb) * 128 + r;
    float mA = ml[rowA * 2], lA = ml[rowA * 2 + 1];
    float mB = ml[rowB * 2], lB = ml[rowB * 2 + 1];
    float m = fmaxf(mA, mB);
    float sA = exp2f(mA - m), sB = exp2f(mB - m);
    float inv = 1.f / (lA * sA + lB * sB);

    float4 oA = *(const float4*)(po + rowA * 64 + 4 * d4);
    float4 oB = *(const float4*)(po + rowB * 64 + 4 * d4);
    float v0 = (oA.x * sA + oB.x * sB) * inv;
    float v1 = (oA.y * sA + oB.y * sB) * inv;
    float v2 = (oA.z * sA + oB.z * sB) * inv;
    float v3 = (oA.w * sA + oB.w * sB) * inv;

    int grow = b * 2048 + (8 + hb) * 128 + r;
    int pr = h * 32 + 2 * d4;
    yp[(size_t)grow * 384 + pr]     = cvtH(v0, v1);
    yp[(size_t)grow * 384 + pr + 1] = cvtH(v2, v3);
}

extern "C" void kernel_launch(void* const* d_in, const int* in_sizes, int n_in,
                              void* d_out, int out_size)
{
    const float* x      = (const float*)d_in[0];
    const float* W_attn = (const float*)d_in[1];
    const float* b_attn = (const float*)d_in[2];
    const float* W_proj = (const float*)d_in[3];
    const float* b_proj = (const float*)d_in[4];
    float* out = (float*)d_out;

    uint32_t *qkvp, *vt, *xp, *yp, *wt, *wt2;
    float *po, *mlb;
    cudaGetSymbolAddress((void**)&qkvp, g_qkvp);
    cudaGetSymbolAddress((void**)&vt, g_vt);
    cudaGetSymbolAddress((void**)&xp, g_xp);
    cudaGetSymbolAddress((void**)&yp, g_yp);
    cudaGetSymbolAddress((void**)&wt, g_wt);
    cudaGetSymbolAddress((void**)&wt2, g_wt2);
    cudaGetSymbolAddress((void**)&po, g_po);
    cudaGetSymbolAddress((void**)&mlb, g_ml);

    const int GEMM_SMEM  = 2 * 9216 * 4;    // 73728
    const int FLASH_SMEM = 2 * 9216 * 4;    // 73728
    cudaFuncSetAttribute(gemm_planes<0>,
                         cudaFuncAttributeMaxDynamicSharedMemorySize, GEMM_SMEM);
    cudaFuncSetAttribute(gemm_planes<1>,
                         cudaFuncAttributeMaxDynamicSharedMemorySize, GEMM_SMEM);
    cudaFuncSetAttribute(flash_planes,
                         cudaFuncAttributeMaxDynamicSharedMemorySize, FLASH_SMEM);

    split_x<<<786432 / 256, 256>>>(x, xp);                                 // 0
    transpose_cvtH<<<dim3(C3 / 32, CC / 32), dim3(32, 8)>>>(               // 1
        W_attn, wt, CC, C3);
    transpose_cvtH<<<dim3(CC / 32, CC / 32), dim3(32, 8)>>>(               // 2
        W_proj, wt2, CC, CC);

    gemm_planes<0><<<dim3(C3 / 128, MTOT / 128), 256, GEMM_SMEM>>>(        // 3
        xp, wt, b_attn, nullptr, qkvp, MTOT, C3, CC);

    pack_vt<<<(2048 * 384) / 256, 256>>>(qkvp + (size_t)3 * PSZ, vt);      // 4

    flash_planes<<<dim3(24, 24), 256, FLASH_SMEM>>>(                       // 5
        qkvp, vt, yp, po, mlb);

    merge_heavy<<<393216 / 256, 256>>>(po, mlb, yp);                       // 6

    gemm_planes<1><<<dim3(CC / 128, MTOT / 128), 256, GEMM_SMEM>>>(        // 7
        yp, wt2, b_proj, out, nullptr, MTOT, CC, CC);
}

// round 16
// speedup vs baseline: 6.1183x; 1.0170x over previous
#include <cuda_runtime.h>
#include <cuda_bf16.h>
#include <cuda_fp16.h>
#include <math.h>
#include <cstdint>

#define BB 2
#define TT 2048
#define CC 768
#define HH 12
#define HS 64
#define C3 2304
#define MTOT (BB*TT)          // 4096
#define PSZ (4096*384)        // u32 per plane for [M][768 cols] fp16x2 pairs
#define QSCALE 0.18033688011112042f   // 0.125 * log2(e)

// Scratch (allocation-free contract) — all planes are fp16x2-packed u32
__device__ uint32_t g_qkvp[4 * (size_t)PSZ];        // q_hi, q_lo, k, v
__device__ uint32_t g_xp[(size_t)PSZ];              // x single fp16 plane
__device__ uint32_t g_yp[(size_t)PSZ];              // y single fp16 plane
__device__ uint32_t g_wt[(size_t)C3 * CC / 2];      // W_attn^T single fp16 plane
__device__ uint32_t g_wt2[(size_t)CC * CC / 2];     // W_proj^T single fp16 plane
// split-KV partials: [2 splits][24 bh][8 heavy blocks][128 rows][64 dims]
__device__ float g_po[(size_t)2 * 24 * 8 * 128 * 64];
__device__ float g_ml[(size_t)2 * 24 * 8 * 128 * 2];

// ---------------------------------------------------------------------------
// Helpers
// ---------------------------------------------------------------------------
__device__ __forceinline__ uint32_t smem_u32(const void* p) {
    uint32_t a;
    asm("{ .reg .u64 t; cvta.to.shared.u64 t, %1; cvt.u32.u64 %0, t; }"
        : "=r"(a) : "l"(p));
    return a;
}

__device__ __forceinline__ void mma_f16(float c[4],
    uint32_t a0, uint32_t a1, uint32_t a2, uint32_t a3,
    uint32_t b0, uint32_t b1)
{
    asm("mma.sync.aligned.m16n8k16.row.col.f32.f16.f16.f32 "
        "{%0,%1,%2,%3}, {%4,%5,%6,%7}, {%8,%9}, {%0,%1,%2,%3};"
        : "+f"(c[0]), "+f"(c[1]), "+f"(c[2]), "+f"(c[3])
        : "r"(a0), "r"(a1), "r"(a2), "r"(a3), "r"(b0), "r"(b1));
}

__device__ __forceinline__ void ldm_x4(uint32_t& r0, uint32_t& r1,
                                       uint32_t& r2, uint32_t& r3, uint32_t addr)
{
    asm volatile("ldmatrix.sync.aligned.m8n8.x4.shared.b16 {%0,%1,%2,%3}, [%4];"
        : "=r"(r0), "=r"(r1), "=r"(r2), "=r"(r3) : "r"(addr));
}

__device__ __forceinline__ void ldm_x4t(uint32_t& r0, uint32_t& r1,
                                        uint32_t& r2, uint32_t& r3, uint32_t addr)
{
    asm volatile("ldmatrix.sync.aligned.m8n8.x4.trans.shared.b16 {%0,%1,%2,%3}, [%4];"
        : "=r"(r0), "=r"(r1), "=r"(r2), "=r"(r3) : "r"(addr));
}

__device__ __forceinline__ uint32_t cvtH(float x, float y)
{
    __half2 h = __floats2half2_rn(x, y);
    return *reinterpret_cast<uint32_t*>(&h);
}

__device__ __forceinline__ void splitH(float x, float y, uint32_t& hi, uint32_t& lo)
{
    __half2 h = __floats2half2_rn(x, y);
    hi = *reinterpret_cast<uint32_t*>(&h);
    float hx = __low2float(h), hy = __high2float(h);
    __half2 l = __floats2half2_rn(x - hx, y - hy);
    lo = *reinterpret_cast<uint32_t*>(&l);
}

__device__ __forceinline__ uint32_t ex2_f16x2(uint32_t x) {
    uint32_t r;
    asm("ex2.approx.f16x2 %0, %1;" : "=r"(r) : "r"(x));
    return r;
}

__device__ __forceinline__ void cpasync16(uint32_t dst, const void* src) {
    asm volatile("cp.async.cg.shared.global [%0], [%1], 16;"
                 :: "r"(dst), "l"(src));
}
#define CP_COMMIT() asm volatile("cp.async.commit_group;" ::: "memory")
#define CP_WAIT1()  asm volatile("cp.async.wait_group 1;" ::: "memory")
#define CP_WAIT0()  asm volatile("cp.async.wait_group 0;" ::: "memory")

// ---------------------------------------------------------------------------
// Prep kernels
// ---------------------------------------------------------------------------
__global__ void split_x(const float* __restrict__ x, uint32_t* __restrict__ xh)
{
    int idx = blockIdx.x * 256 + threadIdx.x;
    int r = idx / 192, j2 = idx % 192;
    float4 v = *(const float4*)(x + (size_t)r * 768 + 4 * j2);
    *(uint2*)(xh + (size_t)r * 384 + 2 * j2) =
        make_uint2(cvtH(v.x, v.y), cvtH(v.z, v.w));
}

__global__ void transpose_cvtH(const float* __restrict__ in,
                               uint32_t* __restrict__ outp,
                               int K, int N)
{
    __shared__ float t[32][33];
    int n0 = blockIdx.x << 5, k0 = blockIdx.y << 5;
    int x = threadIdx.x, y = threadIdx.y;
    #pragma unroll
    for (int i = 0; i < 32; i += 8)
        t[y + i][x] = in[(size_t)(k0 + y + i) * N + n0 + x];
    __syncthreads();
    if (x < 16) {
        #pragma unroll
        for (int i = 0; i < 32; i += 8) {
            int n = n0 + y + i;
            outp[(size_t)n * (K / 2) + k0 / 2 + x] =
                cvtH(t[2 * x][y + i], t[2 * x + 1][y + i]);
        }
    }
}

// ---------------------------------------------------------------------------
// fp16 single-product GEMM, BK=64, 3-stage pipeline, ONE barrier per iter.
// Stage layout (u32): A@0 [128][36], B@4608 [128][36]. Stage = 9216 u32.
// ---------------------------------------------------------------------------
__device__ __forceinline__ void gemm_issue(
    uint32_t st_u32,
    const uint32_t* Ah, const uint32_t* Bp,
    int row0, int col0, int K2, int kp0, int tid)
{
    #pragma unroll
    for (int p = 0; p < 4; p++) {
        int idx = p * 256 + tid;
        int r = idx >> 3, c = idx & 7;
        uint32_t dst = st_u32 + (r * 36 + c * 4) * 4;
        cpasync16(dst, Ah + (size_t)(row0 + r) * K2 + kp0 + c * 4);
    }
    #pragma unroll
    for (int p = 0; p < 4; p++) {
        int idx = p * 256 + tid;
        int r = idx >> 3, c = idx & 7;
        uint32_t dst = st_u32 + (4608 + r * 36 + c * 4) * 4;
        cpasync16(dst, Bp + (size_t)(col0 + r) * K2 + kp0 + c * 4);
    }
}

template <int MODE>
__global__ __launch_bounds__(256, 2) void gemm_planes(
    const uint32_t* __restrict__ Ah, const uint32_t* __restrict__ Bp,
    const float* __restrict__ bias,
    float* __restrict__ outf,
    uint32_t* __restrict__ qkvp,
    int M, int N, int K)
{
    extern __shared__ uint32_t sm[];     // 3 stages x 9216 u32
    const uint32_t sm_u = smem_u32(sm);

    const int tid  = threadIdx.x;
    const int wid  = tid >> 5, lane = tid & 31;
    const int gid  = lane >> 2, tig = lane & 3;
    const int wm   = wid & 3;
    const int wn   = wid >> 2;
    const int row0 = blockIdx.y * 128;
    const int col0 = blockIdx.x * 128;
    const int K2   = K >> 1;
    const int NK   = K >> 6;             // BK = 64 floats

    const int lane7 = lane & 7;
    const int aRow  = wm * 32 + lane7 + ((lane >> 3) & 1) * 8;
    const int aColB = ((lane >> 4) & 1) * 16;
    const uint32_t aOff = (uint32_t)(aRow * 144) + aColB;
    const int bRow  = wn * 64 + lane7 + ((lane >> 4) & 1) * 8;
    const int bColB = ((lane >> 3) & 1) * 16;
    const uint32_t bOff = 4608 * 4 + (uint32_t)(bRow * 144) + bColB;

    float cf[2][8][4];
    #pragma unroll
    for (int ma = 0; ma < 2; ma++)
        #pragma unroll
        for (int na = 0; na < 8; na++)
            #pragma unroll
            for (int r = 0; r < 4; r++) cf[ma][na][r] = 0.f;

    gemm_issue(sm_u, Ah, Bp, row0, col0, K2, 0, tid);
    CP_COMMIT();
    if (NK > 1) {
        gemm_issue(sm_u + 36864, Ah, Bp, row0, col0, K2, 32, tid);
        CP_COMMIT();
    }

    for (int kt = 0; kt < NK; kt++) {
        if (kt + 1 < NK) { CP_WAIT1(); } else { CP_WAIT0(); }
        __syncthreads();
        if (kt + 2 < NK) {
            gemm_issue(sm_u + ((kt + 2) % 3) * 36864, Ah, Bp,
                       row0, col0, K2, (kt + 2) << 5, tid);
            CP_COMMIT();
        }

        const uint32_t stage = sm_u + (kt % 3) * 36864;

        #pragma unroll
        for (int ss = 0; ss < 4; ss++) {
            const uint32_t ssb = ss * 32;
            uint32_t a[2][4];
            #pragma unroll
            for (int ma = 0; ma < 2; ma++)
                ldm_x4(a[ma][0], a[ma][1], a[ma][2], a[ma][3],
                       stage + aOff + ma * 2304 + ssb);
            #pragma unroll
            for (int j = 0; j < 4; j++) {
                uint32_t b0, b1, b2, b3;
                ldm_x4(b0, b1, b2, b3, stage + bOff + j * 2304 + ssb);
                #pragma unroll
                for (int ma = 0; ma < 2; ma++) {
                    mma_f16(cf[ma][2 * j],     a[ma][0], a[ma][1], a[ma][2], a[ma][3], b0, b1);
                    mma_f16(cf[ma][2 * j + 1], a[ma][0], a[ma][1], a[ma][2], a[ma][3], b2, b3);
                }
            }
        }
    }
    __syncthreads();   // all MMAs done before epilogue (and kernel exit)

    if (MODE == 1) {
        #pragma unroll
        for (int ma = 0; ma < 2; ma++) {
            const int rg = row0 + wm * 32 + ma * 16 + gid;
            #pragma unroll
            for (int na = 0; na < 8; na++) {
                const int cg = col0 + wn * 64 + na * 8 + tig * 2;
                const float bx0 = bias[cg], bx1 = bias[cg + 1];
                *(float2*)(outf + (size_t)rg * N + cg) =
                    make_float2(cf[ma][na][0] + bx0, cf[ma][na][1] + bx1);
                *(float2*)(outf + (size_t)(rg + 8) * N + cg) =
                    make_float2(cf[ma][na][2] + bx0, cf[ma][na][3] + bx1);
            }
        }
    } else {
        const int which = col0 / 768;
        const int lc0 = col0 - which * 768;
        #pragma unroll
        for (int ma = 0; ma < 2; ma++) {
            const int rg = row0 + wm * 32 + ma * 16 + gid;
            #pragma unroll
            for (int na = 0; na < 8; na++) {
                const int gc = col0 + wn * 64 + na * 8 + tig * 2;
                const int pr = (lc0 >> 1) + wn * 32 + na * 4 + tig;
                const float bx0 = bias[gc], bx1 = bias[gc + 1];
                float v0 = cf[ma][na][0] + bx0, v1 = cf[ma][na][1] + bx1;
                float v2 = cf[ma][na][2] + bx0, v3 = cf[ma][na][3] + bx1;
                if (which == 0) {
                    uint32_t h, l;
                    splitH(v0 * QSCALE, v1 * QSCALE, h, l);
                    qkvp[(size_t)rg * 384 + pr] = h;
                    qkvp[(size_t)PSZ + (size_t)rg * 384 + pr] = l;
                    splitH(v2 * QSCALE, v3 * QSCALE, h, l);
                    qkvp[(size_t)(rg + 8) * 384 + pr] = h;
                    qkvp[(size_t)PSZ + (size_t)(rg + 8) * 384 + pr] = l;
                } else if (which == 1) {
                    qkvp[(size_t)2 * PSZ + (size_t)rg * 384 + pr] = cvtH(v0, v1);
                    qkvp[(size_t)2 * PSZ + (size_t)(rg + 8) * 384 + pr] = cvtH(v2, v3);
                } else {
                    qkvp[(size_t)3 * PSZ + (size_t)rg * 384 + pr] = cvtH(v0, v1);
                    qkvp[(size_t)3 * PSZ + (size_t)(rg + 8) * 384 + pr] = cvtH(v2, v3);
                }
            }
        }
    }
}

// ---------------------------------------------------------------------------
// Flash attention: 128-token stages, 3-stage pipeline, one barrier per stage.
// V read straight from the dim-major plane via ldmatrix.trans (no pack_vt).
// Stage layout (u32): K@0 [128][36], V@4608 [128][36]. Stage = 9216 u32.
// ---------------------------------------------------------------------------
__device__ __forceinline__ void flash_issue(
    uint32_t st_u32,
    const uint32_t* kp, const uint32_t* vp,
    int tok0, int h, int tid)
{
    #pragma unroll
    for (int p = 0; p < 4; p++) {
        int idx = p * 256 + tid;          // 128 K tokens
        int r = idx >> 3, c = idx & 7;
        uint32_t dst = st_u32 + (r * 36 + c * 4) * 4;
        cpasync16(dst, kp + (size_t)(tok0 + r) * 384 + h * 32 + c * 4);
    }
    #pragma unroll
    for (int p = 0; p < 4; p++) {
        int idx = p * 256 + tid;          // 128 V tokens (dim-major rows)
        int r = idx >> 3, c = idx & 7;
        uint32_t dst = st_u32 + (4608 + r * 36 + c * 4) * 4;
        cpasync16(dst, vp + (size_t)(tok0 + r) * 384 + h * 32 + c * 4);
    }
}

__global__ __launch_bounds__(256, 2) void flash_planes(
    const uint32_t* __restrict__ qkvp,
    uint32_t* __restrict__ yp,
    float* __restrict__ po, float* __restrict__ ml)
{
    extern __shared__ uint32_t sm[];       // 3 stages x 9216 u32
    const uint32_t sm_u = smem_u32(sm);

    const int tid = threadIdx.x;
    const int wid = tid >> 5, lane = tid & 31;
    const int gid = lane >> 2, tig = lane & 3;
    const int bh = blockIdx.x;
    const int u  = blockIdx.y;
    const int b  = bh / HH;
    const int h  = bh % HH;

    int bx, split, kt0, kt1;
    if (u < 16) {
        bx    = 8 + (u >> 1);
        split = u & 1;
        const int half = bx + 1;
        kt0 = split ? half : 0;
        kt1 = split ? (2 * bx + 2) : half;
    } else {
        bx = 23 - u;
        split = -1;
        kt0 = 0;
        kt1 = 2 * bx + 2;
    }
    const int q0 = bx * 128;

    const uint32_t* qph = qkvp;
    const uint32_t* qpl = qkvp + (size_t)PSZ;
    const uint32_t* kp  = qkvp + (size_t)2 * PSZ;
    const uint32_t* vp  = qkvp + (size_t)3 * PSZ;

    const int lane7 = lane & 7;
    // K (non-trans): bit4 -> row half, bit3 -> col half
    const uint32_t kOff = (uint32_t)((lane7 + ((lane >> 4) & 1) * 8) * 144)
                        + ((lane >> 3) & 1) * 16;
    // V (trans): bit3 -> token half, bit4 -> dim half
    const uint32_t vOff = 4608 * 4
                        + (uint32_t)((lane7 + ((lane >> 3) & 1) * 8) * 144)
                        + ((lane >> 4) & 1) * 16;

    const int grow0 = b * 2048 + q0 + wid * 16 + gid;
    uint32_t qh[4][4], ql[4][4];
    #pragma unroll
    for (int ks = 0; ks < 4; ks++) {
        const int pr = h * 32 + 8 * ks + tig;
        qh[ks][0] = qph[(size_t)grow0 * 384 + pr];
        qh[ks][1] = qph[(size_t)(grow0 + 8) * 384 + pr];
        qh[ks][2] = qph[(size_t)grow0 * 384 + pr + 4];
        qh[ks][3] = qph[(size_t)(grow0 + 8) * 384 + pr + 4];
        ql[ks][0] = qpl[(size_t)grow0 * 384 + pr];
        ql[ks][1] = qpl[(size_t)(grow0 + 8) * 384 + pr];
        ql[ks][2] = qpl[(size_t)grow0 * 384 + pr + 4];
        ql[ks][3] = qpl[(size_t)(grow0 + 8) * 384 + pr + 4];
    }

    float of[8][4];
    #pragma unroll
    for (int na = 0; na < 8; na++)
        #pragma unroll
        for (int r = 0; r < 4; r++) of[na][r] = 0.f;
    float m0 = -1e30f, m1 = -1e30f, l0 = 0.f, l1 = 0.f;
    const int r0g = q0 + wid * 16 + gid;
    const int r1g = r0g + 8;

    const int nloc = kt1 - kt0;
    const int nst  = (nloc + 1) >> 1;      // 128-token stages
    flash_issue(sm_u, kp, vp, b * 2048 + kt0 * 64, h, tid);
    CP_COMMIT();
    if (nst > 1) {
        flash_issue(sm_u + 36864, kp, vp, b * 2048 + (kt0 + 2) * 64, h, tid);
        CP_COMMIT();
    }

    for (int si = 0; si < nst; si++) {
        if (si + 1 < nst) { CP_WAIT1(); } else { CP_WAIT0(); }
        __syncthreads();
        if (si + 2 < nst) {
            flash_issue(sm_u + ((si + 2) % 3) * 36864, kp, vp,
                        b * 2048 + (kt0 + 2 * (si + 2)) * 64, h, tid);
            CP_COMMIT();
        }

        #pragma unroll
        for (int sub = 0; sub < 2; sub++) {
            const int kt = kt0 + 2 * si + sub;
            if (kt >= kt1) break;
            if (kt * 64 > q0 + wid * 16 + 15) continue;

            const uint32_t stage = sm_u + (si % 3) * 36864 + (uint32_t)sub * 9216;

            // ---- S(log2) = Qscaled @ K^T (Q hi/lo, K single) ----
            float sf[8][4];
            #pragma unroll
            for (int na = 0; na < 8; na++)
                #pragma unroll
                for (int r = 0; r < 4; r++) sf[na][r] = 0.f;

            #pragma unroll
            for (int ks = 0; ks < 4; ks++) {
                const uint32_t ksb = ks * 32;
                #pragma unroll
                for (int j = 0; j < 4; j++) {
                    uint32_t b0, b1, b2, b3;
                    ldm_x4(b0, b1, b2, b3, stage + kOff + j * 2304 + ksb);
                    mma_f16(sf[2 * j],     qh[ks][0], qh[ks][1], qh[ks][2], qh[ks][3], b0, b1);
                    mma_f16(sf[2 * j],     ql[ks][0], ql[ks][1], ql[ks][2], ql[ks][3], b0, b1);
                    mma_f16(sf[2 * j + 1], qh[ks][0], qh[ks][1], qh[ks][2], qh[ks][3], b2, b3);
                    mma_f16(sf[2 * j + 1], ql[ks][0], ql[ks][1], ql[ks][2], ql[ks][3], b2, b3);
                }
            }

            // ---- causal mask ----
            const bool need_mask = (kt >= 2 * bx);
            if (need_mask) {
                #pragma unroll
                for (int na = 0; na < 8; na++) {
                    const int cg = kt * 64 + na * 8 + tig * 2;
                    if (cg     > r0g) sf[na][0] = -1e30f;
                    if (cg + 1 > r0g) sf[na][1] = -1e30f;
                    if (cg     > r1g) sf[na][2] = -1e30f;
                    if (cg + 1 > r1g) sf[na][3] = -1e30f;
                }
            }

            // ---- online softmax (log2 domain, fp16 exp2) ----
            float rm0 = -1e30f, rm1 = -1e30f;
            #pragma unroll
            for (int na = 0; na < 8; na++) {
                rm0 = fmaxf(rm0, fmaxf(sf[na][0], sf[na][1]));
                rm1 = fmaxf(rm1, fmaxf(sf[na][2], sf[na][3]));
            }
            rm0 = fmaxf(rm0, __shfl_xor_sync(0xffffffffu, rm0, 1));
            rm0 = fmaxf(rm0, __shfl_xor_sync(0xffffffffu, rm0, 2));
            rm1 = fmaxf(rm1, __shfl_xor_sync(0xffffffffu, rm1, 1));
            rm1 = fmaxf(rm1, __shfl_xor_sync(0xffffffffu, rm1, 2));
            const float mn0 = fmaxf(m0, rm0), mn1 = fmaxf(m1, rm1);
            const float c0 = exp2f(m0 - mn0), c1 = exp2f(m1 - mn1);
            float rs0 = 0.f, rs1 = 0.f;
            uint32_t p01[8], p23[8];
            #pragma unroll
            for (int na = 0; na < 8; na++) {
                __half2 h01 = __floats2half2_rn(sf[na][0] - mn0, sf[na][1] - mn0);
                __half2 h23 = __floats2half2_rn(sf[na][2] - mn1, sf[na][3] - mn1);
                p01[na] = ex2_f16x2(*reinterpret_cast<uint32_t*>(&h01));
                p23[na] = ex2_f16x2(*reinterpret_cast<uint32_t*>(&h23));
                float2 f01 = __half22float2(*reinterpret_cast<__half2*>(&p01[na]));
                float2 f23 = __half22float2(*reinterpret_cast<__half2*>(&p23[na]));
                rs0 += f01.x + f01.y;
                rs1 += f23.x + f23.y;
            }
            rs0 += __shfl_xor_sync(0xffffffffu, rs0, 1);
            rs0 += __shfl_xor_sync(0xffffffffu, rs0, 2);
            rs1 += __shfl_xor_sync(0xffffffffu, rs1, 1);
            rs1 += __shfl_xor_sync(0xffffffffu, rs1, 2);
            l0 = l0 * c0 + rs0; m0 = mn0;
            l1 = l1 * c1 + rs1; m1 = mn1;
            #pragma unroll
            for (int na = 0; na < 8; na++) {
                of[na][0] *= c0; of[na][1] *= c0;
                of[na][2] *= c1; of[na][3] *= c1;
            }

            // ---- O += P @ V (V via trans ldmatrix from dim-major tile) ----
            #pragma unroll
            for (int ks = 0; ks < 4; ks++) {
                const uint32_t pa0 = p01[2 * ks],     pa1 = p23[2 * ks];
                const uint32_t pa2 = p01[2 * ks + 1], pa3 = p23[2 * ks + 1];
                #pragma unroll
                for (int np = 0; np < 4; np++) {
                    uint32_t v0, v1, v2, v3;
                    ldm_x4t(v0, v1, v2, v3, stage + vOff + ks * 2304 + np * 32);
                    mma_f16(of[2 * np],     pa0, pa1, pa2, pa3, v0, v1);
                    mma_f16(of[2 * np + 1], pa0, pa1, pa2, pa3, v2, v3);
                }
            }
        }
    }
    __syncthreads();

    if (split < 0) {
        const float i0 = 1.f / l0, i1 = 1.f / l1;
        const int gr0 = b * 2048 + r0g;
        #pragma unroll
        for (int na = 0; na < 8; na++) {
            const int pr = h * 32 + na * 4 + tig;
            yp[(size_t)gr0 * 384 + pr] = cvtH(of[na][0] * i0, of[na][1] * i0);
            yp[(size_t)(gr0 + 8) * 384 + pr] = cvtH(of[na][2] * i1, of[na][3] * i1);
        }
    } else {
        const int hb = bx - 8;
        const int r0 = wid * 16 + gid;
        float* pob = po + ((((size_t)split * 24 + bh) * 8 + hb) * 128) * 64;
        #pragma unroll
        for (int na = 0; na < 8; na++) {
            *(float2*)(pob + (size_t)r0 * 64 + na * 8 + 2 * tig) =
                make_float2(of[na][0], of[na][1]);
            *(float2*)(pob + (size_t)(r0 + 8) * 64 + na * 8 + 2 * tig) =
                make_float2(of[na][2], of[na][3]);
        }
        if (tig == 0) {
            float* mlb = ml + ((((size_t)split * 24 + bh) * 8 + hb) * 128) * 2;
            mlb[r0 * 2]           = m0;
            mlb[r0 * 2 + 1]       = l0;
            mlb[(r0 + 8) * 2]     = m1;
            mlb[(r0 + 8) * 2 + 1] = l1;
        }
    }
}

// ---------------------------------------------------------------------------
// Merge split-KV partials into y plane (heavy q-blocks only).
// ---------------------------------------------------------------------------
__global__ void merge_heavy(const float* __restrict__ po,
                            const float* __restrict__ ml,
                            uint32_t* __restrict__ yp)
{
    int idx = blockIdx.x * 256 + threadIdx.x;
    int d4 = idx & 15;
    int r  = (idx >> 4) & 127;
    int hb = (idx >> 11) & 7;
    int bh = idx >> 14;
    int b = bh / HH, h = bh % HH;

    size_t rowA = (((size_t)0 * 24 + bh) * 8 + hb) * 128 + r;
    size_t rowB = (((size_t)1 * 24 + bh) * 8 + hb) * 128 + r;
    float mA = ml[rowA * 2], lA = ml[rowA * 2 + 1];
    float mB = ml[rowB * 2], lB = ml[rowB * 2 + 1];
    float m = fmaxf(mA, mB);
    float sA = exp2f(mA - m), sB = exp2f(mB - m);
    float inv = 1.f / (lA * sA + lB * sB);

    float4 oA = *(const float4*)(po + rowA * 64 + 4 * d4);
    float4 oB = *(const float4*)(po + rowB * 64 + 4 * d4);
    float v0 = (oA.x * sA + oB.x * sB) * inv;
    float v1 = (oA.y * sA + oB.y * sB) * inv;
    float v2 = (oA.z * sA + oB.z * sB) * inv;
    float v3 = (oA.w * sA + oB.w * sB) * inv;

    int grow = b * 2048 + (8 + hb) * 128 + r;
    int pr = h * 32 + 2 * d4;
    yp[(size_t)grow * 384 + pr]     = cvtH(v0, v1);
    yp[(size_t)grow * 384 + pr + 1] = cvtH(v2, v3);
}

extern "C" void kernel_launch(void* const* d_in, const int* in_sizes, int n_in,
                              void* d_out, int out_size)
{
    const float* x      = (const float*)d_in[0];
    const float* W_attn = (const float*)d_in[1];
    const float* b_attn = (const float*)d_in[2];
    const float* W_proj = (const float*)d_in[3];
    const float* b_proj = (const float*)d_in[4];
    float* out = (float*)d_out;

    uint32_t *qkvp, *xp, *yp, *wt, *wt2;
    float *po, *mlb;
    cudaGetSymbolAddress((void**)&qkvp, g_qkvp);
    cudaGetSymbolAddress((void**)&xp, g_xp);
    cudaGetSymbolAddress((void**)&yp, g_yp);
    cudaGetSymbolAddress((void**)&wt, g_wt);
    cudaGetSymbolAddress((void**)&wt2, g_wt2);
    cudaGetSymbolAddress((void**)&po, g_po);
    cudaGetSymbolAddress((void**)&mlb, g_ml);

    const int GEMM_SMEM  = 3 * 9216 * 4;    // 110592
    const int FLASH_SMEM = 3 * 9216 * 4;    // 110592
    cudaFuncSetAttribute(gemm_planes<0>,
                         cudaFuncAttributeMaxDynamicSharedMemorySize, GEMM_SMEM);
    cudaFuncSetAttribute(gemm_planes<1>,
                         cudaFuncAttributeMaxDynamicSharedMemorySize, GEMM_SMEM);
    cudaFuncSetAttribute(flash_planes,
                         cudaFuncAttributeMaxDynamicSharedMemorySize, FLASH_SMEM);

    split_x<<<786432 / 256, 256>>>(x, xp);                                 // 0
    transpose_cvtH<<<dim3(C3 / 32, CC / 32), dim3(32, 8)>>>(               // 1
        W_attn, wt, CC, C3);
    transpose_cvtH<<<dim3(CC / 32, CC / 32), dim3(32, 8)>>>(               // 2
        W_proj, wt2, CC, CC);

    gemm_planes<0><<<dim3(C3 / 128, MTOT / 128), 256, GEMM_SMEM>>>(        // 3
        xp, wt, b_attn, nullptr, qkvp, MTOT, C3, CC);

    flash_planes<<<dim3(24, 24), 256, FLASH_SMEM>>>(                       // 4
        qkvp, yp, po, mlb);

    merge_heavy<<<393216 / 256, 256>>>(po, mlb, yp);                       // 5

    gemm_planes<1><<<dim3(CC / 128, MTOT / 128), 256, GEMM_SMEM>>>(        // 6
        yp, wt2, b_proj, out, nullptr, MTOT, CC, CC);
}

// round 17
// speedup vs baseline: 6.9998x; 1.1441x over previous
#include <cuda_runtime.h>
#include <cuda_bf16.h>
#include <cuda_fp16.h>
#include <math.h>
#include <cstdint>

#define BB 2
#define TT 2048
#define CC 768
#define HH 12
#define HS 64
#define C3 2304
#define MTOT (BB*TT)          // 4096
#define PSZ (4096*384)        // u32 per plane ([12 kchunks][4096 rows][32 pairs])
#define QSCALE 0.18033688011112042f   // 0.125 * log2(e)

// Scratch — fp16x2-packed u32 planes in BLOCK-K layout [kchunk][row][32 pairs],
// each 128B row XOR-swizzled in 16B chunks by (row&7).
__device__ uint32_t g_qkvp[4 * (size_t)PSZ];        // q_hi, q_lo, k, v  ([head][token][32])
__device__ uint32_t g_xp[(size_t)PSZ];              // x  [12][4096][32]
__device__ uint32_t g_yp[(size_t)PSZ];              // y  [12][4096][32]
__device__ uint32_t g_wt[(size_t)C3 * CC / 2];      // W_attn^T [12][2304][32]
__device__ uint32_t g_wt2[(size_t)CC * CC / 2];     // W_proj^T [12][768][32]
// split-KV partials
__device__ float g_po[(size_t)2 * 24 * 8 * 128 * 64];
__device__ float g_ml[(size_t)2 * 24 * 8 * 128 * 2];

// ---------------------------------------------------------------------------
// Helpers
// ---------------------------------------------------------------------------
__device__ __forceinline__ uint32_t smem_u32(const void* p) {
    uint32_t a;
    asm("{ .reg .u64 t; cvta.to.shared.u64 t, %1; cvt.u32.u64 %0, t; }"
        : "=r"(a) : "l"(p));
    return a;
}

__device__ __forceinline__ void mma_f16(float c[4],
    uint32_t a0, uint32_t a1, uint32_t a2, uint32_t a3,
    uint32_t b0, uint32_t b1)
{
    asm("mma.sync.aligned.m16n8k16.row.col.f32.f16.f16.f32 "
        "{%0,%1,%2,%3}, {%4,%5,%6,%7}, {%8,%9}, {%0,%1,%2,%3};"
        : "+f"(c[0]), "+f"(c[1]), "+f"(c[2]), "+f"(c[3])
        : "r"(a0), "r"(a1), "r"(a2), "r"(a3), "r"(b0), "r"(b1));
}

__device__ __forceinline__ void ldm_x4(uint32_t& r0, uint32_t& r1,
                                       uint32_t& r2, uint32_t& r3, uint32_t addr)
{
    asm volatile("ldmatrix.sync.aligned.m8n8.x4.shared.b16 {%0,%1,%2,%3}, [%4];"
        : "=r"(r0), "=r"(r1), "=r"(r2), "=r"(r3) : "r"(addr));
}

__device__ __forceinline__ void ldm_x4t(uint32_t& r0, uint32_t& r1,
                                        uint32_t& r2, uint32_t& r3, uint32_t addr)
{
    asm volatile("ldmatrix.sync.aligned.m8n8.x4.trans.shared.b16 {%0,%1,%2,%3}, [%4];"
        : "=r"(r0), "=r"(r1), "=r"(r2), "=r"(r3) : "r"(addr));
}

__device__ __forceinline__ uint32_t cvtH(float x, float y)
{
    __half2 h = __floats2half2_rn(x, y);
    return *reinterpret_cast<uint32_t*>(&h);
}

__device__ __forceinline__ void splitH(float x, float y, uint32_t& hi, uint32_t& lo)
{
    __half2 h = __floats2half2_rn(x, y);
    hi = *reinterpret_cast<uint32_t*>(&h);
    float hx = __low2float(h), hy = __high2float(h);
    __half2 l = __floats2half2_rn(x - hx, y - hy);
    lo = *reinterpret_cast<uint32_t*>(&l);
}

__device__ __forceinline__ uint32_t ex2_f16x2(uint32_t x) {
    uint32_t r;
    asm("ex2.approx.f16x2 %0, %1;" : "=r"(r) : "r"(x));
    return r;
}

// bulk DMA: 16KB contiguous gmem -> smem, completion on mbarrier tx-count
__device__ __forceinline__ void bulk16k(uint32_t dst, const void* src, uint32_t mbar)
{
    asm volatile("cp.async.bulk.shared::cta.global.mbarrier::complete_tx::bytes "
                 "[%0], [%1], %2, [%3];"
                 :: "r"(dst), "l"(src), "r"(16384u), "r"(mbar) : "memory");
}

#define MBAR_INIT(a, c) asm volatile("mbarrier.init.shared.b64 [%0], %1;" :: "r"(a), "r"(c) : "memory")
#define MBAR_EXPECT(a, bytes) asm volatile("mbarrier.arrive.expect_tx.shared.b64 _, [%0], %1;" :: "r"(a), "r"(bytes) : "memory")

#define MBAR_WAIT(mbar_addr, phase_parity) do {                                  \
    uint32_t _mbar = (uint32_t)(mbar_addr);                                      \
    uint32_t _parity = (uint32_t)(phase_parity);                                 \
    uint32_t _done;                                                              \
    asm volatile("{\n\t.reg .pred p;\n\t"                                        \
        "mbarrier.try_wait.parity.acquire.cta.shared::cta.b64 p, [%1], %2;\n\t"  \
        "selp.b32 %0, 1, 0, p;\n\t}"                                             \
        : "=r"(_done) : "r"(_mbar), "r"(_parity) : "memory");                    \
    if (!_done) {                                                                \
        asm volatile("{\n\t.reg .pred P1;\n\t"                                   \
            "WAIT_LOOP_%=:\n\t"                                                  \
            "mbarrier.try_wait.parity.acquire.cta.shared::cta.b64 P1, [%0], %1, 0x989680;\n\t" \
            "@P1 bra.uni WAIT_DONE_%=;\n\t"                                      \
            "bra.uni WAIT_LOOP_%=;\n\t"                                          \
            "WAIT_DONE_%=:\n\t}"                                                 \
            :: "r"(_mbar), "r"(_parity) : "memory");                             \
    }                                                                            \
} while (0)

// ---------------------------------------------------------------------------
// Prep kernels (write block-K + swizzled layout)
// ---------------------------------------------------------------------------
__global__ void split_x(const float* __restrict__ x, uint32_t* __restrict__ xh)
{
    int idx = blockIdx.x * 256 + threadIdx.x;
    int r = idx / 192, j2 = idx % 192;
    float4 v = *(const float4*)(x + (size_t)r * 768 + 4 * j2);
    int p0 = 2 * j2;                 // pair index 0..383
    int kc = p0 >> 5;
    int pin = p0 & 31;
    int ch = (pin >> 2) ^ (r & 7);
    size_t o = ((size_t)kc * 4096 + r) * 32 + (ch << 2) + (pin & 3);
    *(uint2*)(xh + o) = make_uint2(cvtH(v.x, v.y), cvtH(v.z, v.w));
}

__global__ void transpose_cvtH(const float* __restrict__ in,
                               uint32_t* __restrict__ outp,
                               int K, int N)
{
    __shared__ float t[32][33];
    int n0 = blockIdx.x << 5, k0 = blockIdx.y << 5;
    int x = threadIdx.x, y = threadIdx.y;
    #pragma unroll
    for (int i = 0; i < 32; i += 8)
        t[y + i][x] = in[(size_t)(k0 + y + i) * N + n0 + x];
    __syncthreads();
    if (x < 16) {
        #pragma unroll
        for (int i = 0; i < 32; i += 8) {
            int n = n0 + y + i;
            int pg = k0 / 2 + x;
            int kc = pg >> 5, pin = pg & 31;
            int ch = (pin >> 2) ^ (n & 7);
            outp[((size_t)kc * N + n) * 32 + (ch << 2) + (pin & 3)] =
                cvtH(t[2 * x][y + i], t[2 * x + 1][y + i]);
        }
    }
}

// ---------------------------------------------------------------------------
// fp16 single-product GEMM, BK=64, 3-stage bulk-DMA pipeline.
// smem: mbar[3]@0, stages@256B, each stage = A 16KB + B 16KB.
// ---------------------------------------------------------------------------
template <int MODE>
__global__ __launch_bounds__(256, 2) void gemm_planes(
    const uint32_t* __restrict__ Ah, const uint32_t* __restrict__ Bp,
    const float* __restrict__ bias,
    float* __restrict__ outf,
    uint32_t* __restrict__ qkvp,
    int M, int N, int K)
{
    extern __shared__ uint32_t sm[];
    const uint32_t mb  = smem_u32(sm);
    const uint32_t st0 = mb + 256;

    const int tid  = threadIdx.x;
    const int wid  = tid >> 5, lane = tid & 31;
    const int gid  = lane >> 2, tig = lane & 3;
    const int wm   = wid & 3;
    const int wn   = wid >> 2;
    const int row0 = blockIdx.y * 128;
    const int col0 = blockIdx.x * 128;
    const int NK   = K >> 6;             // BK = 64 floats (32 pairs)

    const int lane7 = lane & 7;
    const int b3 = (lane >> 3) & 1, b4 = (lane >> 4) & 1;
    const uint32_t aRowB = (uint32_t)(wm * 32 + lane7 + b3 * 8) * 128;
    const uint32_t bRowB = (uint32_t)(wn * 64 + lane7 + b4 * 8) * 128;

    float cf[2][8][4];
    #pragma unroll
    for (int ma = 0; ma < 2; ma++)
        #pragma unroll
        for (int na = 0; na < 8; na++)
            #pragma unroll
            for (int r = 0; r < 4; r++) cf[ma][na][r] = 0.f;

    if (tid == 0) {
        MBAR_INIT(mb, 1); MBAR_INIT(mb + 8, 1); MBAR_INIT(mb + 16, 1);
    }
    __syncthreads();
    if (tid == 0) {
        MBAR_EXPECT(mb, 32768u);
        bulk16k(st0, Ah + ((size_t)0 * M + row0) * 32, mb);
        bulk16k(st0 + 16384, Bp + ((size_t)0 * N + col0) * 32, mb);
        MBAR_EXPECT(mb + 8, 32768u);
        bulk16k(st0 + 32768, Ah + ((size_t)1 * M + row0) * 32, mb + 8);
        bulk16k(st0 + 32768 + 16384, Bp + ((size_t)1 * N + col0) * 32, mb + 8);
    }

    for (int kt = 0; kt < NK; kt++) {
        MBAR_WAIT(mb + (kt % 3) * 8, (kt / 3) & 1);
        __syncthreads();
        if (tid == 0 && kt + 2 < NK) {
            const int s = (kt + 2) % 3;
            MBAR_EXPECT(mb + s * 8, 32768u);
            bulk16k(st0 + s * 32768, Ah + ((size_t)(kt + 2) * M + row0) * 32, mb + s * 8);
            bulk16k(st0 + s * 32768 + 16384, Bp + ((size_t)(kt + 2) * N + col0) * 32, mb + s * 8);
        }

        const uint32_t stA = st0 + (kt % 3) * 32768;
        const uint32_t stB = stA + 16384;

        #pragma unroll
        for (int ss = 0; ss < 4; ss++) {
            const uint32_t aCh = (uint32_t)((((ss << 1) | b4) ^ lane7) << 4);
            const uint32_t bCh = (uint32_t)((((ss << 1) | b3) ^ lane7) << 4);
            uint32_t a[2][4];
            #pragma unroll
            for (int ma = 0; ma < 2; ma++)
                ldm_x4(a[ma][0], a[ma][1], a[ma][2], a[ma][3],
                       stA + aRowB + (uint32_t)(ma * 16 * 128) + aCh);
            #pragma unroll
            for (int j = 0; j < 4; j++) {
                uint32_t b0, b1, b2, b3r;
                ldm_x4(b0, b1, b2, b3r, stB + bRowB + (uint32_t)(j * 16 * 128) + bCh);
                #pragma unroll
                for (int ma = 0; ma < 2; ma++) {
                    mma_f16(cf[ma][2 * j],     a[ma][0], a[ma][1], a[ma][2], a[ma][3], b0, b1);
                    mma_f16(cf[ma][2 * j + 1], a[ma][0], a[ma][1], a[ma][2], a[ma][3], b2, b3r);
                }
            }
        }
    }
    __syncthreads();

    if (MODE == 1) {
        #pragma unroll
        for (int ma = 0; ma < 2; ma++) {
            const int rg = row0 + wm * 32 + ma * 16 + gid;
            #pragma unroll
            for (int na = 0; na < 8; na++) {
                const int cg = col0 + wn * 64 + na * 8 + tig * 2;
                const float bx0 = bias[cg], bx1 = bias[cg + 1];
                *(float2*)(outf + (size_t)rg * N + cg) =
                    make_float2(cf[ma][na][0] + bx0, cf[ma][na][1] + bx1);
                *(float2*)(outf + (size_t)(rg + 8) * N + cg) =
                    make_float2(cf[ma][na][2] + bx0, cf[ma][na][3] + bx1);
            }
        }
    } else {
        const int which = col0 / 768;
        const int lc0 = col0 - which * 768;
        #pragma unroll
        for (int ma = 0; ma < 2; ma++) {
            const int rg = row0 + wm * 32 + ma * 16 + gid;
            const int r7 = rg & 7;       // same for rg+8
            #pragma unroll
            for (int na = 0; na < 8; na++) {
                const int gc = col0 + wn * 64 + na * 8 + tig * 2;
                const int pr = (lc0 >> 1) + wn * 32 + na * 4 + tig;
                const int hI = pr >> 5, dp = pr & 31;
                const size_t o0 = ((size_t)hI * 4096 + rg) * 32
                                + (((dp >> 2) ^ r7) << 2) + (dp & 3);
                const size_t o1 = o0 + 8 * 32;
                const float bx0 = bias[gc], bx1 = bias[gc + 1];
                float v0 = cf[ma][na][0] + bx0, v1 = cf[ma][na][1] + bx1;
                float v2 = cf[ma][na][2] + bx0, v3 = cf[ma][na][3] + bx1;
                if (which == 0) {
                    uint32_t h, l;
                    splitH(v0 * QSCALE, v1 * QSCALE, h, l);
                    qkvp[o0] = h;
                    qkvp[(size_t)PSZ + o0] = l;
                    splitH(v2 * QSCALE, v3 * QSCALE, h, l);
                    qkvp[o1] = h;
                    qkvp[(size_t)PSZ + o1] = l;
                } else if (which == 1) {
                    qkvp[(size_t)2 * PSZ + o0] = cvtH(v0, v1);
                    qkvp[(size_t)2 * PSZ + o1] = cvtH(v2, v3);
                } else {
                    qkvp[(size_t)3 * PSZ + o0] = cvtH(v0, v1);
                    qkvp[(size_t)3 * PSZ + o1] = cvtH(v2, v3);
                }
            }
        }
    }
}

// ---------------------------------------------------------------------------
// Flash attention: 128-token stages loaded with 2 bulk DMAs, 3-stage ring.
// smem: mbar[3]@0, stages@256B, each stage = K 16KB + V 16KB.
// ---------------------------------------------------------------------------
__global__ __launch_bounds__(256, 2) void flash_planes(
    const uint32_t* __restrict__ qkvp,
    uint32_t* __restrict__ yp,
    float* __restrict__ po, float* __restrict__ ml)
{
    extern __shared__ uint32_t sm[];
    const uint32_t mb  = smem_u32(sm);
    const uint32_t st0 = mb + 256;

    const int tid = threadIdx.x;
    const int wid = tid >> 5, lane = tid & 31;
    const int gid = lane >> 2, tig = lane & 3;
    const int bh = blockIdx.x;
    const int u  = blockIdx.y;
    const int b  = bh / HH;
    const int h  = bh % HH;

    int bx, split, kt0, kt1;
    if (u < 16) {
        bx    = 8 + (u >> 1);
        split = u & 1;
        const int half = bx + 1;
        kt0 = split ? half : 0;
        kt1 = split ? (2 * bx + 2) : half;
    } else {
        bx = 23 - u;
        split = -1;
        kt0 = 0;
        kt1 = 2 * bx + 2;
    }
    const int q0 = bx * 128;

    const uint32_t* qph = qkvp;
    const uint32_t* qpl = qkvp + (size_t)PSZ;
    const uint32_t* kp  = qkvp + (size_t)2 * PSZ;
    const uint32_t* vp  = qkvp + (size_t)3 * PSZ;

    const int lane7 = lane & 7;
    const int b3 = (lane >> 3) & 1, b4 = (lane >> 4) & 1;
    const uint32_t kRowB = (uint32_t)(lane7 + b4 * 8) * 128;   // + j*16 rows + sub*64
    const uint32_t vRowB = (uint32_t)(lane7 + b3 * 8) * 128;   // + ks*16 rows + sub*64

    const int grow0 = b * 2048 + q0 + wid * 16 + gid;
    const int g7 = grow0 & 7;            // same for grow0+8
    uint32_t qh[4][4], ql[4][4];
    #pragma unroll
    for (int ks = 0; ks < 4; ks++) {
        const size_t base = ((size_t)h * 4096 + grow0) * 32;
        const int c0 = ((2 * ks) ^ g7) * 4 + tig;
        const int c1 = ((2 * ks + 1) ^ g7) * 4 + tig;
        qh[ks][0] = qph[base + c0];
        qh[ks][1] = qph[base + 8 * 32 + c0];
        qh[ks][2] = qph[base + c1];
        qh[ks][3] = qph[base + 8 * 32 + c1];
        ql[ks][0] = qpl[base + c0];
        ql[ks][1] = qpl[base + 8 * 32 + c0];
        ql[ks][2] = qpl[base + c1];
        ql[ks][3] = qpl[base + 8 * 32 + c1];
    }

    float of[8][4];
    #pragma unroll
    for (int na = 0; na < 8; na++)
        #pragma unroll
        for (int r = 0; r < 4; r++) of[na][r] = 0.f;
    float m0 = -1e30f, m1 = -1e30f, l0 = 0.f, l1 = 0.f;
    const int r0g = q0 + wid * 16 + gid;
    const int r1g = r0g + 8;

    const int nloc = kt1 - kt0;
    const int nst  = (nloc + 1) >> 1;
    const size_t kvbase = ((size_t)h * 4096 + b * 2048) * 32;

    if (tid == 0) {
        MBAR_INIT(mb, 1); MBAR_INIT(mb + 8, 1); MBAR_INIT(mb + 16, 1);
    }
    __syncthreads();
    if (tid == 0) {
        MBAR_EXPECT(mb, 32768u);
        bulk16k(st0, kp + kvbase + (size_t)kt0 * 64 * 32, mb);
        bulk16k(st0 + 16384, vp + kvbase + (size_t)kt0 * 64 * 32, mb);
        if (nst > 1) {
            MBAR_EXPECT(mb + 8, 32768u);
            bulk16k(st0 + 32768, kp + kvbase + (size_t)(kt0 + 2) * 64 * 32, mb + 8);
            bulk16k(st0 + 32768 + 16384, vp + kvbase + (size_t)(kt0 + 2) * 64 * 32, mb + 8);
        }
    }

    for (int si = 0; si < nst; si++) {
        MBAR_WAIT(mb + (si % 3) * 8, (si / 3) & 1);
        __syncthreads();
        if (tid == 0 && si + 2 < nst) {
            const int s = (si + 2) % 3;
            MBAR_EXPECT(mb + s * 8, 32768u);
            bulk16k(st0 + s * 32768, kp + kvbase + (size_t)(kt0 + 2 * (si + 2)) * 64 * 32, mb + s * 8);
            bulk16k(st0 + s * 32768 + 16384, vp + kvbase + (size_t)(kt0 + 2 * (si + 2)) * 64 * 32, mb + s * 8);
        }

        #pragma unroll
        for (int sub = 0; sub < 2; sub++) {
            const int kt = kt0 + 2 * si + sub;
            if (kt >= kt1) break;
            if (kt * 64 > q0 + wid * 16 + 15) continue;

            const uint32_t stK = st0 + (si % 3) * 32768 + (uint32_t)sub * 64 * 128;
            const uint32_t stV = st0 + (si % 3) * 32768 + 16384 + (uint32_t)sub * 64 * 128;

            // ---- S(log2) = Qscaled @ K^T ----
            float sf[8][4];
            #pragma unroll
            for (int na = 0; na < 8; na++)
                #pragma unroll
                for (int r = 0; r < 4; r++) sf[na][r] = 0.f;

            #pragma unroll
            for (int ks = 0; ks < 4; ks++) {
                const uint32_t kCh = (uint32_t)((((ks << 1) | b3) ^ lane7) << 4);
                #pragma unroll
                for (int j = 0; j < 4; j++) {
                    uint32_t b0, b1, b2, b3r;
                    ldm_x4(b0, b1, b2, b3r, stK + kRowB + (uint32_t)(j * 16 * 128) + kCh);
                    mma_f16(sf[2 * j],     qh[ks][0], qh[ks][1], qh[ks][2], qh[ks][3], b0, b1);
                    mma_f16(sf[2 * j],     ql[ks][0], ql[ks][1], ql[ks][2], ql[ks][3], b0, b1);
                    mma_f16(sf[2 * j + 1], qh[ks][0], qh[ks][1], qh[ks][2], qh[ks][3], b2, b3r);
                    mma_f16(sf[2 * j + 1], ql[ks][0], ql[ks][1], ql[ks][2], ql[ks][3], b2, b3r);
                }
            }

            // ---- causal mask ----
            const bool need_mask = (kt >= 2 * bx);
            if (need_mask) {
                #pragma unroll
                for (int na = 0; na < 8; na++) {
                    const int cg = kt * 64 + na * 8 + tig * 2;
                    if (cg     > r0g) sf[na][0] = -1e30f;
                    if (cg + 1 > r0g) sf[na][1] = -1e30f;
                    if (cg     > r1g) sf[na][2] = -1e30f;
                    if (cg + 1 > r1g) sf[na][3] = -1e30f;
                }
            }

            // ---- online softmax (log2 domain, fp16 exp2) ----
            float rm0 = -1e30f, rm1 = -1e30f;
            #pragma unroll
            for (int na = 0; na < 8; na++) {
                rm0 = fmaxf(rm0, fmaxf(sf[na][0], sf[na][1]));
                rm1 = fmaxf(rm1, fmaxf(sf[na][2], sf[na][3]));
            }
            rm0 = fmaxf(rm0, __shfl_xor_sync(0xffffffffu, rm0, 1));
            rm0 = fmaxf(rm0, __shfl_xor_sync(0xffffffffu, rm0, 2));
            rm1 = fmaxf(rm1, __shfl_xor_sync(0xffffffffu, rm1, 1));
            rm1 = fmaxf(rm1, __shfl_xor_sync(0xffffffffu, rm1, 2));
            const float mn0 = fmaxf(m0, rm0), mn1 = fmaxf(m1, rm1);
            const float c0 = exp2f(m0 - mn0), c1 = exp2f(m1 - mn1);
            float rs0 = 0.f, rs1 = 0.f;
            uint32_t p01[8], p23[8];
            #pragma unroll
            for (int na = 0; na < 8; na++) {
                __half2 h01 = __floats2half2_rn(sf[na][0] - mn0, sf[na][1] - mn0);
                __half2 h23 = __floats2half2_rn(sf[na][2] - mn1, sf[na][3] - mn1);
                p01[na] = ex2_f16x2(*reinterpret_cast<uint32_t*>(&h01));
                p23[na] = ex2_f16x2(*reinterpret_cast<uint32_t*>(&h23));
                float2 f01 = __half22float2(*reinterpret_cast<__half2*>(&p01[na]));
                float2 f23 = __half22float2(*reinterpret_cast<__half2*>(&p23[na]));
                rs0 += f01.x + f01.y;
                rs1 += f23.x + f23.y;
            }
            rs0 += __shfl_xor_sync(0xffffffffu, rs0, 1);
            rs0 += __shfl_xor_sync(0xffffffffu, rs0, 2);
            rs1 += __shfl_xor_sync(0xffffffffu, rs1, 1);
            rs1 += __shfl_xor_sync(0xffffffffu, rs1, 2);
            l0 = l0 * c0 + rs0; m0 = mn0;
            l1 = l1 * c1 + rs1; m1 = mn1;
            #pragma unroll
            for (int na = 0; na < 8; na++) {
                of[na][0] *= c0; of[na][1] *= c0;
                of[na][2] *= c1; of[na][3] *= c1;
            }

            // ---- O += P @ V (trans ldmatrix) ----
            #pragma unroll
            for (int ks = 0; ks < 4; ks++) {
                const uint32_t pa0 = p01[2 * ks],     pa1 = p23[2 * ks];
                const uint32_t pa2 = p01[2 * ks + 1], pa3 = p23[2 * ks + 1];
                #pragma unroll
                for (int np = 0; np < 4; np++) {
                    const uint32_t vCh = (uint32_t)((((np << 1) | b4) ^ lane7) << 4);
                    uint32_t v0, v1, v2, v3;
                    ldm_x4t(v0, v1, v2, v3,
                            stV + vRowB + (uint32_t)(ks * 16 * 128) + vCh);
                    mma_f16(of[2 * np],     pa0, pa1, pa2, pa3, v0, v1);
                    mma_f16(of[2 * np + 1], pa0, pa1, pa2, pa3, v2, v3);
                }
            }
        }
    }
    __syncthreads();

    if (split < 0) {
        const float i0 = 1.f / l0, i1 = 1.f / l1;
        const int gr0 = b * 2048 + r0g;
        const int g7e = gr0 & 7;
        #pragma unroll
        for (int na = 0; na < 8; na++) {
            const int dp = na * 4 + tig;
            const size_t o0 = ((size_t)h * 4096 + gr0) * 32
                            + (((dp >> 2) ^ g7e) << 2) + (dp & 3);
            yp[o0] = cvtH(of[na][0] * i0, of[na][1] * i0);
            yp[o0 + 8 * 32] = cvtH(of[na][2] * i1, of[na][3] * i1);
        }
    } else {
        const int hb = bx - 8;
        const int r0 = wid * 16 + gid;
        float* pob = po + ((((size_t)split * 24 + bh) * 8 + hb) * 128) * 64;
        #pragma unroll
        for (int na = 0; na < 8; na++) {
            *(float2*)(pob + (size_t)r0 * 64 + na * 8 + 2 * tig) =
                make_float2(of[na][0], of[na][1]);
            *(float2*)(pob + (size_t)(r0 + 8) * 64 + na * 8 + 2 * tig) =
                make_float2(of[na][2], of[na][3]);
        }
        if (tig == 0) {
            float* mlb = ml + ((((size_t)split * 24 + bh) * 8 + hb) * 128) * 2;
            mlb[r0 * 2]           = m0;
            mlb[r0 * 2 + 1]       = l0;
            mlb[(r0 + 8) * 2]     = m1;
            mlb[(r0 + 8) * 2 + 1] = l1;
        }
    }
}

// ---------------------------------------------------------------------------
// Merge split-KV partials into y plane (heavy q-blocks only).
// ---------------------------------------------------------------------------
__global__ void merge_heavy(const float* __restrict__ po,
                            const float* __restrict__ ml,
                            uint32_t* __restrict__ yp)
{
    int idx = blockIdx.x * 256 + threadIdx.x;
    int d4 = idx & 15;
    int r  = (idx >> 4) & 127;
    int hb = (idx >> 11) & 7;
    int bh = idx >> 14;
    int b = bh / HH, h = bh % HH;

    size_t rowA = (((size_t)0 * 24 + bh) * 8 + hb) * 128 + r;
    size_t rowB = (((size_t)1 * 24 + bh) * 8 + hb) * 128 + r;
    float mA = ml[rowA * 2], lA = ml[rowA * 2 + 1];
    float mB = ml[rowB * 2], lB = ml[rowB * 2 + 1];
    float m = fmaxf(mA, mB);
    float sA = exp2f(mA - m), sB = exp2f(mB - m);
    float inv = 1.f / (lA * sA + lB * sB);

    float4 oA = *(const float4*)(po + rowA * 64 + 4 * d4);
    float4 oB = *(const float4*)(po + rowB * 64 + 4 * d4);
    float v0 = (oA.x * sA + oB.x * sB) * inv;
    float v1 = (oA.y * sA + oB.y * sB) * inv;
    float v2 = (oA.z * sA + oB.z * sB) * inv;
    float v3 = (oA.w * sA + oB.w * sB) * inv;

    int grow = b * 2048 + (8 + hb) * 128 + r;
    int dp = 2 * d4;                      // dp, dp+1 share a 16B chunk
    int ch = (dp >> 2) ^ (grow & 7);
    size_t o = ((size_t)h * 4096 + grow) * 32 + (ch << 2) + (dp & 3);
    yp[o]     = cvtH(v0, v1);
    yp[o + 1] = cvtH(v2, v3);
}

extern "C" void kernel_launch(void* const* d_in, const int* in_sizes, int n_in,
                              void* d_out, int out_size)
{
    const float* x      = (const float*)d_in[0];
    const float* W_attn = (const float*)d_in[1];
    const float* b_attn = (const float*)d_in[2];
    const float* W_proj = (const float*)d_in[3];
    const float* b_proj = (const float*)d_in[4];
    float* out = (float*)d_out;

    uint32_t *qkvp, *xp, *yp, *wt, *wt2;
    float *po, *mlb;
    cudaGetSymbolAddress((void**)&qkvp, g_qkvp);
    cudaGetSymbolAddress((void**)&xp, g_xp);
    cudaGetSymbolAddress((void**)&yp, g_yp);
    cudaGetSymbolAddress((void**)&wt, g_wt);
    cudaGetSymbolAddress((void**)&wt2, g_wt2);
    cudaGetSymbolAddress((void**)&po, g_po);
    cudaGetSymbolAddress((void**)&mlb, g_ml);

    const int PIPE_SMEM = 256 + 3 * 32768;   // 98560
    cudaFuncSetAttribute(gemm_planes<0>,
                         cudaFuncAttributeMaxDynamicSharedMemorySize, PIPE_SMEM);
    cudaFuncSetAttribute(gemm_planes<1>,
                         cudaFuncAttributeMaxDynamicSharedMemorySize, PIPE_SMEM);
    cudaFuncSetAttribute(flash_planes,
                         cudaFuncAttributeMaxDynamicSharedMemorySize, PIPE_SMEM);

    split_x<<<786432 / 256, 256>>>(x, xp);                                 // 0
    transpose_cvtH<<<dim3(C3 / 32, CC / 32), dim3(32, 8)>>>(               // 1
        W_attn, wt, CC, C3);
    transpose_cvtH<<<dim3(CC / 32, CC / 32), dim3(32, 8)>>>(               // 2
        W_proj, wt2, CC, CC);

    gemm_planes<0><<<dim3(C3 / 128, MTOT / 128), 256, PIPE_SMEM>>>(        // 3
        xp, wt, b_attn, nullptr, qkvp, MTOT, C3, CC);

    flash_planes<<<dim3(24, 24), 256, PIPE_SMEM>>>(                        // 4
        qkvp, yp, po, mlb);

    merge_heavy<<<393216 / 256, 256>>>(po, mlb, yp);                       // 5

    gemm_planes<1><<<dim3(CC / 128, MTOT / 128), 256, PIPE_SMEM>>>(        // 6
        yp, wt2, b_proj, out, nullptr, MTOT, CC, CC);
}